// round 7
// baseline (speedup 1.0000x reference)
#include <cuda_runtime.h>
#include <cuda_bf16.h>
#include <cstdint>

#define NEGC 1e9f

#define B_  32
#define T_  512
#define D_  256
#define O_  256
#define KF_ 8
#define G_  64

// ---------------- scratch ----------------
__device__ float g_R [B_ * O_ * T_];
__device__ float g_Q [B_ * O_ * T_];
__device__ float g_F [B_ * T_ * T_];
__device__ float g_WR[B_ * G_ * T_];
__device__ float g_WQ[B_ * G_ * T_];
__device__ float g_d1[B_ * T_];
__device__ float g_d2[B_ * T_];
__device__ float g_g1[B_ * T_];
__device__ float g_g2[B_ * T_];
__device__ float g_pq[B_ * T_];
__device__ float g_pv[B_ * T_];
__device__ int   g_len1[B_];
__device__ int   g_len2[B_];
__device__ int   g_jmin[B_];
__device__ int   g_imax[B_];

__device__ __nv_bfloat16 g_Ukh[KF_ * T_ * O_];
__device__ __nv_bfloat16 g_Ukl[KF_ * T_ * O_];
__device__ __nv_bfloat16 g_Vkh[KF_ * T_ * O_];
__device__ __nv_bfloat16 g_Vkl[KF_ * T_ * O_];
__device__ __nv_bfloat16 g_Rth[B_ * T_ * O_];
__device__ __nv_bfloat16 g_Rtl[B_ * T_ * O_];
__device__ __nv_bfloat16 g_Qth[B_ * T_ * O_];
__device__ __nv_bfloat16 g_Qtl[B_ * T_ * O_];

// =================== helpers ===================
__device__ __forceinline__ uint32_t smem_to_u32(const void* p) {
    uint32_t a;
    asm("{ .reg .u64 t; cvta.to.shared.u64 t, %1; cvt.u32.u64 %0, t; }" : "=r"(a) : "l"(p));
    return a;
}
__device__ __forceinline__ void ldsm4(uint32_t* r, uint32_t addr) {
    asm volatile("ldmatrix.sync.aligned.m8n8.x4.shared.b16 {%0,%1,%2,%3}, [%4];"
        : "=r"(r[0]), "=r"(r[1]), "=r"(r[2]), "=r"(r[3]) : "r"(addr));
}
__device__ __forceinline__ void mma16816(float* d, const uint32_t* a,
                                         uint32_t b0, uint32_t b1) {
    asm volatile("mma.sync.aligned.m16n8k16.row.col.f32.bf16.bf16.f32 "
        "{%0,%1,%2,%3}, {%4,%5,%6,%7}, {%8,%9}, {%0,%1,%2,%3};"
        : "+f"(d[0]), "+f"(d[1]), "+f"(d[2]), "+f"(d[3])
        : "r"(a[0]), "r"(a[1]), "r"(a[2]), "r"(a[3]), "r"(b0), "r"(b1));
}
__device__ __forceinline__ void cpasync16(uint32_t dst, const void* src) {
    asm volatile("cp.async.cg.shared.global [%0], [%1], 16;" :: "r"(dst), "l"(src));
}
#define CP_COMMIT() asm volatile("cp.async.commit_group;" ::: "memory")
#define CP_WAIT(n)  asm volatile("cp.async.wait_group %0;" :: "n"(n) : "memory")

__device__ __forceinline__ uint32_t paddr(uint32_t row, uint32_t cb) {
    uint32_t pr = row >> 1;
    return pr * 128 + ((((row & 1) << 6) + cb) ^ ((pr & 7) << 4));
}

__device__ __forceinline__ void decode_mask(const unsigned char* q, const unsigned char* v,
                                            int i, bool& qv, bool& vv) {
    unsigned char b1 = q[1], b3 = q[3];
    int type = (b1 == 1) ? 0 : (b1 == 0x3F) ? 3 : (b3 == 0x3F) ? 2 : 1;
    switch (type) {
        case 0: qv = q[i] != 0;                            vv = v[i] != 0; break;
        case 1: qv = ((const int*)q)[i] != 0;              vv = ((const int*)v)[i] != 0; break;
        case 2: qv = ((const float*)q)[i] != 0.f;          vv = ((const float*)v)[i] != 0.f; break;
        default: qv = ((const unsigned short*)q)[i] != 0;  vv = ((const unsigned short*)v)[i] != 0; break;
    }
}

// ---------------- mask decode ----------------
__global__ void maskconv_kernel(const unsigned char* __restrict__ q,
                                const unsigned char* __restrict__ v,
                                float* __restrict__ pq, float* __restrict__ pv) {
    int i = blockIdx.x * blockDim.x + threadIdx.x;
    if (i >= B_ * T_) return;
    bool qv, vv;
    decode_mask(q, v, i, qv, vv);
    pq[i] = qv ? 0.f : 1.f;
    pv[i] = vv ? 0.f : 1.f;
}

// ---------------- per-batch valid lengths ----------------
__global__ void lens_kernel(const unsigned char* __restrict__ q,
                            const unsigned char* __restrict__ v,
                            int* __restrict__ len1, int* __restrict__ len2,
                            int* __restrict__ jmin, int* __restrict__ imax) {
    __shared__ int s1, s2;
    int b = blockIdx.x, t = threadIdx.x;
    if (t == 0) { s1 = 0; s2 = 0; }
    __syncthreads();
    bool qv, vv;
    decode_mask(q, v, b * T_ + t, qv, vv);
    unsigned m1 = __ballot_sync(0xffffffffu, qv);
    unsigned m2 = __ballot_sync(0xffffffffu, vv);
    if ((t & 31) == 0) { atomicAdd(&s1, __popc(m1)); atomicAdd(&s2, __popc(m2)); }
    __syncthreads();
    if (t == 0) {
        len1[b] = s1; len2[b] = s2;
        jmin[b] = s1 < s2 ? s1 : s2;
        imax[b] = s1 > s2 ? s1 : s2;
    }
}

// ---------------- U/V de-interleave + bf16 split ----------------
__global__ void convUV_kernel(const float* __restrict__ U, const float* __restrict__ V,
                              __nv_bfloat16* __restrict__ Uh, __nv_bfloat16* __restrict__ Ul,
                              __nv_bfloat16* __restrict__ Vh, __nv_bfloat16* __restrict__ Vl) {
    int idx = blockIdx.x * blockDim.x + threadIdx.x;
    if (idx >= KF_ * T_ * O_) return;
    int k = idx >> 17;
    int m = idx & (T_ * O_ - 1);
    float u = U[m * KF_ + k];
    float v = V[m * KF_ + k];
    __nv_bfloat16 uh = __float2bfloat16(u);
    __nv_bfloat16 vh = __float2bfloat16(v);
    Uh[idx] = uh; Ul[idx] = __float2bfloat16(u - __bfloat162float(uh));
    Vh[idx] = vh; Vl[idx] = __float2bfloat16(v - __bfloat162float(vh));
}

// ---------------- transpose + bf16 split ----------------
__global__ void convRQ_kernel(const float* __restrict__ R, const float* __restrict__ Q,
                              __nv_bfloat16* __restrict__ Rh, __nv_bfloat16* __restrict__ Rl,
                              __nv_bfloat16* __restrict__ Qh, __nv_bfloat16* __restrict__ Ql) {
    __shared__ float tile[32][33];
    int zz = blockIdx.z;
    int b = zz & 31;
    bool isQ = (zz >> 5) != 0;
    const float* src = (isQ ? Q : R) + (long)b * O_ * T_;
    __nv_bfloat16* dh = (isQ ? Qh : Rh) + (long)b * T_ * O_;
    __nv_bfloat16* dl = (isQ ? Ql : Rl) + (long)b * T_ * O_;
    int t0 = blockIdx.x * 32, o0 = blockIdx.y * 32;
    int tx = threadIdx.x, ty = threadIdx.y;
    #pragma unroll
    for (int r = 0; r < 4; r++)
        tile[ty + r * 8][tx] = src[(long)(o0 + ty + r * 8) * T_ + t0 + tx];
    __syncthreads();
    #pragma unroll
    for (int r = 0; r < 4; r++) {
        int t = t0 + ty + r * 8;
        float v = tile[tx][ty + r * 8];
        __nv_bfloat16 h = __float2bfloat16(v);
        dh[(long)t * O_ + o0 + tx] = h;
        dl[(long)t * O_ + o0 + tx] = __float2bfloat16(v - __bfloat162float(h));
    }
}

// ---------------- R/Q GEMM: 64(m)x128(n) tile, 128 thr, 8x8/thread ----------------
__global__ __launch_bounds__(128) void gemm_rq_kernel(
    const float* __restrict__ A, const float* __restrict__ Bm,
    float* __restrict__ C, const float* __restrict__ bias,
    const float* __restrict__ pad, const int* __restrict__ lenp) {
    int b = blockIdx.z;
    int n0 = blockIdx.x * 128;
    int m0 = blockIdx.y * 64;
    int tid = threadIdx.x;
    if (n0 >= lenp[b]) {
        // masked columns: R/Q are exactly relu(-1e9)=0
        float4 z = make_float4(0.f, 0.f, 0.f, 0.f);
        #pragma unroll
        for (int e = 0; e < 16; e++) {
            int idx = tid + e * 128;
            int m = idx >> 5, nq = idx & 31;
            *reinterpret_cast<float4*>(&C[((long)b * O_ + m0 + m) * T_ + n0 + nq * 4]) = z;
        }
        return;
    }
    const float* Bb = Bm + (long)b * (D_ * T_);
    __shared__ float As[16][68];
    __shared__ float Bs[16][132];
    int tx = tid & 15, ty = tid >> 4;
    float acc[8][8] = {};
    for (int k0 = 0; k0 < D_; k0 += 16) {
        #pragma unroll
        for (int e = 0; e < 2; e++) {
            int idx = tid + e * 128;
            int m = idx >> 2, kq = idx & 3;
            float4 a = *reinterpret_cast<const float4*>(&A[(m0 + m) * D_ + k0 + kq * 4]);
            As[kq * 4 + 0][m] = a.x; As[kq * 4 + 1][m] = a.y;
            As[kq * 4 + 2][m] = a.z; As[kq * 4 + 3][m] = a.w;
        }
        #pragma unroll
        for (int e = 0; e < 4; e++) {
            int idx = tid + e * 128;
            int r = idx >> 5, cq = idx & 31;
            *reinterpret_cast<float4*>(&Bs[r][cq * 4]) =
                *reinterpret_cast<const float4*>(&Bb[(long)(k0 + r) * T_ + n0 + cq * 4]);
        }
        __syncthreads();
        #pragma unroll
        for (int kk = 0; kk < 16; kk++) {
            float4 a0 = *reinterpret_cast<const float4*>(&As[kk][ty * 8]);
            float4 a1 = *reinterpret_cast<const float4*>(&As[kk][ty * 8 + 4]);
            float4 b0 = *reinterpret_cast<const float4*>(&Bs[kk][tx * 8]);
            float4 b1 = *reinterpret_cast<const float4*>(&Bs[kk][tx * 8 + 4]);
            float av[8] = {a0.x, a0.y, a0.z, a0.w, a1.x, a1.y, a1.z, a1.w};
            float bv[8] = {b0.x, b0.y, b0.z, b0.w, b1.x, b1.y, b1.z, b1.w};
            #pragma unroll
            for (int i = 0; i < 8; i++)
                #pragma unroll
                for (int j = 0; j < 8; j++)
                    acc[i][j] += av[i] * bv[j];
        }
        __syncthreads();
    }
    #pragma unroll
    for (int i = 0; i < 8; i++) {
        int m = m0 + ty * 8 + i;
        float bi = bias[m];
        #pragma unroll
        for (int j = 0; j < 8; j++) {
            int n = n0 + tx * 8 + j;
            acc[i][j] = fmaxf(acc[i][j] - NEGC * pad[b * T_ + n] + bi, 0.f);
        }
        float* dst = &C[((long)b * O_ + m) * T_ + n0 + tx * 8];
        *reinterpret_cast<float4*>(dst) = make_float4(acc[i][0], acc[i][1], acc[i][2], acc[i][3]);
        *reinterpret_cast<float4*>(dst + 4) = make_float4(acc[i][4], acc[i][5], acc[i][6], acc[i][7]);
    }
}

// ---------------- generic 64x64 tile GEMM (W2 only) ----------------
__global__ void gemm64_kernel(const float* __restrict__ A, const float* __restrict__ Bm,
                              float* __restrict__ C, int K, int N, int Mtot,
                              long strideB) {
    int b  = blockIdx.z;
    int n0 = blockIdx.x * 64;
    int m0 = blockIdx.y * 64;
    const float* Bb = Bm + (long)b * strideB;
    __shared__ float As[16][68];
    __shared__ float Bs[16][68];
    int tid = threadIdx.x;
    int tx = tid & 15, ty = tid >> 4;
    float acc[4][4] = {};
    for (int k0 = 0; k0 < K; k0 += 16) {
        #pragma unroll
        for (int p = 0; p < 4; p++) {
            int r = (tid >> 4) + p * 16;
            int c = tid & 15;
            As[c][r] = A[(m0 + r) * K + k0 + c];
        }
        #pragma unroll
        for (int p = 0; p < 4; p++) {
            int r = (tid >> 6) + p * 4;
            int c = tid & 63;
            Bs[r][c] = Bb[(long)(k0 + r) * N + n0 + c];
        }
        __syncthreads();
        #pragma unroll
        for (int kk = 0; kk < 16; kk++) {
            float4 a4 = *reinterpret_cast<const float4*>(&As[kk][ty * 4]);
            float a[4] = {a4.x, a4.y, a4.z, a4.w};
            float4 bb = *reinterpret_cast<const float4*>(&Bs[kk][tx * 4]);
            float bv[4] = {bb.x, bb.y, bb.z, bb.w};
            #pragma unroll
            for (int i = 0; i < 4; i++)
                #pragma unroll
                for (int j = 0; j < 4; j++)
                    acc[i][j] += a[i] * bv[j];
        }
        __syncthreads();
    }
    #pragma unroll
    for (int i = 0; i < 4; i++) {
        int m = m0 + ty * 4 + i;
        #pragma unroll
        for (int j = 0; j < 4; j++) {
            int n = n0 + tx * 4 + j;
            C[(long)b * Mtot * N + (long)m * N + n] = acc[i][j];
        }
    }
}

// ======================= HMMA F kernel (skips + interleaved terms) =======================
#define FS_B 65536
#define FS_TOTAL 196608

__global__ __launch_bounds__(256, 1) void f_mma_kernel(
    const __nv_bfloat16* __restrict__ Uh, const __nv_bfloat16* __restrict__ Ul,
    const __nv_bfloat16* __restrict__ Vh, const __nv_bfloat16* __restrict__ Vl,
    const __nv_bfloat16* __restrict__ Rh, const __nv_bfloat16* __restrict__ Rl,
    const __nv_bfloat16* __restrict__ Qh, const __nv_bfloat16* __restrict__ Ql,
    float* __restrict__ F, const int* __restrict__ jmin, const int* __restrict__ imax) {
    extern __shared__ char sm[];
    uint32_t sb = smem_to_u32(sm);
    int tid = threadIdx.x, lane = tid & 31, w = tid >> 5;
    int wi = w >> 1, wj = w & 1;
    int b = blockIdx.z, i0 = blockIdx.y * 128, j0 = blockIdx.x * 64;
    int l16 = lane & 15, lh = lane >> 4;

    // rows i >= imax are only ever consumed with exactly-zero weights (bounded md loop)
    if (i0 >= imax[b]) return;

    // fully masked j-tile: F is exactly zero there
    if (j0 >= jmin[b]) {
        int row = tid >> 1, half = tid & 1;
        float4 z = make_float4(0.f, 0.f, 0.f, 0.f);
        float* dst = F + ((long)b * T_ + i0 + row) * T_ + j0 + half * 32;
        #pragma unroll
        for (int e = 0; e < 8; e++) reinterpret_cast<float4*>(dst)[e] = z;
        return;
    }

    const __nv_bfloat16* apt[4] = {Uh, Ul, Vh, Vl};
    const __nv_bfloat16* bpt[4] = {Rh, Rl, Qh, Ql};

    #pragma unroll
    for (int arr = 0; arr < 4; arr++) {
        const __nv_bfloat16* src = bpt[arr] + ((long)b * T_ + j0) * O_;
        #pragma unroll
        for (int e = 0; e < 8; e++) {
            int idx = tid + e * 256;
            int ch = idx >> 8;
            int row = (idx & 255) >> 2;
            int cb = (idx & 3) * 16;
            const void* g = src + (long)row * O_ + ch * 32 + cb / 2;
            cpasync16(sb + FS_B + arr * 32768 + ch * 4096 + paddr(row, cb), g);
        }
    }
    CP_COMMIT();

    auto load_a = [&](int cu, int st) {
        int k = cu >> 3, ch = cu & 7;
        #pragma unroll
        for (int arr = 0; arr < 4; arr++) {
            const __nv_bfloat16* src = apt[arr] + ((long)k * T_ + i0) * O_ + ch * 32;
            #pragma unroll
            for (int e = 0; e < 2; e++) {
                int idx = tid + e * 256;
                int row = idx >> 2;
                int cb = (idx & 3) * 16;
                const void* g = src + (long)row * O_ + cb / 2;
                cpasync16(sb + st * 32768 + arr * 8192 + paddr(row, cb), g);
            }
        }
    };

    load_a(0, 0);
    CP_COMMIT();

    float f[32], d1[32], d2[32];
    #pragma unroll
    for (int i = 0; i < 32; i++) { f[i] = 0.f; d1[i] = 0.f; d2[i] = 0.f; }

    for (int cu = 0; cu < 64; cu++) {
        int st = cu & 1, ch = cu & 7;
        if (cu + 1 < 64) {
            load_a(cu + 1, (cu + 1) & 1);
            CP_COMMIT();
            CP_WAIT(1);
        } else {
            CP_WAIT(0);
        }
        __syncthreads();

        uint32_t abase = sb + st * 32768;
        #pragma unroll
        for (int os = 0; os < 2; os++) {
            uint32_t colb = (uint32_t)(os * 32 + lh * 16);
            uint32_t arow = (uint32_t)(wi * 32 + l16);
            uint32_t brow = (uint32_t)(wj * 32 + l16);
            // ---- pass 1: d1 += U.R ----
            {
                uint32_t ah0[4], ah1[4], al0[4], al1[4];
                ldsm4(ah0, abase + 0 * 8192 + paddr(arow, colb));
                ldsm4(ah1, abase + 0 * 8192 + paddr(arow + 16, colb));
                ldsm4(al0, abase + 1 * 8192 + paddr(arow, colb));
                ldsm4(al1, abase + 1 * 8192 + paddr(arow + 16, colb));
                uint32_t bh0[4], bh1[4], bl0[4], bl1[4];
                uint32_t b0 = sb + FS_B + 0 * 32768 + ch * 4096;
                uint32_t b1 = sb + FS_B + 1 * 32768 + ch * 4096;
                ldsm4(bh0, b0 + paddr(brow, colb));
                ldsm4(bh1, b0 + paddr(brow + 16, colb));
                ldsm4(bl0, b1 + paddr(brow, colb));
                ldsm4(bl1, b1 + paddr(brow + 16, colb));
                #pragma unroll
                for (int term = 0; term < 3; term++) {
                    const uint32_t* A0 = (term == 2) ? al0 : ah0;
                    const uint32_t* A1 = (term == 2) ? al1 : ah1;
                    const uint32_t* B0 = (term == 1) ? bl0 : bh0;
                    const uint32_t* B1 = (term == 1) ? bl1 : bh1;
                    #pragma unroll
                    for (int mt = 0; mt < 2; mt++) {
                        const uint32_t* a = mt ? A1 : A0;
                        #pragma unroll
                        for (int nt = 0; nt < 4; nt++) {
                            const uint32_t* bb = (nt >> 1) ? B1 : B0;
                            int s = nt & 1;
                            mma16816(d1 + (mt * 4 + nt) * 4, a, bb[s], bb[s + 2]);
                        }
                    }
                }
            }
            // ---- pass 2: d2 += V.Q ----
            {
                uint32_t ah0[4], ah1[4], al0[4], al1[4];
                ldsm4(ah0, abase + 2 * 8192 + paddr(arow, colb));
                ldsm4(ah1, abase + 2 * 8192 + paddr(arow + 16, colb));
                ldsm4(al0, abase + 3 * 8192 + paddr(arow, colb));
                ldsm4(al1, abase + 3 * 8192 + paddr(arow + 16, colb));
                uint32_t bh0[4], bh1[4], bl0[4], bl1[4];
                uint32_t b2 = sb + FS_B + 2 * 32768 + ch * 4096;
                uint32_t b3 = sb + FS_B + 3 * 32768 + ch * 4096;
                ldsm4(bh0, b2 + paddr(brow, colb));
                ldsm4(bh1, b2 + paddr(brow + 16, colb));
                ldsm4(bl0, b3 + paddr(brow, colb));
                ldsm4(bl1, b3 + paddr(brow + 16, colb));
                #pragma unroll
                for (int term = 0; term < 3; term++) {
                    const uint32_t* A0 = (term == 2) ? al0 : ah0;
                    const uint32_t* A1 = (term == 2) ? al1 : ah1;
                    const uint32_t* B0 = (term == 1) ? bl0 : bh0;
                    const uint32_t* B1 = (term == 1) ? bl1 : bh1;
                    #pragma unroll
                    for (int mt = 0; mt < 2; mt++) {
                        const uint32_t* a = mt ? A1 : A0;
                        #pragma unroll
                        for (int nt = 0; nt < 4; nt++) {
                            const uint32_t* bb = (nt >> 1) ? B1 : B0;
                            int s = nt & 1;
                            mma16816(d2 + (mt * 4 + nt) * 4, a, bb[s], bb[s + 2]);
                        }
                    }
                }
            }
        }
        if (ch == 7) {
            #pragma unroll
            for (int i = 0; i < 32; i++) {
                f[i] += d1[i] * d2[i];
                d1[i] = 0.f; d2[i] = 0.f;
            }
        }
        __syncthreads();
    }

    int r4 = lane >> 2, c2 = (lane & 3) * 2;
    #pragma unroll
    for (int mt = 0; mt < 2; mt++) {
        #pragma unroll
        for (int nt = 0; nt < 4; nt++) {
            float* d = f + (mt * 4 + nt) * 4;
            long row = i0 + wi * 32 + mt * 16 + r4;
            long col = j0 + wj * 32 + nt * 8 + c2;
            float* dst = F + ((long)b * T_ + row) * T_ + col;
            dst[0] = d[0]; dst[1] = d[1];
            dst[8 * T_] = d[2]; dst[8 * T_ + 1] = d[3];
        }
    }
}

// ---------------- fused M + d kernel (col skip + bounded contraction) ----------------
__global__ void md_kernel(const float* __restrict__ Bias, const float* __restrict__ Mul,
                          const float* __restrict__ F, const float* __restrict__ w,
                          const float* __restrict__ pad, float* __restrict__ d,
                          const int* __restrict__ lencol, const int* __restrict__ lenmul) {
    int b  = blockIdx.y;
    int c0 = blockIdx.x * 64;
    int tid = threadIdx.x;
    if (c0 >= lencol[b]) {
        if (tid < 64) d[b * T_ + c0 + tid] = -NEGC;
        return;
    }
    int ibound = (lenmul[b] + 15) & ~15;   // Mul rows beyond lenmul are exactly zero
    __shared__ float Ms[16][68];
    __shared__ float Fs[16][68];
    __shared__ float red[16][64];
    int tx = tid & 15, ty = tid >> 4;
    float acc[4][4] = {};
    const float* Mb = Mul + (long)b * G_ * T_;
    const float* Fb = F   + (long)b * T_ * T_;
    for (int i0 = 0; i0 < ibound; i0 += 16) {
        #pragma unroll
        for (int p = 0; p < 4; p++) {
            int r = (tid >> 4) + p * 16;
            int c = tid & 15;
            Ms[c][r] = Mb[r * T_ + i0 + c];
        }
        #pragma unroll
        for (int p = 0; p < 4; p++) {
            int r = (tid >> 6) + p * 4;
            int c = tid & 63;
            Fs[r][c] = Fb[(long)(i0 + r) * T_ + c0 + c];
        }
        __syncthreads();
        #pragma unroll
        for (int ii = 0; ii < 16; ii++) {
            float4 m4 = *reinterpret_cast<const float4*>(&Ms[ii][ty * 4]);
            float m[4] = {m4.x, m4.y, m4.z, m4.w};
            float4 f4 = *reinterpret_cast<const float4*>(&Fs[ii][tx * 4]);
            float ff[4] = {f4.x, f4.y, f4.z, f4.w};
            #pragma unroll
            for (int i = 0; i < 4; i++)
                #pragma unroll
                for (int j = 0; j < 4; j++)
                    acc[i][j] += m[i] * ff[j];
        }
        __syncthreads();
    }
    float part[4] = {0.f, 0.f, 0.f, 0.f};
    #pragma unroll
    for (int gq = 0; gq < 4; gq++) {
        int g = ty * 4 + gq;
        float wg = w[g];
        #pragma unroll
        for (int c = 0; c < 4; c++) {
            float vv = acc[gq][c] + Bias[(long)b * G_ * T_ + g * T_ + c0 + tx * 4 + c];
            part[c] += wg * fmaxf(vv, 0.f);
        }
    }
    #pragma unroll
    for (int c = 0; c < 4; c++) red[ty][tx * 4 + c] = part[c];
    __syncthreads();
    #pragma unroll
    for (int s = 8; s > 0; s >>= 1) {
        if (ty < s) {
            #pragma unroll
            for (int c = 0; c < 4; c++) red[ty][tx * 4 + c] += red[ty + s][tx * 4 + c];
        }
        __syncthreads();
    }
    if (ty == 0) {
        #pragma unroll
        for (int c = 0; c < 4; c++) {
            int col = c0 + tx * 4 + c;
            d[b * T_ + col] = red[0][tx * 4 + c] - NEGC * pad[b * T_ + col];
        }
    }
}

// ---------------- softmax ----------------
__global__ void softmax_kernel(const float* __restrict__ d1, const float* __restrict__ d2,
                               float* __restrict__ g1, float* __restrict__ g2) {
    int b = blockIdx.x;
    const float* d = blockIdx.y ? d2 : d1;
    float* g = blockIdx.y ? g2 : g1;
    int t = threadIdx.x;
    float v = d[b * T_ + t];
    __shared__ float red[16];
    float m = v;
    #pragma unroll
    for (int o = 16; o; o >>= 1) m = fmaxf(m, __shfl_xor_sync(0xffffffffu, m, o));
    if ((t & 31) == 0) red[t >> 5] = m;
    __syncthreads();
    if (t < 32) {
        float x = (t < 16) ? red[t] : -3.4e38f;
        #pragma unroll
        for (int o = 8; o; o >>= 1) x = fmaxf(x, __shfl_xor_sync(0xffffffffu, x, o));
        if (t == 0) red[0] = x;
    }
    __syncthreads();
    float mx = red[0];
    __syncthreads();
    float e = expf(v - mx);
    float s = e;
    #pragma unroll
    for (int o = 16; o; o >>= 1) s += __shfl_xor_sync(0xffffffffu, s, o);
    if ((t & 31) == 0) red[t >> 5] = s;
    __syncthreads();
    if (t < 32) {
        float x = (t < 16) ? red[t] : 0.f;
        #pragma unroll
        for (int o = 8; o; o >>= 1) x += __shfl_xor_sync(0xffffffffu, x, o);
        if (t == 0) red[0] = x;
    }
    __syncthreads();
    g[b * T_ + t] = e / red[0];
}

// ---------------- final reduction ----------------
__global__ void final_kernel(const float* __restrict__ R, const float* __restrict__ Q,
                             const float* __restrict__ gv, const float* __restrict__ gq,
                             float* __restrict__ out) {
    int b = blockIdx.x;
    __shared__ float sgv[T_], sgq[T_];
    int tid = threadIdx.x;
    sgv[tid] = gv[b * T_ + tid];
    sgq[tid] = gq[b * T_ + tid];
    __syncthreads();
    int o = tid & 255;
    int h = tid >> 8;
    const float* Rb = R + (long)b * O_ * T_;
    const float* Qb = Q + (long)b * O_ * T_;
    float tr = 0.f, lg = 0.f;
    #pragma unroll 4
    for (int t = h * 256; t < h * 256 + 256; t++) {
        tr += sgv[t] * Rb[t * O_ + o];
        lg += sgq[t] * Qb[t * O_ + o];
    }
    __shared__ float str[2][256], slg[2][256];
    str[h][o] = tr;
    slg[h][o] = lg;
    __syncthreads();
    if (h == 0) out[b * O_ + o] = (str[0][o] + str[1][o]) * (slg[0][o] + slg[1][o]);
}

// ---------------- launcher ----------------
extern "C" void kernel_launch(void* const* d_in, const int* in_sizes, int n_in,
                              void* d_out, int out_size) {
    const float* x0  = (const float*)d_in[0];
    const float* x1  = (const float*)d_in[1];
    const unsigned char* qm = (const unsigned char*)d_in[2];
    const unsigned char* vm = (const unsigned char*)d_in[3];
    const float* W_R = (const float*)d_in[4];
    const float* W_Q = (const float*)d_in[5];
    const float* br  = (const float*)d_in[6];
    const float* bq  = (const float*)d_in[7];
    const float* U   = (const float*)d_in[8];
    const float* V   = (const float*)d_in[9];
    const float* W2R = (const float*)d_in[10];
    const float* W2Q = (const float*)d_in[11];
    const float* wmv = (const float*)d_in[12];
    const float* wmq = (const float*)d_in[13];
    float* out = (float*)d_out;

    float *pR, *pQ, *pF, *pWR, *pWQ, *pd1, *pd2, *pg1, *pg2, *ppq, *ppv;
    int *pl1, *pl2, *pjm, *pim;
    __nv_bfloat16 *pUh, *pUl, *pVh, *pVl, *pRh, *pRl, *pQh, *pQl;
    cudaGetSymbolAddress((void**)&pR,  g_R);
    cudaGetSymbolAddress((void**)&pQ,  g_Q);
    cudaGetSymbolAddress((void**)&pF,  g_F);
    cudaGetSymbolAddress((void**)&pWR, g_WR);
    cudaGetSymbolAddress((void**)&pWQ, g_WQ);
    cudaGetSymbolAddress((void**)&pd1, g_d1);
    cudaGetSymbolAddress((void**)&pd2, g_d2);
    cudaGetSymbolAddress((void**)&pg1, g_g1);
    cudaGetSymbolAddress((void**)&pg2, g_g2);
    cudaGetSymbolAddress((void**)&ppq, g_pq);
    cudaGetSymbolAddress((void**)&ppv, g_pv);
    cudaGetSymbolAddress((void**)&pl1, g_len1);
    cudaGetSymbolAddress((void**)&pl2, g_len2);
    cudaGetSymbolAddress((void**)&pjm, g_jmin);
    cudaGetSymbolAddress((void**)&pim, g_imax);
    cudaGetSymbolAddress((void**)&pUh, g_Ukh);
    cudaGetSymbolAddress((void**)&pUl, g_Ukl);
    cudaGetSymbolAddress((void**)&pVh, g_Vkh);
    cudaGetSymbolAddress((void**)&pVl, g_Vkl);
    cudaGetSymbolAddress((void**)&pRh, g_Rth);
    cudaGetSymbolAddress((void**)&pRl, g_Rtl);
    cudaGetSymbolAddress((void**)&pQh, g_Qth);
    cudaGetSymbolAddress((void**)&pQl, g_Qtl);

    static bool attr_done = false;
    if (!attr_done) {
        cudaFuncSetAttribute(f_mma_kernel, cudaFuncAttributeMaxDynamicSharedMemorySize, FS_TOTAL);
        attr_done = true;
    }

    maskconv_kernel<<<(B_ * T_ + 255) / 256, 256>>>(qm, vm, ppq, ppv);
    lens_kernel<<<B_, T_>>>(qm, vm, pl1, pl2, pjm, pim);
    convUV_kernel<<<(KF_ * T_ * O_ + 255) / 256, 256>>>(U, V, pUh, pUl, pVh, pVl);

    gemm_rq_kernel<<<dim3(T_ / 128, O_ / 64, B_), 128>>>(W_R, x0, pR, br, ppq, pl1);
    gemm_rq_kernel<<<dim3(T_ / 128, O_ / 64, B_), 128>>>(W_Q, x1, pQ, bq, ppv, pl2);

    convRQ_kernel<<<dim3(T_ / 32, O_ / 32, 2 * B_), dim3(32, 8)>>>(
        pR, pQ, pRh, pRl, pQh, pQl);

    f_mma_kernel<<<dim3(T_ / 64, T_ / 128, B_), 256, FS_TOTAL>>>(
        pUh, pUl, pVh, pVl, pRh, pRl, pQh, pQl, pF, pjm, pim);

    gemm64_kernel<<<dim3(T_ / 64, 1, B_), 256>>>(
        W2R, pR, pWR, O_, T_, G_, (long)O_ * T_);
    gemm64_kernel<<<dim3(T_ / 64, 1, B_), 256>>>(
        W2Q, pQ, pWQ, O_, T_, G_, (long)O_ * T_);

    md_kernel<<<dim3(T_ / 64, B_), 256>>>(pWR, pWQ, pF, wmv, ppq, pd1, pl1, pl2);
    md_kernel<<<dim3(T_ / 64, B_), 256>>>(pWQ, pWR, pF, wmq, ppv, pd2, pl2, pl1);

    softmax_kernel<<<dim3(B_, 2), T_>>>(pd1, pd2, pg1, pg2);

    final_kernel<<<B_, T_>>>(pR, pQ, pg1, pg2, out);
}

// round 8
// speedup vs baseline: 1.1938x; 1.1938x over previous
#include <cuda_runtime.h>
#include <cuda_fp16.h>
#include <cstdint>

#define NEGC 1e9f

#define B_  32
#define T_  512
#define D_  256
#define O_  256
#define KF_ 8
#define G_  64

// ---------------- scratch ----------------
__device__ float g_R [B_ * O_ * T_];
__device__ float g_Q [B_ * O_ * T_];
__device__ float g_F [B_ * T_ * T_];
__device__ float g_WR[B_ * G_ * T_];
__device__ float g_WQ[B_ * G_ * T_];
__device__ float g_d1[B_ * T_];
__device__ float g_d2[B_ * T_];
__device__ float g_g1[B_ * T_];
__device__ float g_g2[B_ * T_];
__device__ float g_pq[B_ * T_];
__device__ float g_pv[B_ * T_];
__device__ int   g_len1[B_];
__device__ int   g_len2[B_];
__device__ int   g_jmin[B_];
__device__ int   g_imax[B_];

// fp16 operands: A split (hi+lo), B single
__device__ __half g_Ukh[KF_ * T_ * O_];
__device__ __half g_Ukl[KF_ * T_ * O_];
__device__ __half g_Vkh[KF_ * T_ * O_];
__device__ __half g_Vkl[KF_ * T_ * O_];
__device__ __half g_Rt [B_ * T_ * O_];   // R transposed [b][t][o], fp16
__device__ __half g_Qt [B_ * T_ * O_];

// =================== helpers ===================
__device__ __forceinline__ uint32_t smem_to_u32(const void* p) {
    uint32_t a;
    asm("{ .reg .u64 t; cvta.to.shared.u64 t, %1; cvt.u32.u64 %0, t; }" : "=r"(a) : "l"(p));
    return a;
}
__device__ __forceinline__ void ldsm4(uint32_t* r, uint32_t addr) {
    asm volatile("ldmatrix.sync.aligned.m8n8.x4.shared.b16 {%0,%1,%2,%3}, [%4];"
        : "=r"(r[0]), "=r"(r[1]), "=r"(r[2]), "=r"(r[3]) : "r"(addr));
}
__device__ __forceinline__ void mma16816h(float* d, const uint32_t* a,
                                          uint32_t b0, uint32_t b1) {
    asm volatile("mma.sync.aligned.m16n8k16.row.col.f32.f16.f16.f32 "
        "{%0,%1,%2,%3}, {%4,%5,%6,%7}, {%8,%9}, {%0,%1,%2,%3};"
        : "+f"(d[0]), "+f"(d[1]), "+f"(d[2]), "+f"(d[3])
        : "r"(a[0]), "r"(a[1]), "r"(a[2]), "r"(a[3]), "r"(b0), "r"(b1));
}
__device__ __forceinline__ void cpasync16(uint32_t dst, const void* src) {
    asm volatile("cp.async.cg.shared.global [%0], [%1], 16;" :: "r"(dst), "l"(src));
}
#define CP_COMMIT() asm volatile("cp.async.commit_group;" ::: "memory")
#define CP_WAIT(n)  asm volatile("cp.async.wait_group %0;" :: "n"(n) : "memory")

__device__ __forceinline__ uint32_t paddr(uint32_t row, uint32_t cb) {
    uint32_t pr = row >> 1;
    return pr * 128 + ((((row & 1) << 6) + cb) ^ ((pr & 7) << 4));
}

__device__ __forceinline__ void decode_mask(const unsigned char* q, const unsigned char* v,
                                            int i, bool& qv, bool& vv) {
    unsigned char b1 = q[1], b3 = q[3];
    int type = (b1 == 1) ? 0 : (b1 == 0x3F) ? 3 : (b3 == 0x3F) ? 2 : 1;
    switch (type) {
        case 0: qv = q[i] != 0;                            vv = v[i] != 0; break;
        case 1: qv = ((const int*)q)[i] != 0;              vv = ((const int*)v)[i] != 0; break;
        case 2: qv = ((const float*)q)[i] != 0.f;          vv = ((const float*)v)[i] != 0.f; break;
        default: qv = ((const unsigned short*)q)[i] != 0;  vv = ((const unsigned short*)v)[i] != 0; break;
    }
}

// ---------------- mask decode ----------------
__global__ void maskconv_kernel(const unsigned char* __restrict__ q,
                                const unsigned char* __restrict__ v,
                                float* __restrict__ pq, float* __restrict__ pv) {
    int i = blockIdx.x * blockDim.x + threadIdx.x;
    if (i >= B_ * T_) return;
    bool qv, vv;
    decode_mask(q, v, i, qv, vv);
    pq[i] = qv ? 0.f : 1.f;
    pv[i] = vv ? 0.f : 1.f;
}

// ---------------- per-batch valid lengths ----------------
__global__ void lens_kernel(const unsigned char* __restrict__ q,
                            const unsigned char* __restrict__ v,
                            int* __restrict__ len1, int* __restrict__ len2,
                            int* __restrict__ jmin, int* __restrict__ imax) {
    __shared__ int s1, s2;
    int b = blockIdx.x, t = threadIdx.x;
    if (t == 0) { s1 = 0; s2 = 0; }
    __syncthreads();
    bool qv, vv;
    decode_mask(q, v, b * T_ + t, qv, vv);
    unsigned m1 = __ballot_sync(0xffffffffu, qv);
    unsigned m2 = __ballot_sync(0xffffffffu, vv);
    if ((t & 31) == 0) { atomicAdd(&s1, __popc(m1)); atomicAdd(&s2, __popc(m2)); }
    __syncthreads();
    if (t == 0) {
        len1[b] = s1; len2[b] = s2;
        jmin[b] = s1 < s2 ? s1 : s2;
        imax[b] = s1 > s2 ? s1 : s2;
    }
}

// ---------------- U/V de-interleave + fp16 split ----------------
__global__ void convUV_kernel(const float* __restrict__ U, const float* __restrict__ V,
                              __half* __restrict__ Uh, __half* __restrict__ Ul,
                              __half* __restrict__ Vh, __half* __restrict__ Vl) {
    int idx = blockIdx.x * blockDim.x + threadIdx.x;
    if (idx >= KF_ * T_ * O_) return;
    int k = idx >> 17;
    int m = idx & (T_ * O_ - 1);
    float u = U[m * KF_ + k];
    float v = V[m * KF_ + k];
    __half uh = __float2half(u);
    __half vh = __float2half(v);
    Uh[idx] = uh; Ul[idx] = __float2half(u - __half2float(uh));
    Vh[idx] = vh; Vl[idx] = __float2half(v - __half2float(vh));
}

// ---------------- R/Q GEMM: 64(o)x128(t) tile + fused transpose-to-fp16 ----------------
__global__ __launch_bounds__(128) void gemm_rq_kernel(
    const float* __restrict__ A, const float* __restrict__ Bm,
    float* __restrict__ C, __half* __restrict__ Ct,
    const float* __restrict__ bias,
    const float* __restrict__ pad, const int* __restrict__ lenp) {
    int b = blockIdx.z;
    int n0 = blockIdx.x * 128;
    int m0 = blockIdx.y * 64;
    int tid = threadIdx.x;
    if (n0 >= lenp[b]) {
        // masked columns: exactly relu(-1e9)=0
        float4 z = make_float4(0.f, 0.f, 0.f, 0.f);
        #pragma unroll
        for (int e = 0; e < 16; e++) {
            int idx = tid + e * 128;
            int m = idx >> 5, nq = idx & 31;
            *reinterpret_cast<float4*>(&C[((long)b * O_ + m0 + m) * T_ + n0 + nq * 4]) = z;
        }
        uint4 zh = make_uint4(0, 0, 0, 0);
        #pragma unroll
        for (int e = 0; e < 8; e++) {
            int idx = tid + e * 128;             // 0..1023 transfers of 8 halfs
            int n = idx >> 3, mq = idx & 7;      // n 0..127, mq 0..7
            *reinterpret_cast<uint4*>(&Ct[((long)b * T_ + n0 + n) * O_ + m0 + mq * 8]) = zh;
        }
        return;
    }
    const float* Bb = Bm + (long)b * (D_ * T_);
    __shared__ float As[16][68];
    __shared__ float Bs[16][132];
    int tx = tid & 15, ty = tid >> 4;
    float acc[8][8] = {};
    for (int k0 = 0; k0 < D_; k0 += 16) {
        #pragma unroll
        for (int e = 0; e < 2; e++) {
            int idx = tid + e * 128;
            int m = idx >> 2, kq = idx & 3;
            float4 a = *reinterpret_cast<const float4*>(&A[(m0 + m) * D_ + k0 + kq * 4]);
            As[kq * 4 + 0][m] = a.x; As[kq * 4 + 1][m] = a.y;
            As[kq * 4 + 2][m] = a.z; As[kq * 4 + 3][m] = a.w;
        }
        #pragma unroll
        for (int e = 0; e < 4; e++) {
            int idx = tid + e * 128;
            int r = idx >> 5, cq = idx & 31;
            *reinterpret_cast<float4*>(&Bs[r][cq * 4]) =
                *reinterpret_cast<const float4*>(&Bb[(long)(k0 + r) * T_ + n0 + cq * 4]);
        }
        __syncthreads();
        #pragma unroll
        for (int kk = 0; kk < 16; kk++) {
            float4 a0 = *reinterpret_cast<const float4*>(&As[kk][ty * 8]);
            float4 a1 = *reinterpret_cast<const float4*>(&As[kk][ty * 8 + 4]);
            float4 b0 = *reinterpret_cast<const float4*>(&Bs[kk][tx * 8]);
            float4 b1 = *reinterpret_cast<const float4*>(&Bs[kk][tx * 8 + 4]);
            float av[8] = {a0.x, a0.y, a0.z, a0.w, a1.x, a1.y, a1.z, a1.w};
            float bv[8] = {b0.x, b0.y, b0.z, b0.w, b1.x, b1.y, b1.z, b1.w};
            #pragma unroll
            for (int i = 0; i < 8; i++)
                #pragma unroll
                for (int j = 0; j < 8; j++)
                    acc[i][j] += av[i] * bv[j];
        }
        __syncthreads();
    }
    #pragma unroll
    for (int i = 0; i < 8; i++) {
        int m = m0 + ty * 8 + i;
        float bi = bias[m];
        #pragma unroll
        for (int j = 0; j < 8; j++) {
            int n = n0 + tx * 8 + j;
            acc[i][j] = fmaxf(acc[i][j] - NEGC * pad[b * T_ + n] + bi, 0.f);
        }
        float* dst = &C[((long)b * O_ + m) * T_ + n0 + tx * 8];
        *reinterpret_cast<float4*>(dst) = make_float4(acc[i][0], acc[i][1], acc[i][2], acc[i][3]);
        *reinterpret_cast<float4*>(dst + 4) = make_float4(acc[i][4], acc[i][5], acc[i][6], acc[i][7]);
    }
    // fused transposed fp16 write: Ct[b][t=n][o=m]
    #pragma unroll
    for (int j = 0; j < 8; j++) {
        int n = n0 + tx * 8 + j;
        __half h[8];
        #pragma unroll
        for (int i = 0; i < 8; i++) h[i] = __float2half(acc[i][j]);
        *reinterpret_cast<uint4*>(&Ct[((long)b * T_ + n) * O_ + m0 + ty * 8]) =
            *reinterpret_cast<const uint4*>(h);
    }
}

// ---------------- generic 64x64 tile GEMM (W2 only) ----------------
__global__ void gemm64_kernel(const float* __restrict__ A, const float* __restrict__ Bm,
                              float* __restrict__ C, int K, int N, int Mtot,
                              long strideB) {
    int b  = blockIdx.z;
    int n0 = blockIdx.x * 64;
    int m0 = blockIdx.y * 64;
    const float* Bb = Bm + (long)b * strideB;
    __shared__ float As[16][68];
    __shared__ float Bs[16][68];
    int tid = threadIdx.x;
    int tx = tid & 15, ty = tid >> 4;
    float acc[4][4] = {};
    for (int k0 = 0; k0 < K; k0 += 16) {
        #pragma unroll
        for (int p = 0; p < 4; p++) {
            int r = (tid >> 4) + p * 16;
            int c = tid & 15;
            As[c][r] = A[(m0 + r) * K + k0 + c];
        }
        #pragma unroll
        for (int p = 0; p < 4; p++) {
            int r = (tid >> 6) + p * 4;
            int c = tid & 63;
            Bs[r][c] = Bb[(long)(k0 + r) * N + n0 + c];
        }
        __syncthreads();
        #pragma unroll
        for (int kk = 0; kk < 16; kk++) {
            float4 a4 = *reinterpret_cast<const float4*>(&As[kk][ty * 4]);
            float a[4] = {a4.x, a4.y, a4.z, a4.w};
            float4 bb = *reinterpret_cast<const float4*>(&Bs[kk][tx * 4]);
            float bv[4] = {bb.x, bb.y, bb.z, bb.w};
            #pragma unroll
            for (int i = 0; i < 4; i++)
                #pragma unroll
                for (int j = 0; j < 4; j++)
                    acc[i][j] += a[i] * bv[j];
        }
        __syncthreads();
    }
    #pragma unroll
    for (int i = 0; i < 4; i++) {
        int m = m0 + ty * 4 + i;
        #pragma unroll
        for (int j = 0; j < 4; j++) {
            int n = n0 + tx * 4 + j;
            C[(long)b * Mtot * N + (long)m * N + n] = acc[i][j];
        }
    }
}

// ======================= fp16 HMMA F kernel (2-term split) =======================
// SMEM: A ring 2 stages x 4 arr x 8KB = 64KB at 0; B persistent 2 arr x 32KB at 65536.
#define FS_B 65536
#define FS_TOTAL 131072

__global__ __launch_bounds__(256, 1) void f_mma_kernel(
    const __half* __restrict__ Uh, const __half* __restrict__ Ul,
    const __half* __restrict__ Vh, const __half* __restrict__ Vl,
    const __half* __restrict__ Rt, const __half* __restrict__ Qt,
    float* __restrict__ F, const int* __restrict__ jmin, const int* __restrict__ imax) {
    extern __shared__ char sm[];
    uint32_t sb = smem_to_u32(sm);
    int tid = threadIdx.x, lane = tid & 31, w = tid >> 5;
    int wi = w >> 1, wj = w & 1;
    int b = blockIdx.z, i0 = blockIdx.y * 128, j0 = blockIdx.x * 64;
    int l16 = lane & 15, lh = lane >> 4;

    if (i0 >= imax[b]) return;   // rows only consumed with exactly-zero weights

    if (j0 >= jmin[b]) {         // fully masked j-tile: F exactly zero
        int row = tid >> 1, half = tid & 1;
        float4 z = make_float4(0.f, 0.f, 0.f, 0.f);
        float* dst = F + ((long)b * T_ + i0 + row) * T_ + j0 + half * 32;
        #pragma unroll
        for (int e = 0; e < 8; e++) reinterpret_cast<float4*>(dst)[e] = z;
        return;
    }

    const __half* apt[4] = {Uh, Ul, Vh, Vl};
    const __half* bpt[2] = {Rt, Qt};

    // ---- B persistent: 2 arr x [64j][256o] fp16, chunked per 32 o ----
    #pragma unroll
    for (int arr = 0; arr < 2; arr++) {
        const __half* src = bpt[arr] + ((long)b * T_ + j0) * O_;
        #pragma unroll
        for (int e = 0; e < 8; e++) {
            int idx = tid + e * 256;              // 0..2047
            int ch = idx >> 8;
            int row = (idx & 255) >> 2;
            int cb = (idx & 3) * 16;
            const void* g = src + (long)row * O_ + ch * 32 + cb / 2;
            cpasync16(sb + FS_B + arr * 32768 + ch * 4096 + paddr(row, cb), g);
        }
    }
    CP_COMMIT();

    auto load_a = [&](int cu, int st) {
        int k = cu >> 3, ch = cu & 7;
        #pragma unroll
        for (int arr = 0; arr < 4; arr++) {
            const __half* src = apt[arr] + ((long)k * T_ + i0) * O_ + ch * 32;
            #pragma unroll
            for (int e = 0; e < 2; e++) {
                int idx = tid + e * 256;
                int row = idx >> 2;
                int cb = (idx & 3) * 16;
                const void* g = src + (long)row * O_ + cb / 2;
                cpasync16(sb + st * 32768 + arr * 8192 + paddr(row, cb), g);
            }
        }
    };

    load_a(0, 0);
    CP_COMMIT();

    float f[32], d1[32], d2[32];
    #pragma unroll
    for (int i = 0; i < 32; i++) { f[i] = 0.f; d1[i] = 0.f; d2[i] = 0.f; }

    for (int cu = 0; cu < 64; cu++) {
        int st = cu & 1, ch = cu & 7;
        if (cu + 1 < 64) {
            load_a(cu + 1, (cu + 1) & 1);
            CP_COMMIT();
            CP_WAIT(1);
        } else {
            CP_WAIT(0);
        }
        __syncthreads();

        uint32_t abase = sb + st * 32768;
        #pragma unroll
        for (int os = 0; os < 2; os++) {
            uint32_t colb = (uint32_t)(os * 32 + lh * 16);
            uint32_t arow = (uint32_t)(wi * 32 + l16);
            uint32_t brow = (uint32_t)(wj * 32 + l16);
            // ---- pass 1: d1 += (Uh+Ul) . Rt ----
            {
                uint32_t ah0[4], ah1[4], al0[4], al1[4];
                ldsm4(ah0, abase + 0 * 8192 + paddr(arow, colb));
                ldsm4(ah1, abase + 0 * 8192 + paddr(arow + 16, colb));
                ldsm4(al0, abase + 1 * 8192 + paddr(arow, colb));
                ldsm4(al1, abase + 1 * 8192 + paddr(arow + 16, colb));
                uint32_t bh0[4], bh1[4];
                uint32_t bb0 = sb + FS_B + 0 * 32768 + ch * 4096;
                ldsm4(bh0, bb0 + paddr(brow, colb));
                ldsm4(bh1, bb0 + paddr(brow + 16, colb));
                #pragma unroll
                for (int term = 0; term < 2; term++) {
                    const uint32_t* A0 = term ? al0 : ah0;
                    const uint32_t* A1 = term ? al1 : ah1;
                    #pragma unroll
                    for (int mt = 0; mt < 2; mt++) {
                        const uint32_t* a = mt ? A1 : A0;
                        #pragma unroll
                        for (int nt = 0; nt < 4; nt++) {
                            const uint32_t* bb = (nt >> 1) ? bh1 : bh0;
                            int s = nt & 1;
                            mma16816h(d1 + (mt * 4 + nt) * 4, a, bb[s], bb[s + 2]);
                        }
                    }
                }
            }
            // ---- pass 2: d2 += (Vh+Vl) . Qt ----
            {
                uint32_t ah0[4], ah1[4], al0[4], al1[4];
                ldsm4(ah0, abase + 2 * 8192 + paddr(arow, colb));
                ldsm4(ah1, abase + 2 * 8192 + paddr(arow + 16, colb));
                ldsm4(al0, abase + 3 * 8192 + paddr(arow, colb));
                ldsm4(al1, abase + 3 * 8192 + paddr(arow + 16, colb));
                uint32_t bh0[4], bh1[4];
                uint32_t bb1 = sb + FS_B + 1 * 32768 + ch * 4096;
                ldsm4(bh0, bb1 + paddr(brow, colb));
                ldsm4(bh1, bb1 + paddr(brow + 16, colb));
                #pragma unroll
                for (int term = 0; term < 2; term++) {
                    const uint32_t* A0 = term ? al0 : ah0;
                    const uint32_t* A1 = term ? al1 : ah1;
                    #pragma unroll
                    for (int mt = 0; mt < 2; mt++) {
                        const uint32_t* a = mt ? A1 : A0;
                        #pragma unroll
                        for (int nt = 0; nt < 4; nt++) {
                            const uint32_t* bb = (nt >> 1) ? bh1 : bh0;
                            int s = nt & 1;
                            mma16816h(d2 + (mt * 4 + nt) * 4, a, bb[s], bb[s + 2]);
                        }
                    }
                }
            }
        }
        if (ch == 7) {
            #pragma unroll
            for (int i = 0; i < 32; i++) {
                f[i] += d1[i] * d2[i];
                d1[i] = 0.f; d2[i] = 0.f;
            }
        }
        __syncthreads();
    }

    int r4 = lane >> 2, c2 = (lane & 3) * 2;
    #pragma unroll
    for (int mt = 0; mt < 2; mt++) {
        #pragma unroll
        for (int nt = 0; nt < 4; nt++) {
            float* d = f + (mt * 4 + nt) * 4;
            long row = i0 + wi * 32 + mt * 16 + r4;
            long col = j0 + wj * 32 + nt * 8 + c2;
            float* dst = F + ((long)b * T_ + row) * T_ + col;
            dst[0] = d[0]; dst[1] = d[1];
            dst[8 * T_] = d[2]; dst[8 * T_ + 1] = d[3];
        }
    }
}

// ---------------- fused M + d kernel ----------------
__global__ void md_kernel(const float* __restrict__ Bias, const float* __restrict__ Mul,
                          const float* __restrict__ F, const float* __restrict__ w,
                          const float* __restrict__ pad, float* __restrict__ d,
                          const int* __restrict__ lencol, const int* __restrict__ lenmul) {
    int b  = blockIdx.y;
    int c0 = blockIdx.x * 64;
    int tid = threadIdx.x;
    if (c0 >= lencol[b]) {
        if (tid < 64) d[b * T_ + c0 + tid] = -NEGC;
        return;
    }
    int ibound = (lenmul[b] + 15) & ~15;
    __shared__ float Ms[16][68];
    __shared__ float Fs[16][68];
    __shared__ float red[16][64];
    int tx = tid & 15, ty = tid >> 4;
    float acc[4][4] = {};
    const float* Mb = Mul + (long)b * G_ * T_;
    const float* Fb = F   + (long)b * T_ * T_;
    for (int i0 = 0; i0 < ibound; i0 += 16) {
        #pragma unroll
        for (int p = 0; p < 4; p++) {
            int r = (tid >> 4) + p * 16;
            int c = tid & 15;
            Ms[c][r] = Mb[r * T_ + i0 + c];
        }
        #pragma unroll
        for (int p = 0; p < 4; p++) {
            int r = (tid >> 6) + p * 4;
            int c = tid & 63;
            Fs[r][c] = Fb[(long)(i0 + r) * T_ + c0 + c];
        }
        __syncthreads();
        #pragma unroll
        for (int ii = 0; ii < 16; ii++) {
            float4 m4 = *reinterpret_cast<const float4*>(&Ms[ii][ty * 4]);
            float m[4] = {m4.x, m4.y, m4.z, m4.w};
            float4 f4 = *reinterpret_cast<const float4*>(&Fs[ii][tx * 4]);
            float ff[4] = {f4.x, f4.y, f4.z, f4.w};
            #pragma unroll
            for (int i = 0; i < 4; i++)
                #pragma unroll
                for (int j = 0; j < 4; j++)
                    acc[i][j] += m[i] * ff[j];
        }
        __syncthreads();
    }
    float part[4] = {0.f, 0.f, 0.f, 0.f};
    #pragma unroll
    for (int gq = 0; gq < 4; gq++) {
        int g = ty * 4 + gq;
        float wg = w[g];
        #pragma unroll
        for (int c = 0; c < 4; c++) {
            float vv = acc[gq][c] + Bias[(long)b * G_ * T_ + g * T_ + c0 + tx * 4 + c];
            part[c] += wg * fmaxf(vv, 0.f);
        }
    }
    #pragma unroll
    for (int c = 0; c < 4; c++) red[ty][tx * 4 + c] = part[c];
    __syncthreads();
    #pragma unroll
    for (int s = 8; s > 0; s >>= 1) {
        if (ty < s) {
            #pragma unroll
            for (int c = 0; c < 4; c++) red[ty][tx * 4 + c] += red[ty + s][tx * 4 + c];
        }
        __syncthreads();
    }
    if (ty == 0) {
        #pragma unroll
        for (int c = 0; c < 4; c++) {
            int col = c0 + tx * 4 + c;
            d[b * T_ + col] = red[0][tx * 4 + c] - NEGC * pad[b * T_ + col];
        }
    }
}

// ---------------- softmax ----------------
__global__ void softmax_kernel(const float* __restrict__ d1, const float* __restrict__ d2,
                               float* __restrict__ g1, float* __restrict__ g2) {
    int b = blockIdx.x;
    const float* d = blockIdx.y ? d2 : d1;
    float* g = blockIdx.y ? g2 : g1;
    int t = threadIdx.x;
    float v = d[b * T_ + t];
    __shared__ float red[16];
    float m = v;
    #pragma unroll
    for (int o = 16; o; o >>= 1) m = fmaxf(m, __shfl_xor_sync(0xffffffffu, m, o));
    if ((t & 31) == 0) red[t >> 5] = m;
    __syncthreads();
    if (t < 32) {
        float x = (t < 16) ? red[t] : -3.4e38f;
        #pragma unroll
        for (int o = 8; o; o >>= 1) x = fmaxf(x, __shfl_xor_sync(0xffffffffu, x, o));
        if (t == 0) red[0] = x;
    }
    __syncthreads();
    float mx = red[0];
    __syncthreads();
    float e = expf(v - mx);
    float s = e;
    #pragma unroll
    for (int o = 16; o; o >>= 1) s += __shfl_xor_sync(0xffffffffu, s, o);
    if ((t & 31) == 0) red[t >> 5] = s;
    __syncthreads();
    if (t < 32) {
        float x = (t < 16) ? red[t] : 0.f;
        #pragma unroll
        for (int o = 8; o; o >>= 1) x += __shfl_xor_sync(0xffffffffu, x, o);
        if (t == 0) red[0] = x;
    }
    __syncthreads();
    g[b * T_ + t] = e / red[0];
}

// ---------------- final reduction ----------------
__global__ void final_kernel(const float* __restrict__ R, const float* __restrict__ Q,
                             const float* __restrict__ gv, const float* __restrict__ gq,
                             float* __restrict__ out) {
    int b = blockIdx.x;
    __shared__ float sgv[T_], sgq[T_];
    int tid = threadIdx.x;
    sgv[tid] = gv[b * T_ + tid];
    sgq[tid] = gq[b * T_ + tid];
    __syncthreads();
    int o = tid & 255;
    int h = tid >> 8;
    const float* Rb = R + (long)b * O_ * T_;
    const float* Qb = Q + (long)b * O_ * T_;
    float tr = 0.f, lg = 0.f;
    #pragma unroll 4
    for (int t = h * 256; t < h * 256 + 256; t++) {
        tr += sgv[t] * Rb[t * O_ + o];
        lg += sgq[t] * Qb[t * O_ + o];
    }
    __shared__ float str[2][256], slg[2][256];
    str[h][o] = tr;
    slg[h][o] = lg;
    __syncthreads();
    if (h == 0) out[b * O_ + o] = (str[0][o] + str[1][o]) * (slg[0][o] + slg[1][o]);
}

// ---------------- launcher ----------------
extern "C" void kernel_launch(void* const* d_in, const int* in_sizes, int n_in,
                              void* d_out, int out_size) {
    const float* x0  = (const float*)d_in[0];
    const float* x1  = (const float*)d_in[1];
    const unsigned char* qm = (const unsigned char*)d_in[2];
    const unsigned char* vm = (const unsigned char*)d_in[3];
    const float* W_R = (const float*)d_in[4];
    const float* W_Q = (const float*)d_in[5];
    const float* br  = (const float*)d_in[6];
    const float* bq  = (const float*)d_in[7];
    const float* U   = (const float*)d_in[8];
    const float* V   = (const float*)d_in[9];
    const float* W2R = (const float*)d_in[10];
    const float* W2Q = (const float*)d_in[11];
    const float* wmv = (const float*)d_in[12];
    const float* wmq = (const float*)d_in[13];
    float* out = (float*)d_out;

    float *pR, *pQ, *pF, *pWR, *pWQ, *pd1, *pd2, *pg1, *pg2, *ppq, *ppv;
    int *pl1, *pl2, *pjm, *pim;
    __half *pUh, *pUl, *pVh, *pVl, *pRt, *pQt;
    cudaGetSymbolAddress((void**)&pR,  g_R);
    cudaGetSymbolAddress((void**)&pQ,  g_Q);
    cudaGetSymbolAddress((void**)&pF,  g_F);
    cudaGetSymbolAddress((void**)&pWR, g_WR);
    cudaGetSymbolAddress((void**)&pWQ, g_WQ);
    cudaGetSymbolAddress((void**)&pd1, g_d1);
    cudaGetSymbolAddress((void**)&pd2, g_d2);
    cudaGetSymbolAddress((void**)&pg1, g_g1);
    cudaGetSymbolAddress((void**)&pg2, g_g2);
    cudaGetSymbolAddress((void**)&ppq, g_pq);
    cudaGetSymbolAddress((void**)&ppv, g_pv);
    cudaGetSymbolAddress((void**)&pl1, g_len1);
    cudaGetSymbolAddress((void**)&pl2, g_len2);
    cudaGetSymbolAddress((void**)&pjm, g_jmin);
    cudaGetSymbolAddress((void**)&pim, g_imax);
    cudaGetSymbolAddress((void**)&pUh, g_Ukh);
    cudaGetSymbolAddress((void**)&pUl, g_Ukl);
    cudaGetSymbolAddress((void**)&pVh, g_Vkh);
    cudaGetSymbolAddress((void**)&pVl, g_Vkl);
    cudaGetSymbolAddress((void**)&pRt, g_Rt);
    cudaGetSymbolAddress((void**)&pQt, g_Qt);

    static bool attr_done = false;
    if (!attr_done) {
        cudaFuncSetAttribute(f_mma_kernel, cudaFuncAttributeMaxDynamicSharedMemorySize, FS_TOTAL);
        attr_done = true;
    }

    maskconv_kernel<<<(B_ * T_ + 255) / 256, 256>>>(qm, vm, ppq, ppv);
    lens_kernel<<<B_, T_>>>(qm, vm, pl1, pl2, pjm, pim);
    convUV_kernel<<<(KF_ * T_ * O_ + 255) / 256, 256>>>(U, V, pUh, pUl, pVh, pVl);

    gemm_rq_kernel<<<dim3(T_ / 128, O_ / 64, B_), 128>>>(W_R, x0, pR, pRt, br, ppq, pl1);
    gemm_rq_kernel<<<dim3(T_ / 128, O_ / 64, B_), 128>>>(W_Q, x1, pQ, pQt, bq, ppv, pl2);

    f_mma_kernel<<<dim3(T_ / 64, T_ / 128, B_), 256, FS_TOTAL>>>(
        pUh, pUl, pVh, pVl, pRt, pQt, pF, pjm, pim);

    gemm64_kernel<<<dim3(T_ / 64, 1, B_), 256>>>(
        W2R, pR, pWR, O_, T_, G_, (long)O_ * T_);
    gemm64_kernel<<<dim3(T_ / 64, 1, B_), 256>>>(
        W2Q, pQ, pWQ, O_, T_, G_, (long)O_ * T_);

    md_kernel<<<dim3(T_ / 64, B_), 256>>>(pWR, pWQ, pF, wmv, ppq, pd1, pl1, pl2);
    md_kernel<<<dim3(T_ / 64, B_), 256>>>(pWQ, pWR, pF, wmq, ppv, pd2, pl2, pl1);

    softmax_kernel<<<dim3(B_, 2), T_>>>(pd1, pd2, pg1, pg2);

    final_kernel<<<B_, T_>>>(pR, pQ, pg1, pg2, out);
}

// round 9
// speedup vs baseline: 1.5442x; 1.2935x over previous
#include <cuda_runtime.h>
#include <cuda_fp16.h>
#include <cstdint>

#define NEGC 1e9f

#define B_  32
#define T_  512
#define D_  256
#define O_  256
#define KF_ 8
#define G_  64

// ---------------- scratch ----------------
__device__ float g_R [B_ * O_ * T_];
__device__ float g_Q [B_ * O_ * T_];
__device__ float g_F [B_ * T_ * T_];
__device__ float g_WR[B_ * G_ * T_];
__device__ float g_WQ[B_ * G_ * T_];
__device__ float g_d1[B_ * T_];
__device__ float g_d2[B_ * T_];
__device__ float g_g1[B_ * T_];
__device__ float g_g2[B_ * T_];
__device__ float g_pq[B_ * T_];
__device__ float g_pv[B_ * T_];
__device__ int   g_len1[B_];
__device__ int   g_len2[B_];
__device__ int   g_jmin[B_];
__device__ int   g_imax[B_];

// fp16 operands (single precision on both sides for F)
__device__ __half g_Uk[KF_ * T_ * O_];
__device__ __half g_Vk[KF_ * T_ * O_];
__device__ __half g_Rt[B_ * T_ * O_];   // R transposed [b][t][o], fp16
__device__ __half g_Qt[B_ * T_ * O_];

// =================== helpers ===================
__device__ __forceinline__ uint32_t smem_to_u32(const void* p) {
    uint32_t a;
    asm("{ .reg .u64 t; cvta.to.shared.u64 t, %1; cvt.u32.u64 %0, t; }" : "=r"(a) : "l"(p));
    return a;
}
__device__ __forceinline__ void ldsm4(uint32_t* r, uint32_t addr) {
    asm volatile("ldmatrix.sync.aligned.m8n8.x4.shared.b16 {%0,%1,%2,%3}, [%4];"
        : "=r"(r[0]), "=r"(r[1]), "=r"(r[2]), "=r"(r[3]) : "r"(addr));
}
__device__ __forceinline__ void mma16816h(float* d, const uint32_t* a,
                                          uint32_t b0, uint32_t b1) {
    asm volatile("mma.sync.aligned.m16n8k16.row.col.f32.f16.f16.f32 "
        "{%0,%1,%2,%3}, {%4,%5,%6,%7}, {%8,%9}, {%0,%1,%2,%3};"
        : "+f"(d[0]), "+f"(d[1]), "+f"(d[2]), "+f"(d[3])
        : "r"(a[0]), "r"(a[1]), "r"(a[2]), "r"(a[3]), "r"(b0), "r"(b1));
}
__device__ __forceinline__ void cpasync16(uint32_t dst, const void* src) {
    asm volatile("cp.async.cg.shared.global [%0], [%1], 16;" :: "r"(dst), "l"(src));
}
#define CP_COMMIT() asm volatile("cp.async.commit_group;" ::: "memory")
#define CP_WAIT(n)  asm volatile("cp.async.wait_group %0;" :: "n"(n) : "memory")

__device__ __forceinline__ uint32_t paddr(uint32_t row, uint32_t cb) {
    uint32_t pr = row >> 1;
    return pr * 128 + ((((row & 1) << 6) + cb) ^ ((pr & 7) << 4));
}

__device__ __forceinline__ void decode_mask(const unsigned char* q, const unsigned char* v,
                                            int i, bool& qv, bool& vv) {
    unsigned char b1 = q[1], b3 = q[3];
    int type = (b1 == 1) ? 0 : (b1 == 0x3F) ? 3 : (b3 == 0x3F) ? 2 : 1;
    switch (type) {
        case 0: qv = q[i] != 0;                            vv = v[i] != 0; break;
        case 1: qv = ((const int*)q)[i] != 0;              vv = ((const int*)v)[i] != 0; break;
        case 2: qv = ((const float*)q)[i] != 0.f;          vv = ((const float*)v)[i] != 0.f; break;
        default: qv = ((const unsigned short*)q)[i] != 0;  vv = ((const unsigned short*)v)[i] != 0; break;
    }
}

// ---------------- mask decode ----------------
__global__ void maskconv_kernel(const unsigned char* __restrict__ q,
                                const unsigned char* __restrict__ v,
                                float* __restrict__ pq, float* __restrict__ pv) {
    int i = blockIdx.x * blockDim.x + threadIdx.x;
    if (i >= B_ * T_) return;
    bool qv, vv;
    decode_mask(q, v, i, qv, vv);
    pq[i] = qv ? 0.f : 1.f;
    pv[i] = vv ? 0.f : 1.f;
}

// ---------------- per-batch valid lengths ----------------
__global__ void lens_kernel(const unsigned char* __restrict__ q,
                            const unsigned char* __restrict__ v,
                            int* __restrict__ len1, int* __restrict__ len2,
                            int* __restrict__ jmin, int* __restrict__ imax) {
    __shared__ int s1, s2;
    int b = blockIdx.x, t = threadIdx.x;
    if (t == 0) { s1 = 0; s2 = 0; }
    __syncthreads();
    bool qv, vv;
    decode_mask(q, v, b * T_ + t, qv, vv);
    unsigned m1 = __ballot_sync(0xffffffffu, qv);
    unsigned m2 = __ballot_sync(0xffffffffu, vv);
    if ((t & 31) == 0) { atomicAdd(&s1, __popc(m1)); atomicAdd(&s2, __popc(m2)); }
    __syncthreads();
    if (t == 0) {
        len1[b] = s1; len2[b] = s2;
        jmin[b] = s1 < s2 ? s1 : s2;
        imax[b] = s1 > s2 ? s1 : s2;
    }
}

// ---------------- U/V de-interleave + fp16 convert ----------------
__global__ void convUV_kernel(const float* __restrict__ U, const float* __restrict__ V,
                              __half* __restrict__ Uo, __half* __restrict__ Vo) {
    int idx = blockIdx.x * blockDim.x + threadIdx.x;
    if (idx >= KF_ * T_ * O_) return;
    int k = idx >> 17;
    int m = idx & (T_ * O_ - 1);
    Uo[idx] = __float2half(U[m * KF_ + k]);
    Vo[idx] = __float2half(V[m * KF_ + k]);
}

// ---------------- R/Q GEMM: 64(o)x128(t) tile + fused transpose-to-fp16 ----------------
__global__ __launch_bounds__(128) void gemm_rq_kernel(
    const float* __restrict__ A, const float* __restrict__ Bm,
    float* __restrict__ C, __half* __restrict__ Ct,
    const float* __restrict__ bias,
    const float* __restrict__ pad, const int* __restrict__ lenp) {
    int b = blockIdx.z;
    int n0 = blockIdx.x * 128;
    int m0 = blockIdx.y * 64;
    int tid = threadIdx.x;
    if (n0 >= lenp[b]) {
        float4 z = make_float4(0.f, 0.f, 0.f, 0.f);
        #pragma unroll
        for (int e = 0; e < 16; e++) {
            int idx = tid + e * 128;
            int m = idx >> 5, nq = idx & 31;
            *reinterpret_cast<float4*>(&C[((long)b * O_ + m0 + m) * T_ + n0 + nq * 4]) = z;
        }
        uint4 zh = make_uint4(0, 0, 0, 0);
        #pragma unroll
        for (int e = 0; e < 8; e++) {
            int idx = tid + e * 128;
            int n = idx >> 3, mq = idx & 7;
            *reinterpret_cast<uint4*>(&Ct[((long)b * T_ + n0 + n) * O_ + m0 + mq * 8]) = zh;
        }
        return;
    }
    const float* Bb = Bm + (long)b * (D_ * T_);
    __shared__ float As[16][68];
    __shared__ float Bs[16][132];
    int tx = tid & 15, ty = tid >> 4;
    float acc[8][8] = {};
    for (int k0 = 0; k0 < D_; k0 += 16) {
        #pragma unroll
        for (int e = 0; e < 2; e++) {
            int idx = tid + e * 128;
            int m = idx >> 2, kq = idx & 3;
            float4 a = *reinterpret_cast<const float4*>(&A[(m0 + m) * D_ + k0 + kq * 4]);
            As[kq * 4 + 0][m] = a.x; As[kq * 4 + 1][m] = a.y;
            As[kq * 4 + 2][m] = a.z; As[kq * 4 + 3][m] = a.w;
        }
        #pragma unroll
        for (int e = 0; e < 4; e++) {
            int idx = tid + e * 128;
            int r = idx >> 5, cq = idx & 31;
            *reinterpret_cast<float4*>(&Bs[r][cq * 4]) =
                *reinterpret_cast<const float4*>(&Bb[(long)(k0 + r) * T_ + n0 + cq * 4]);
        }
        __syncthreads();
        #pragma unroll
        for (int kk = 0; kk < 16; kk++) {
            float4 a0 = *reinterpret_cast<const float4*>(&As[kk][ty * 8]);
            float4 a1 = *reinterpret_cast<const float4*>(&As[kk][ty * 8 + 4]);
            float4 b0 = *reinterpret_cast<const float4*>(&Bs[kk][tx * 8]);
            float4 b1 = *reinterpret_cast<const float4*>(&Bs[kk][tx * 8 + 4]);
            float av[8] = {a0.x, a0.y, a0.z, a0.w, a1.x, a1.y, a1.z, a1.w};
            float bv[8] = {b0.x, b0.y, b0.z, b0.w, b1.x, b1.y, b1.z, b1.w};
            #pragma unroll
            for (int i = 0; i < 8; i++)
                #pragma unroll
                for (int j = 0; j < 8; j++)
                    acc[i][j] += av[i] * bv[j];
        }
        __syncthreads();
    }
    #pragma unroll
    for (int i = 0; i < 8; i++) {
        int m = m0 + ty * 8 + i;
        float bi = bias[m];
        #pragma unroll
        for (int j = 0; j < 8; j++) {
            int n = n0 + tx * 8 + j;
            acc[i][j] = fmaxf(acc[i][j] - NEGC * pad[b * T_ + n] + bi, 0.f);
        }
        float* dst = &C[((long)b * O_ + m) * T_ + n0 + tx * 8];
        *reinterpret_cast<float4*>(dst) = make_float4(acc[i][0], acc[i][1], acc[i][2], acc[i][3]);
        *reinterpret_cast<float4*>(dst + 4) = make_float4(acc[i][4], acc[i][5], acc[i][6], acc[i][7]);
    }
    #pragma unroll
    for (int j = 0; j < 8; j++) {
        int n = n0 + tx * 8 + j;
        __half h[8];
        #pragma unroll
        for (int i = 0; i < 8; i++) h[i] = __float2half(acc[i][j]);
        *reinterpret_cast<uint4*>(&Ct[((long)b * T_ + n) * O_ + m0 + ty * 8]) =
            *reinterpret_cast<const uint4*>(h);
    }
}

// ---------------- generic 64x64 tile GEMM (W2 only) ----------------
__global__ void gemm64_kernel(const float* __restrict__ A, const float* __restrict__ Bm,
                              float* __restrict__ C, int K, int N, int Mtot,
                              long strideB) {
    int b  = blockIdx.z;
    int n0 = blockIdx.x * 64;
    int m0 = blockIdx.y * 64;
    const float* Bb = Bm + (long)b * strideB;
    __shared__ float As[16][68];
    __shared__ float Bs[16][68];
    int tid = threadIdx.x;
    int tx = tid & 15, ty = tid >> 4;
    float acc[4][4] = {};
    for (int k0 = 0; k0 < K; k0 += 16) {
        #pragma unroll
        for (int p = 0; p < 4; p++) {
            int r = (tid >> 4) + p * 16;
            int c = tid & 15;
            As[c][r] = A[(m0 + r) * K + k0 + c];
        }
        #pragma unroll
        for (int p = 0; p < 4; p++) {
            int r = (tid >> 6) + p * 4;
            int c = tid & 63;
            Bs[r][c] = Bb[(long)(k0 + r) * N + n0 + c];
        }
        __syncthreads();
        #pragma unroll
        for (int kk = 0; kk < 16; kk++) {
            float4 a4 = *reinterpret_cast<const float4*>(&As[kk][ty * 4]);
            float a[4] = {a4.x, a4.y, a4.z, a4.w};
            float4 bb = *reinterpret_cast<const float4*>(&Bs[kk][tx * 4]);
            float bv[4] = {bb.x, bb.y, bb.z, bb.w};
            #pragma unroll
            for (int i = 0; i < 4; i++)
                #pragma unroll
                for (int j = 0; j < 4; j++)
                    acc[i][j] += a[i] * bv[j];
        }
        __syncthreads();
    }
    #pragma unroll
    for (int i = 0; i < 4; i++) {
        int m = m0 + ty * 4 + i;
        #pragma unroll
        for (int j = 0; j < 4; j++) {
            int n = n0 + tx * 4 + j;
            C[(long)b * Mtot * N + (long)m * N + n] = acc[i][j];
        }
    }
}

// ======================= fp16 HMMA F kernel (single-precision operands) =======================
// SMEM: A ring 2 stages x 2 arr x 8KB = 32KB at 0; B persistent 2 arr x 32KB at 32768.
#define FS_B 32768
#define FS_TOTAL 98304

__global__ __launch_bounds__(256, 1) void f_mma_kernel(
    const __half* __restrict__ Uk, const __half* __restrict__ Vk,
    const __half* __restrict__ Rt, const __half* __restrict__ Qt,
    float* __restrict__ F, const int* __restrict__ jmin, const int* __restrict__ imax) {
    extern __shared__ char sm[];
    uint32_t sb = smem_to_u32(sm);
    int tid = threadIdx.x, lane = tid & 31, w = tid >> 5;
    int wi = w >> 1, wj = w & 1;
    int b = blockIdx.z, i0 = blockIdx.y * 128, j0 = blockIdx.x * 64;
    int l16 = lane & 15, lh = lane >> 4;

    if (i0 >= imax[b]) return;

    if (j0 >= jmin[b]) {
        int row = tid >> 1, half = tid & 1;
        float4 z = make_float4(0.f, 0.f, 0.f, 0.f);
        float* dst = F + ((long)b * T_ + i0 + row) * T_ + j0 + half * 32;
        #pragma unroll
        for (int e = 0; e < 8; e++) reinterpret_cast<float4*>(dst)[e] = z;
        return;
    }

    const __half* apt[2] = {Uk, Vk};
    const __half* bpt[2] = {Rt, Qt};

    // ---- B persistent: 2 arr x [64j][256o] fp16, chunked per 32 o ----
    #pragma unroll
    for (int arr = 0; arr < 2; arr++) {
        const __half* src = bpt[arr] + ((long)b * T_ + j0) * O_;
        #pragma unroll
        for (int e = 0; e < 8; e++) {
            int idx = tid + e * 256;
            int ch = idx >> 8;
            int row = (idx & 255) >> 2;
            int cb = (idx & 3) * 16;
            const void* g = src + (long)row * O_ + ch * 32 + cb / 2;
            cpasync16(sb + FS_B + arr * 32768 + ch * 4096 + paddr(row, cb), g);
        }
    }
    CP_COMMIT();

    auto load_a = [&](int cu, int st) {
        int k = cu >> 3, ch = cu & 7;
        #pragma unroll
        for (int arr = 0; arr < 2; arr++) {
            const __half* src = apt[arr] + ((long)k * T_ + i0) * O_ + ch * 32;
            #pragma unroll
            for (int e = 0; e < 2; e++) {
                int idx = tid + e * 256;
                int row = idx >> 2;
                int cb = (idx & 3) * 16;
                const void* g = src + (long)row * O_ + cb / 2;
                cpasync16(sb + st * 16384 + arr * 8192 + paddr(row, cb), g);
            }
        }
    };

    load_a(0, 0);
    CP_COMMIT();

    float f[32], d1[32], d2[32];
    #pragma unroll
    for (int i = 0; i < 32; i++) { f[i] = 0.f; d1[i] = 0.f; d2[i] = 0.f; }

    for (int cu = 0; cu < 64; cu++) {
        int st = cu & 1, ch = cu & 7;
        if (cu + 1 < 64) {
            load_a(cu + 1, (cu + 1) & 1);
            CP_COMMIT();
            CP_WAIT(1);
        } else {
            CP_WAIT(0);
        }
        __syncthreads();

        uint32_t abase = sb + st * 16384;
        #pragma unroll
        for (int os = 0; os < 2; os++) {
            uint32_t colb = (uint32_t)(os * 32 + lh * 16);
            uint32_t arow = (uint32_t)(wi * 32 + l16);
            uint32_t brow = (uint32_t)(wj * 32 + l16);
            // ---- pass 1: d1 += U . Rt ----
            {
                uint32_t a0[4], a1[4], b0r[4], b1r[4];
                ldsm4(a0, abase + 0 * 8192 + paddr(arow, colb));
                ldsm4(a1, abase + 0 * 8192 + paddr(arow + 16, colb));
                uint32_t bb0 = sb + FS_B + 0 * 32768 + ch * 4096;
                ldsm4(b0r, bb0 + paddr(brow, colb));
                ldsm4(b1r, bb0 + paddr(brow + 16, colb));
                #pragma unroll
                for (int mt = 0; mt < 2; mt++) {
                    const uint32_t* a = mt ? a1 : a0;
                    #pragma unroll
                    for (int nt = 0; nt < 4; nt++) {
                        const uint32_t* bb = (nt >> 1) ? b1r : b0r;
                        int s = nt & 1;
                        mma16816h(d1 + (mt * 4 + nt) * 4, a, bb[s], bb[s + 2]);
                    }
                }
            }
            // ---- pass 2: d2 += V . Qt ----
            {
                uint32_t a0[4], a1[4], b0r[4], b1r[4];
                ldsm4(a0, abase + 1 * 8192 + paddr(arow, colb));
                ldsm4(a1, abase + 1 * 8192 + paddr(arow + 16, colb));
                uint32_t bb1 = sb + FS_B + 1 * 32768 + ch * 4096;
                ldsm4(b0r, bb1 + paddr(brow, colb));
                ldsm4(b1r, bb1 + paddr(brow + 16, colb));
                #pragma unroll
                for (int mt = 0; mt < 2; mt++) {
                    const uint32_t* a = mt ? a1 : a0;
                    #pragma unroll
                    for (int nt = 0; nt < 4; nt++) {
                        const uint32_t* bb = (nt >> 1) ? b1r : b0r;
                        int s = nt & 1;
                        mma16816h(d2 + (mt * 4 + nt) * 4, a, bb[s], bb[s + 2]);
                    }
                }
            }
        }
        if (ch == 7) {
            #pragma unroll
            for (int i = 0; i < 32; i++) {
                f[i] += d1[i] * d2[i];
                d1[i] = 0.f; d2[i] = 0.f;
            }
        }
        __syncthreads();
    }

    int r4 = lane >> 2, c2 = (lane & 3) * 2;
    #pragma unroll
    for (int mt = 0; mt < 2; mt++) {
        #pragma unroll
        for (int nt = 0; nt < 4; nt++) {
            float* d = f + (mt * 4 + nt) * 4;
            long row = i0 + wi * 32 + mt * 16 + r4;
            long col = j0 + wj * 32 + nt * 8 + c2;
            float* dst = F + ((long)b * T_ + row) * T_ + col;
            dst[0] = d[0]; dst[1] = d[1];
            dst[8 * T_] = d[2]; dst[8 * T_ + 1] = d[3];
        }
    }
}

// ---------------- fused M + d kernel ----------------
__global__ void md_kernel(const float* __restrict__ Bias, const float* __restrict__ Mul,
                          const float* __restrict__ F, const float* __restrict__ w,
                          const float* __restrict__ pad, float* __restrict__ d,
                          const int* __restrict__ lencol, const int* __restrict__ lenmul) {
    int b  = blockIdx.y;
    int c0 = blockIdx.x * 64;
    int tid = threadIdx.x;
    if (c0 >= lencol[b]) {
        if (tid < 64) d[b * T_ + c0 + tid] = -NEGC;
        return;
    }
    int ibound = (lenmul[b] + 15) & ~15;
    __shared__ float Ms[16][68];
    __shared__ float Fs[16][68];
    __shared__ float red[16][64];
    int tx = tid & 15, ty = tid >> 4;
    float acc[4][4] = {};
    const float* Mb = Mul + (long)b * G_ * T_;
    const float* Fb = F   + (long)b * T_ * T_;
    for (int i0 = 0; i0 < ibound; i0 += 16) {
        #pragma unroll
        for (int p = 0; p < 4; p++) {
            int r = (tid >> 4) + p * 16;
            int c = tid & 15;
            Ms[c][r] = Mb[r * T_ + i0 + c];
        }
        #pragma unroll
        for (int p = 0; p < 4; p++) {
            int r = (tid >> 6) + p * 4;
            int c = tid & 63;
            Fs[r][c] = Fb[(long)(i0 + r) * T_ + c0 + c];
        }
        __syncthreads();
        #pragma unroll
        for (int ii = 0; ii < 16; ii++) {
            float4 m4 = *reinterpret_cast<const float4*>(&Ms[ii][ty * 4]);
            float m[4] = {m4.x, m4.y, m4.z, m4.w};
            float4 f4 = *reinterpret_cast<const float4*>(&Fs[ii][tx * 4]);
            float ff[4] = {f4.x, f4.y, f4.z, f4.w};
            #pragma unroll
            for (int i = 0; i < 4; i++)
                #pragma unroll
                for (int j = 0; j < 4; j++)
                    acc[i][j] += m[i] * ff[j];
        }
        __syncthreads();
    }
    float part[4] = {0.f, 0.f, 0.f, 0.f};
    #pragma unroll
    for (int gq = 0; gq < 4; gq++) {
        int g = ty * 4 + gq;
        float wg = w[g];
        #pragma unroll
        for (int c = 0; c < 4; c++) {
            float vv = acc[gq][c] + Bias[(long)b * G_ * T_ + g * T_ + c0 + tx * 4 + c];
            part[c] += wg * fmaxf(vv, 0.f);
        }
    }
    #pragma unroll
    for (int c = 0; c < 4; c++) red[ty][tx * 4 + c] = part[c];
    __syncthreads();
    #pragma unroll
    for (int s = 8; s > 0; s >>= 1) {
        if (ty < s) {
            #pragma unroll
            for (int c = 0; c < 4; c++) red[ty][tx * 4 + c] += red[ty + s][tx * 4 + c];
        }
        __syncthreads();
    }
    if (ty == 0) {
        #pragma unroll
        for (int c = 0; c < 4; c++) {
            int col = c0 + tx * 4 + c;
            d[b * T_ + col] = red[0][tx * 4 + c] - NEGC * pad[b * T_ + col];
        }
    }
}

// ---------------- softmax ----------------
__global__ void softmax_kernel(const float* __restrict__ d1, const float* __restrict__ d2,
                               float* __restrict__ g1, float* __restrict__ g2) {
    int b = blockIdx.x;
    const float* d = blockIdx.y ? d2 : d1;
    float* g = blockIdx.y ? g2 : g1;
    int t = threadIdx.x;
    float v = d[b * T_ + t];
    __shared__ float red[16];
    float m = v;
    #pragma unroll
    for (int o = 16; o; o >>= 1) m = fmaxf(m, __shfl_xor_sync(0xffffffffu, m, o));
    if ((t & 31) == 0) red[t >> 5] = m;
    __syncthreads();
    if (t < 32) {
        float x = (t < 16) ? red[t] : -3.4e38f;
        #pragma unroll
        for (int o = 8; o; o >>= 1) x = fmaxf(x, __shfl_xor_sync(0xffffffffu, x, o));
        if (t == 0) red[0] = x;
    }
    __syncthreads();
    float mx = red[0];
    __syncthreads();
    float e = expf(v - mx);
    float s = e;
    #pragma unroll
    for (int o = 16; o; o >>= 1) s += __shfl_xor_sync(0xffffffffu, s, o);
    if ((t & 31) == 0) red[t >> 5] = s;
    __syncthreads();
    if (t < 32) {
        float x = (t < 16) ? red[t] : 0.f;
        #pragma unroll
        for (int o = 8; o; o >>= 1) x += __shfl_xor_sync(0xffffffffu, x, o);
        if (t == 0) red[0] = x;
    }
    __syncthreads();
    g[b * T_ + t] = e / red[0];
}

// ---------------- final reduction ----------------
__global__ void final_kernel(const float* __restrict__ R, const float* __restrict__ Q,
                             const float* __restrict__ gv, const float* __restrict__ gq,
                             float* __restrict__ out) {
    int b = blockIdx.x;
    __shared__ float sgv[T_], sgq[T_];
    int tid = threadIdx.x;
    sgv[tid] = gv[b * T_ + tid];
    sgq[tid] = gq[b * T_ + tid];
    __syncthreads();
    int o = tid & 255;
    int h = tid >> 8;
    const float* Rb = R + (long)b * O_ * T_;
    const float* Qb = Q + (long)b * O_ * T_;
    float tr = 0.f, lg = 0.f;
    #pragma unroll 4
    for (int t = h * 256; t < h * 256 + 256; t++) {
        tr += sgv[t] * Rb[t * O_ + o];
        lg += sgq[t] * Qb[t * O_ + o];
    }
    __shared__ float str[2][256], slg[2][256];
    str[h][o] = tr;
    slg[h][o] = lg;
    __syncthreads();
    if (h == 0) out[b * O_ + o] = (str[0][o] + str[1][o]) * (slg[0][o] + slg[1][o]);
}

// ---------------- launcher ----------------
extern "C" void kernel_launch(void* const* d_in, const int* in_sizes, int n_in,
                              void* d_out, int out_size) {
    const float* x0  = (const float*)d_in[0];
    const float* x1  = (const float*)d_in[1];
    const unsigned char* qm = (const unsigned char*)d_in[2];
    const unsigned char* vm = (const unsigned char*)d_in[3];
    const float* W_R = (const float*)d_in[4];
    const float* W_Q = (const float*)d_in[5];
    const float* br  = (const float*)d_in[6];
    const float* bq  = (const float*)d_in[7];
    const float* U   = (const float*)d_in[8];
    const float* V   = (const float*)d_in[9];
    const float* W2R = (const float*)d_in[10];
    const float* W2Q = (const float*)d_in[11];
    const float* wmv = (const float*)d_in[12];
    const float* wmq = (const float*)d_in[13];
    float* out = (float*)d_out;

    float *pR, *pQ, *pF, *pWR, *pWQ, *pd1, *pd2, *pg1, *pg2, *ppq, *ppv;
    int *pl1, *pl2, *pjm, *pim;
    __half *pUk, *pVk, *pRt, *pQt;
    cudaGetSymbolAddress((void**)&pR,  g_R);
    cudaGetSymbolAddress((void**)&pQ,  g_Q);
    cudaGetSymbolAddress((void**)&pF,  g_F);
    cudaGetSymbolAddress((void**)&pWR, g_WR);
    cudaGetSymbolAddress((void**)&pWQ, g_WQ);
    cudaGetSymbolAddress((void**)&pd1, g_d1);
    cudaGetSymbolAddress((void**)&pd2, g_d2);
    cudaGetSymbolAddress((void**)&pg1, g_g1);
    cudaGetSymbolAddress((void**)&pg2, g_g2);
    cudaGetSymbolAddress((void**)&ppq, g_pq);
    cudaGetSymbolAddress((void**)&ppv, g_pv);
    cudaGetSymbolAddress((void**)&pl1, g_len1);
    cudaGetSymbolAddress((void**)&pl2, g_len2);
    cudaGetSymbolAddress((void**)&pjm, g_jmin);
    cudaGetSymbolAddress((void**)&pim, g_imax);
    cudaGetSymbolAddress((void**)&pUk, g_Uk);
    cudaGetSymbolAddress((void**)&pVk, g_Vk);
    cudaGetSymbolAddress((void**)&pRt, g_Rt);
    cudaGetSymbolAddress((void**)&pQt, g_Qt);

    static bool attr_done = false;
    if (!attr_done) {
        cudaFuncSetAttribute(f_mma_kernel, cudaFuncAttributeMaxDynamicSharedMemorySize, FS_TOTAL);
        attr_done = true;
    }

    maskconv_kernel<<<(B_ * T_ + 255) / 256, 256>>>(qm, vm, ppq, ppv);
    lens_kernel<<<B_, T_>>>(qm, vm, pl1, pl2, pjm, pim);
    convUV_kernel<<<(KF_ * T_ * O_ + 255) / 256, 256>>>(U, V, pUk, pVk);

    gemm_rq_kernel<<<dim3(T_ / 128, O_ / 64, B_), 128>>>(W_R, x0, pR, pRt, br, ppq, pl1);
    gemm_rq_kernel<<<dim3(T_ / 128, O_ / 64, B_), 128>>>(W_Q, x1, pQ, pQt, bq, ppv, pl2);

    f_mma_kernel<<<dim3(T_ / 64, T_ / 128, B_), 256, FS_TOTAL>>>(
        pUk, pVk, pRt, pQt, pF, pjm, pim);

    gemm64_kernel<<<dim3(T_ / 64, 1, B_), 256>>>(
        W2R, pR, pWR, O_, T_, G_, (long)O_ * T_);
    gemm64_kernel<<<dim3(T_ / 64, 1, B_), 256>>>(
        W2Q, pQ, pWQ, O_, T_, G_, (long)O_ * T_);

    md_kernel<<<dim3(T_ / 64, B_), 256>>>(pWR, pWQ, pF, wmv, ppq, pd1, pl1, pl2);
    md_kernel<<<dim3(T_ / 64, B_), 256>>>(pWQ, pWR, pF, wmq, ppv, pd2, pl2, pl1);

    softmax_kernel<<<dim3(B_, 2), T_>>>(pd1, pd2, pg1, pg2);

    final_kernel<<<B_, T_>>>(pR, pQ, pg1, pg2, out);
}

// round 10
// speedup vs baseline: 1.5512x; 1.0045x over previous
#include <cuda_runtime.h>
#include <cuda_fp16.h>
#include <cstdint>

#define NEGC 1e9f

#define B_  32
#define T_  512
#define D_  256
#define O_  256
#define KF_ 8
#define G_  64

// ---------------- scratch ----------------
__device__ float g_R [B_ * O_ * T_];
__device__ float g_Q [B_ * O_ * T_];
__device__ float g_F [B_ * T_ * T_];
__device__ float g_WR[B_ * G_ * T_];
__device__ float g_WQ[B_ * G_ * T_];
__device__ float g_d1[B_ * T_];
__device__ float g_d2[B_ * T_];
__device__ float g_g1[B_ * T_];
__device__ float g_g2[B_ * T_];
__device__ float g_pq[B_ * T_];
__device__ float g_pv[B_ * T_];
__device__ int   g_len1[B_];
__device__ int   g_len2[B_];
__device__ int   g_jmin[B_];
__device__ int   g_imax[B_];

__device__ __half g_Uk[KF_ * T_ * O_];
__device__ __half g_Vk[KF_ * T_ * O_];
__device__ __half g_Rt[B_ * T_ * O_];
__device__ __half g_Qt[B_ * T_ * O_];

// =================== helpers ===================
__device__ __forceinline__ uint32_t smem_to_u32(const void* p) {
    uint32_t a;
    asm("{ .reg .u64 t; cvta.to.shared.u64 t, %1; cvt.u32.u64 %0, t; }" : "=r"(a) : "l"(p));
    return a;
}
__device__ __forceinline__ void ldsm4(uint32_t* r, uint32_t addr) {
    asm volatile("ldmatrix.sync.aligned.m8n8.x4.shared.b16 {%0,%1,%2,%3}, [%4];"
        : "=r"(r[0]), "=r"(r[1]), "=r"(r[2]), "=r"(r[3]) : "r"(addr));
}
__device__ __forceinline__ void mma16816h(float* d, const uint32_t* a,
                                          uint32_t b0, uint32_t b1) {
    asm volatile("mma.sync.aligned.m16n8k16.row.col.f32.f16.f16.f32 "
        "{%0,%1,%2,%3}, {%4,%5,%6,%7}, {%8,%9}, {%0,%1,%2,%3};"
        : "+f"(d[0]), "+f"(d[1]), "+f"(d[2]), "+f"(d[3])
        : "r"(a[0]), "r"(a[1]), "r"(a[2]), "r"(a[3]), "r"(b0), "r"(b1));
}
__device__ __forceinline__ void cpasync16(uint32_t dst, const void* src) {
    asm volatile("cp.async.cg.shared.global [%0], [%1], 16;" :: "r"(dst), "l"(src));
}
#define CP_COMMIT() asm volatile("cp.async.commit_group;" ::: "memory")
#define CP_WAIT(n)  asm volatile("cp.async.wait_group %0;" :: "n"(n) : "memory")

__device__ __forceinline__ uint32_t paddr(uint32_t row, uint32_t cb) {
    uint32_t pr = row >> 1;
    return pr * 128 + ((((row & 1) << 6) + cb) ^ ((pr & 7) << 4));
}

__device__ __forceinline__ void decode_mask(const unsigned char* q, const unsigned char* v,
                                            int i, bool& qv, bool& vv) {
    unsigned char b1 = q[1], b3 = q[3];
    int type = (b1 == 1) ? 0 : (b1 == 0x3F) ? 3 : (b3 == 0x3F) ? 2 : 1;
    switch (type) {
        case 0: qv = q[i] != 0;                            vv = v[i] != 0; break;
        case 1: qv = ((const int*)q)[i] != 0;              vv = ((const int*)v)[i] != 0; break;
        case 2: qv = ((const float*)q)[i] != 0.f;          vv = ((const float*)v)[i] != 0.f; break;
        default: qv = ((const unsigned short*)q)[i] != 0;  vv = ((const unsigned short*)v)[i] != 0; break;
    }
}

// ---------------- mask decode ----------------
__global__ void maskconv_kernel(const unsigned char* __restrict__ q,
                                const unsigned char* __restrict__ v,
                                float* __restrict__ pq, float* __restrict__ pv) {
    int i = blockIdx.x * blockDim.x + threadIdx.x;
    if (i >= B_ * T_) return;
    bool qv, vv;
    decode_mask(q, v, i, qv, vv);
    pq[i] = qv ? 0.f : 1.f;
    pv[i] = vv ? 0.f : 1.f;
}

// ---------------- per-batch valid lengths ----------------
__global__ void lens_kernel(const unsigned char* __restrict__ q,
                            const unsigned char* __restrict__ v,
                            int* __restrict__ len1, int* __restrict__ len2,
                            int* __restrict__ jmin, int* __restrict__ imax) {
    __shared__ int s1, s2;
    int b = blockIdx.x, t = threadIdx.x;
    if (t == 0) { s1 = 0; s2 = 0; }
    __syncthreads();
    bool qv, vv;
    decode_mask(q, v, b * T_ + t, qv, vv);
    unsigned m1 = __ballot_sync(0xffffffffu, qv);
    unsigned m2 = __ballot_sync(0xffffffffu, vv);
    if ((t & 31) == 0) { atomicAdd(&s1, __popc(m1)); atomicAdd(&s2, __popc(m2)); }
    __syncthreads();
    if (t == 0) {
        len1[b] = s1; len2[b] = s2;
        jmin[b] = s1 < s2 ? s1 : s2;
        imax[b] = s1 > s2 ? s1 : s2;
    }
}

// ---------------- U/V de-interleave + fp16 convert ----------------
__global__ void convUV_kernel(const float* __restrict__ U, const float* __restrict__ V,
                              __half* __restrict__ Uo, __half* __restrict__ Vo) {
    int idx = blockIdx.x * blockDim.x + threadIdx.x;
    if (idx >= KF_ * T_ * O_) return;
    int k = idx >> 17;
    int m = idx & (T_ * O_ - 1);
    Uo[idx] = __float2half(U[m * KF_ + k]);
    Vo[idx] = __float2half(V[m * KF_ + k]);
}

// ---------------- R/Q GEMM: A-resident + cp.async-pipelined B ----------------
// SMEM: As [256 k][68] floats at 0 (69632B); Bs 2 stages x [16][132] floats (16896B).
#define GQ_AS_FLOATS (256 * 68)
#define GQ_BS_OFF    69632
#define GQ_BS_STRIDE 8448
#define GQ_TOTAL     86528

__global__ __launch_bounds__(128) void gemm_rq_kernel(
    const float* __restrict__ A, const float* __restrict__ Bm,
    float* __restrict__ C, __half* __restrict__ Ct,
    const float* __restrict__ bias,
    const float* __restrict__ pad, const int* __restrict__ lenp) {
    extern __shared__ float smf[];
    int b = blockIdx.z;
    int n0 = blockIdx.x * 128;
    int m0 = blockIdx.y * 64;
    int tid = threadIdx.x;
    if (n0 >= lenp[b]) {
        float4 z = make_float4(0.f, 0.f, 0.f, 0.f);
        #pragma unroll
        for (int e = 0; e < 16; e++) {
            int idx = tid + e * 128;
            int m = idx >> 5, nq = idx & 31;
            *reinterpret_cast<float4*>(&C[((long)b * O_ + m0 + m) * T_ + n0 + nq * 4]) = z;
        }
        uint4 zh = make_uint4(0, 0, 0, 0);
        #pragma unroll
        for (int e = 0; e < 8; e++) {
            int idx = tid + e * 128;
            int n = idx >> 3, mq = idx & 7;
            *reinterpret_cast<uint4*>(&Ct[((long)b * T_ + n0 + n) * O_ + m0 + mq * 8]) = zh;
        }
        return;
    }
    const float* Bb = Bm + (long)b * (D_ * T_);
    float* As = smf;                       // [k][m] layout, 68 stride
    uint32_t bs_base = smem_to_u32(smf) + GQ_BS_OFF;
    int tx = tid & 15, ty = tid >> 4;

    // preload full A tile: rows m0..m0+63, K=256; store transposed As[k][m]
    #pragma unroll
    for (int e = 0; e < 32; e++) {
        int idx = tid + e * 128;           // 0..4095 float4 units
        int m = idx >> 6;                  // 0..63
        int kq = idx & 63;                 // 0..63 (float4 along K)
        float4 a = *reinterpret_cast<const float4*>(&A[(m0 + m) * D_ + kq * 4]);
        As[(kq * 4 + 0) * 68 + m] = a.x;
        As[(kq * 4 + 1) * 68 + m] = a.y;
        As[(kq * 4 + 2) * 68 + m] = a.z;
        As[(kq * 4 + 3) * 68 + m] = a.w;
    }

    // prefetch B stage 0
    auto load_b = [&](int k0, int st) {
        #pragma unroll
        for (int e = 0; e < 4; e++) {
            int idx = tid + e * 128;       // 0..511 float4 units
            int r = idx >> 5, cq = idx & 31;
            cpasync16(bs_base + st * GQ_BS_STRIDE + (r * 132 + cq * 4) * 4,
                      &Bb[(long)(r) * T_ + n0 + cq * 4 + (long)k0 * T_]);
        }
    };
    load_b(0, 0);
    CP_COMMIT();

    float acc[8][8] = {};
    for (int it = 0; it < 16; it++) {
        int st = it & 1;
        if (it + 1 < 16) {
            load_b((it + 1) * 16, st ^ 1);
            CP_COMMIT();
            CP_WAIT(1);
        } else {
            CP_WAIT(0);
        }
        __syncthreads();
        const float* Bss = smf + (GQ_BS_OFF / 4) + st * (GQ_BS_STRIDE / 4);
        int k0 = it * 16;
        #pragma unroll
        for (int kk = 0; kk < 16; kk++) {
            const float* arow = &As[(k0 + kk) * 68];
            float4 a0 = *reinterpret_cast<const float4*>(&arow[ty * 8]);
            float4 a1 = *reinterpret_cast<const float4*>(&arow[ty * 8 + 4]);
            float4 b0 = *reinterpret_cast<const float4*>(&Bss[kk * 132 + tx * 8]);
            float4 b1 = *reinterpret_cast<const float4*>(&Bss[kk * 132 + tx * 8 + 4]);
            float av[8] = {a0.x, a0.y, a0.z, a0.w, a1.x, a1.y, a1.z, a1.w};
            float bv[8] = {b0.x, b0.y, b0.z, b0.w, b1.x, b1.y, b1.z, b1.w};
            #pragma unroll
            for (int i = 0; i < 8; i++)
                #pragma unroll
                for (int j = 0; j < 8; j++)
                    acc[i][j] += av[i] * bv[j];
        }
        __syncthreads();
    }

    #pragma unroll
    for (int i = 0; i < 8; i++) {
        int m = m0 + ty * 8 + i;
        float bi = bias[m];
        #pragma unroll
        for (int j = 0; j < 8; j++) {
            int n = n0 + tx * 8 + j;
            acc[i][j] = fmaxf(acc[i][j] - NEGC * pad[b * T_ + n] + bi, 0.f);
        }
        float* dst = &C[((long)b * O_ + m) * T_ + n0 + tx * 8];
        *reinterpret_cast<float4*>(dst) = make_float4(acc[i][0], acc[i][1], acc[i][2], acc[i][3]);
        *reinterpret_cast<float4*>(dst + 4) = make_float4(acc[i][4], acc[i][5], acc[i][6], acc[i][7]);
    }
    #pragma unroll
    for (int j = 0; j < 8; j++) {
        int n = n0 + tx * 8 + j;
        __half h[8];
        #pragma unroll
        for (int i = 0; i < 8; i++) h[i] = __float2half(acc[i][j]);
        *reinterpret_cast<uint4*>(&Ct[((long)b * T_ + n) * O_ + m0 + ty * 8]) =
            *reinterpret_cast<const uint4*>(h);
    }
}

// ---------------- generic 64x64 tile GEMM (W2 only) ----------------
__global__ void gemm64_kernel(const float* __restrict__ A, const float* __restrict__ Bm,
                              float* __restrict__ C, int K, int N, int Mtot,
                              long strideB) {
    int b  = blockIdx.z;
    int n0 = blockIdx.x * 64;
    int m0 = blockIdx.y * 64;
    const float* Bb = Bm + (long)b * strideB;
    __shared__ float As[16][68];
    __shared__ float Bs[16][68];
    int tid = threadIdx.x;
    int tx = tid & 15, ty = tid >> 4;
    float acc[4][4] = {};
    for (int k0 = 0; k0 < K; k0 += 16) {
        #pragma unroll
        for (int p = 0; p < 4; p++) {
            int r = (tid >> 4) + p * 16;
            int c = tid & 15;
            As[c][r] = A[(m0 + r) * K + k0 + c];
        }
        #pragma unroll
        for (int p = 0; p < 4; p++) {
            int r = (tid >> 6) + p * 4;
            int c = tid & 63;
            Bs[r][c] = Bb[(long)(k0 + r) * N + n0 + c];
        }
        __syncthreads();
        #pragma unroll
        for (int kk = 0; kk < 16; kk++) {
            float4 a4 = *reinterpret_cast<const float4*>(&As[kk][ty * 4]);
            float a[4] = {a4.x, a4.y, a4.z, a4.w};
            float4 bb = *reinterpret_cast<const float4*>(&Bs[kk][tx * 4]);
            float bv[4] = {bb.x, bb.y, bb.z, bb.w};
            #pragma unroll
            for (int i = 0; i < 4; i++)
                #pragma unroll
                for (int j = 0; j < 4; j++)
                    acc[i][j] += a[i] * bv[j];
        }
        __syncthreads();
    }
    #pragma unroll
    for (int i = 0; i < 4; i++) {
        int m = m0 + ty * 4 + i;
        #pragma unroll
        for (int j = 0; j < 4; j++) {
            int n = n0 + tx * 4 + j;
            C[(long)b * Mtot * N + (long)m * N + n] = acc[i][j];
        }
    }
}

// ======================= fp16 HMMA F kernel =======================
#define FS_B 32768
#define FS_TOTAL 98304

__global__ __launch_bounds__(256, 2) void f_mma_kernel(
    const __half* __restrict__ Uk, const __half* __restrict__ Vk,
    const __half* __restrict__ Rt, const __half* __restrict__ Qt,
    float* __restrict__ F, const int* __restrict__ jmin, const int* __restrict__ imax) {
    extern __shared__ char sm[];
    uint32_t sb = smem_to_u32(sm);
    int tid = threadIdx.x, lane = tid & 31, w = tid >> 5;
    int wi = w >> 1, wj = w & 1;
    int b = blockIdx.z, i0 = blockIdx.y * 128, j0 = blockIdx.x * 64;
    int l16 = lane & 15, lh = lane >> 4;

    if (i0 >= imax[b]) return;

    if (j0 >= jmin[b]) {
        int row = tid >> 1, half = tid & 1;
        float4 z = make_float4(0.f, 0.f, 0.f, 0.f);
        float* dst = F + ((long)b * T_ + i0 + row) * T_ + j0 + half * 32;
        #pragma unroll
        for (int e = 0; e < 8; e++) reinterpret_cast<float4*>(dst)[e] = z;
        return;
    }

    const __half* apt[2] = {Uk, Vk};
    const __half* bpt[2] = {Rt, Qt};

    #pragma unroll
    for (int arr = 0; arr < 2; arr++) {
        const __half* src = bpt[arr] + ((long)b * T_ + j0) * O_;
        #pragma unroll
        for (int e = 0; e < 8; e++) {
            int idx = tid + e * 256;
            int ch = idx >> 8;
            int row = (idx & 255) >> 2;
            int cb = (idx & 3) * 16;
            const void* g = src + (long)row * O_ + ch * 32 + cb / 2;
            cpasync16(sb + FS_B + arr * 32768 + ch * 4096 + paddr(row, cb), g);
        }
    }
    CP_COMMIT();

    auto load_a = [&](int cu, int st) {
        int k = cu >> 3, ch = cu & 7;
        #pragma unroll
        for (int arr = 0; arr < 2; arr++) {
            const __half* src = apt[arr] + ((long)k * T_ + i0) * O_ + ch * 32;
            #pragma unroll
            for (int e = 0; e < 2; e++) {
                int idx = tid + e * 256;
                int row = idx >> 2;
                int cb = (idx & 3) * 16;
                const void* g = src + (long)row * O_ + cb / 2;
                cpasync16(sb + st * 16384 + arr * 8192 + paddr(row, cb), g);
            }
        }
    };

    load_a(0, 0);
    CP_COMMIT();

    float f[32], d1[32], d2[32];
    #pragma unroll
    for (int i = 0; i < 32; i++) { f[i] = 0.f; d1[i] = 0.f; d2[i] = 0.f; }

    for (int cu = 0; cu < 64; cu++) {
        int st = cu & 1, ch = cu & 7;
        if (cu + 1 < 64) {
            load_a(cu + 1, (cu + 1) & 1);
            CP_COMMIT();
            CP_WAIT(1);
        } else {
            CP_WAIT(0);
        }
        __syncthreads();

        uint32_t abase = sb + st * 16384;
        #pragma unroll
        for (int os = 0; os < 2; os++) {
            uint32_t colb = (uint32_t)(os * 32 + lh * 16);
            uint32_t arow = (uint32_t)(wi * 32 + l16);
            uint32_t brow = (uint32_t)(wj * 32 + l16);
            {
                uint32_t a0[4], a1[4], b0r[4], b1r[4];
                ldsm4(a0, abase + 0 * 8192 + paddr(arow, colb));
                ldsm4(a1, abase + 0 * 8192 + paddr(arow + 16, colb));
                uint32_t bb0 = sb + FS_B + 0 * 32768 + ch * 4096;
                ldsm4(b0r, bb0 + paddr(brow, colb));
                ldsm4(b1r, bb0 + paddr(brow + 16, colb));
                #pragma unroll
                for (int mt = 0; mt < 2; mt++) {
                    const uint32_t* a = mt ? a1 : a0;
                    #pragma unroll
                    for (int nt = 0; nt < 4; nt++) {
                        const uint32_t* bb = (nt >> 1) ? b1r : b0r;
                        int s = nt & 1;
                        mma16816h(d1 + (mt * 4 + nt) * 4, a, bb[s], bb[s + 2]);
                    }
                }
            }
            {
                uint32_t a0[4], a1[4], b0r[4], b1r[4];
                ldsm4(a0, abase + 1 * 8192 + paddr(arow, colb));
                ldsm4(a1, abase + 1 * 8192 + paddr(arow + 16, colb));
                uint32_t bb1 = sb + FS_B + 1 * 32768 + ch * 4096;
                ldsm4(b0r, bb1 + paddr(brow, colb));
                ldsm4(b1r, bb1 + paddr(brow + 16, colb));
                #pragma unroll
                for (int mt = 0; mt < 2; mt++) {
                    const uint32_t* a = mt ? a1 : a0;
                    #pragma unroll
                    for (int nt = 0; nt < 4; nt++) {
                        const uint32_t* bb = (nt >> 1) ? b1r : b0r;
                        int s = nt & 1;
                        mma16816h(d2 + (mt * 4 + nt) * 4, a, bb[s], bb[s + 2]);
                    }
                }
            }
        }
        if (ch == 7) {
            #pragma unroll
            for (int i = 0; i < 32; i++) {
                f[i] += d1[i] * d2[i];
                d1[i] = 0.f; d2[i] = 0.f;
            }
        }
        __syncthreads();
    }

    int r4 = lane >> 2, c2 = (lane & 3) * 2;
    #pragma unroll
    for (int mt = 0; mt < 2; mt++) {
        #pragma unroll
        for (int nt = 0; nt < 4; nt++) {
            float* d = f + (mt * 4 + nt) * 4;
            long row = i0 + wi * 32 + mt * 16 + r4;
            long col = j0 + wj * 32 + nt * 8 + c2;
            float* dst = F + ((long)b * T_ + row) * T_ + col;
            dst[0] = d[0]; dst[1] = d[1];
            dst[8 * T_] = d[2]; dst[8 * T_ + 1] = d[3];
        }
    }
}

// ---------------- fused M + d kernel ----------------
__global__ void md_kernel(const float* __restrict__ Bias, const float* __restrict__ Mul,
                          const float* __restrict__ F, const float* __restrict__ w,
                          const float* __restrict__ pad, float* __restrict__ d,
                          const int* __restrict__ lencol, const int* __restrict__ lenmul) {
    int b  = blockIdx.y;
    int c0 = blockIdx.x * 64;
    int tid = threadIdx.x;
    if (c0 >= lencol[b]) {
        if (tid < 64) d[b * T_ + c0 + tid] = -NEGC;
        return;
    }
    int ibound = (lenmul[b] + 15) & ~15;
    __shared__ float Ms[16][68];
    __shared__ float Fs[16][68];
    __shared__ float red[16][64];
    int tx = tid & 15, ty = tid >> 4;
    float acc[4][4] = {};
    const float* Mb = Mul + (long)b * G_ * T_;
    const float* Fb = F   + (long)b * T_ * T_;
    for (int i0 = 0; i0 < ibound; i0 += 16) {
        #pragma unroll
        for (int p = 0; p < 4; p++) {
            int r = (tid >> 4) + p * 16;
            int c = tid & 15;
            Ms[c][r] = Mb[r * T_ + i0 + c];
        }
        #pragma unroll
        for (int p = 0; p < 4; p++) {
            int r = (tid >> 6) + p * 4;
            int c = tid & 63;
            Fs[r][c] = Fb[(long)(i0 + r) * T_ + c0 + c];
        }
        __syncthreads();
        #pragma unroll
        for (int ii = 0; ii < 16; ii++) {
            float4 m4 = *reinterpret_cast<const float4*>(&Ms[ii][ty * 4]);
            float m[4] = {m4.x, m4.y, m4.z, m4.w};
            float4 f4 = *reinterpret_cast<const float4*>(&Fs[ii][tx * 4]);
            float ff[4] = {f4.x, f4.y, f4.z, f4.w};
            #pragma unroll
            for (int i = 0; i < 4; i++)
                #pragma unroll
                for (int j = 0; j < 4; j++)
                    acc[i][j] += m[i] * ff[j];
        }
        __syncthreads();
    }
    float part[4] = {0.f, 0.f, 0.f, 0.f};
    #pragma unroll
    for (int gq = 0; gq < 4; gq++) {
        int g = ty * 4 + gq;
        float wg = w[g];
        #pragma unroll
        for (int c = 0; c < 4; c++) {
            float vv = acc[gq][c] + Bias[(long)b * G_ * T_ + g * T_ + c0 + tx * 4 + c];
            part[c] += wg * fmaxf(vv, 0.f);
        }
    }
    #pragma unroll
    for (int c = 0; c < 4; c++) red[ty][tx * 4 + c] = part[c];
    __syncthreads();
    #pragma unroll
    for (int s = 8; s > 0; s >>= 1) {
        if (ty < s) {
            #pragma unroll
            for (int c = 0; c < 4; c++) red[ty][tx * 4 + c] += red[ty + s][tx * 4 + c];
        }
        __syncthreads();
    }
    if (ty == 0) {
        #pragma unroll
        for (int c = 0; c < 4; c++) {
            int col = c0 + tx * 4 + c;
            d[b * T_ + col] = red[0][tx * 4 + c] - NEGC * pad[b * T_ + col];
        }
    }
}

// ---------------- softmax ----------------
__global__ void softmax_kernel(const float* __restrict__ d1, const float* __restrict__ d2,
                               float* __restrict__ g1, float* __restrict__ g2) {
    int b = blockIdx.x;
    const float* d = blockIdx.y ? d2 : d1;
    float* g = blockIdx.y ? g2 : g1;
    int t = threadIdx.x;
    float v = d[b * T_ + t];
    __shared__ float red[16];
    float m = v;
    #pragma unroll
    for (int o = 16; o; o >>= 1) m = fmaxf(m, __shfl_xor_sync(0xffffffffu, m, o));
    if ((t & 31) == 0) red[t >> 5] = m;
    __syncthreads();
    if (t < 32) {
        float x = (t < 16) ? red[t] : -3.4e38f;
        #pragma unroll
        for (int o = 8; o; o >>= 1) x = fmaxf(x, __shfl_xor_sync(0xffffffffu, x, o));
        if (t == 0) red[0] = x;
    }
    __syncthreads();
    float mx = red[0];
    __syncthreads();
    float e = expf(v - mx);
    float s = e;
    #pragma unroll
    for (int o = 16; o; o >>= 1) s += __shfl_xor_sync(0xffffffffu, s, o);
    if ((t & 31) == 0) red[t >> 5] = s;
    __syncthreads();
    if (t < 32) {
        float x = (t < 16) ? red[t] : 0.f;
        #pragma unroll
        for (int o = 8; o; o >>= 1) x += __shfl_xor_sync(0xffffffffu, x, o);
        if (t == 0) red[0] = x;
    }
    __syncthreads();
    g[b * T_ + t] = e / red[0];
}

// ---------------- final reduction ----------------
__global__ void final_kernel(const float* __restrict__ R, const float* __restrict__ Q,
                             const float* __restrict__ gv, const float* __restrict__ gq,
                             float* __restrict__ out) {
    int b = blockIdx.x;
    __shared__ float sgv[T_], sgq[T_];
    int tid = threadIdx.x;
    sgv[tid] = gv[b * T_ + tid];
    sgq[tid] = gq[b * T_ + tid];
    __syncthreads();
    int o = tid & 255;
    int h = tid >> 8;
    const float* Rb = R + (long)b * O_ * T_;
    const float* Qb = Q + (long)b * O_ * T_;
    float tr = 0.f, lg = 0.f;
    #pragma unroll 4
    for (int t = h * 256; t < h * 256 + 256; t++) {
        tr += sgv[t] * Rb[t * O_ + o];
        lg += sgq[t] * Qb[t * O_ + o];
    }
    __shared__ float str[2][256], slg[2][256];
    str[h][o] = tr;
    slg[h][o] = lg;
    __syncthreads();
    if (h == 0) out[b * O_ + o] = (str[0][o] + str[1][o]) * (slg[0][o] + slg[1][o]);
}

// ---------------- launcher ----------------
extern "C" void kernel_launch(void* const* d_in, const int* in_sizes, int n_in,
                              void* d_out, int out_size) {
    const float* x0  = (const float*)d_in[0];
    const float* x1  = (const float*)d_in[1];
    const unsigned char* qm = (const unsigned char*)d_in[2];
    const unsigned char* vm = (const unsigned char*)d_in[3];
    const float* W_R = (const float*)d_in[4];
    const float* W_Q = (const float*)d_in[5];
    const float* br  = (const float*)d_in[6];
    const float* bq  = (const float*)d_in[7];
    const float* U   = (const float*)d_in[8];
    const float* V   = (const float*)d_in[9];
    const float* W2R = (const float*)d_in[10];
    const float* W2Q = (const float*)d_in[11];
    const float* wmv = (const float*)d_in[12];
    const float* wmq = (const float*)d_in[13];
    float* out = (float*)d_out;

    float *pR, *pQ, *pF, *pWR, *pWQ, *pd1, *pd2, *pg1, *pg2, *ppq, *ppv;
    int *pl1, *pl2, *pjm, *pim;
    __half *pUk, *pVk, *pRt, *pQt;
    cudaGetSymbolAddress((void**)&pR,  g_R);
    cudaGetSymbolAddress((void**)&pQ,  g_Q);
    cudaGetSymbolAddress((void**)&pF,  g_F);
    cudaGetSymbolAddress((void**)&pWR, g_WR);
    cudaGetSymbolAddress((void**)&pWQ, g_WQ);
    cudaGetSymbolAddress((void**)&pd1, g_d1);
    cudaGetSymbolAddress((void**)&pd2, g_d2);
    cudaGetSymbolAddress((void**)&pg1, g_g1);
    cudaGetSymbolAddress((void**)&pg2, g_g2);
    cudaGetSymbolAddress((void**)&ppq, g_pq);
    cudaGetSymbolAddress((void**)&ppv, g_pv);
    cudaGetSymbolAddress((void**)&pl1, g_len1);
    cudaGetSymbolAddress((void**)&pl2, g_len2);
    cudaGetSymbolAddress((void**)&pjm, g_jmin);
    cudaGetSymbolAddress((void**)&pim, g_imax);
    cudaGetSymbolAddress((void**)&pUk, g_Uk);
    cudaGetSymbolAddress((void**)&pVk, g_Vk);
    cudaGetSymbolAddress((void**)&pRt, g_Rt);
    cudaGetSymbolAddress((void**)&pQt, g_Qt);

    static bool attr_done = false;
    if (!attr_done) {
        cudaFuncSetAttribute(f_mma_kernel, cudaFuncAttributeMaxDynamicSharedMemorySize, FS_TOTAL);
        cudaFuncSetAttribute(gemm_rq_kernel, cudaFuncAttributeMaxDynamicSharedMemorySize, GQ_TOTAL);
        attr_done = true;
    }

    maskconv_kernel<<<(B_ * T_ + 255) / 256, 256>>>(qm, vm, ppq, ppv);
    lens_kernel<<<B_, T_>>>(qm, vm, pl1, pl2, pjm, pim);
    convUV_kernel<<<(KF_ * T_ * O_ + 255) / 256, 256>>>(U, V, pUk, pVk);

    gemm_rq_kernel<<<dim3(T_ / 128, O_ / 64, B_), 128, GQ_TOTAL>>>(
        W_R, x0, pR, pRt, br, ppq, pl1);
    gemm_rq_kernel<<<dim3(T_ / 128, O_ / 64, B_), 128, GQ_TOTAL>>>(
        W_Q, x1, pQ, pQt, bq, ppv, pl2);

    f_mma_kernel<<<dim3(T_ / 64, T_ / 128, B_), 256, FS_TOTAL>>>(
        pUk, pVk, pRt, pQt, pF, pjm, pim);

    gemm64_kernel<<<dim3(T_ / 64, 1, B_), 256>>>(
        W2R, pR, pWR, O_, T_, G_, (long)O_ * T_);
    gemm64_kernel<<<dim3(T_ / 64, 1, B_), 256>>>(
        W2Q, pQ, pWQ, O_, T_, G_, (long)O_ * T_);

    md_kernel<<<dim3(T_ / 64, B_), 256>>>(pWR, pWQ, pF, wmv, ppq, pd1, pl1, pl2);
    md_kernel<<<dim3(T_ / 64, B_), 256>>>(pWQ, pWR, pF, wmq, ppv, pd2, pl2, pl1);

    softmax_kernel<<<dim3(B_, 2), T_>>>(pd1, pd2, pg1, pg2);

    final_kernel<<<B_, T_>>>(pR, pQ, pg1, pg2, out);
}

// round 11
// speedup vs baseline: 1.7646x; 1.1375x over previous
#include <cuda_runtime.h>
#include <cuda_fp16.h>
#include <cstdint>

#define NEGC 1e9f

#define B_  32
#define T_  512
#define D_  256
#define O_  256
#define KF_ 8
#define G_  64

// ---------------- scratch ----------------
__device__ float g_R [B_ * O_ * T_];
__device__ float g_Q [B_ * O_ * T_];
__device__ float g_F [B_ * T_ * T_];
__device__ float g_WR[B_ * G_ * T_];
__device__ float g_WQ[B_ * G_ * T_];
__device__ float g_d1[B_ * T_];
__device__ float g_d2[B_ * T_];
__device__ float g_g1[B_ * T_];
__device__ float g_g2[B_ * T_];
__device__ float g_pq[B_ * T_];
__device__ float g_pv[B_ * T_];
__device__ int   g_len1[B_];
__device__ int   g_len2[B_];
__device__ int   g_jmin[B_];
__device__ int   g_imax[B_];

__device__ __half g_Uk[KF_ * T_ * O_];
__device__ __half g_Vk[KF_ * T_ * O_];
__device__ __half g_Rt[B_ * T_ * O_];
__device__ __half g_Qt[B_ * T_ * O_];

// =================== helpers ===================
__device__ __forceinline__ uint32_t smem_to_u32(const void* p) {
    uint32_t a;
    asm("{ .reg .u64 t; cvta.to.shared.u64 t, %1; cvt.u32.u64 %0, t; }" : "=r"(a) : "l"(p));
    return a;
}
__device__ __forceinline__ void ldsm4(uint32_t* r, uint32_t addr) {
    asm volatile("ldmatrix.sync.aligned.m8n8.x4.shared.b16 {%0,%1,%2,%3}, [%4];"
        : "=r"(r[0]), "=r"(r[1]), "=r"(r[2]), "=r"(r[3]) : "r"(addr));
}
__device__ __forceinline__ void mma16816h(float* d, const uint32_t* a,
                                          uint32_t b0, uint32_t b1) {
    asm volatile("mma.sync.aligned.m16n8k16.row.col.f32.f16.f16.f32 "
        "{%0,%1,%2,%3}, {%4,%5,%6,%7}, {%8,%9}, {%0,%1,%2,%3};"
        : "+f"(d[0]), "+f"(d[1]), "+f"(d[2]), "+f"(d[3])
        : "r"(a[0]), "r"(a[1]), "r"(a[2]), "r"(a[3]), "r"(b0), "r"(b1));
}
__device__ __forceinline__ void cpasync16(uint32_t dst, const void* src) {
    asm volatile("cp.async.cg.shared.global [%0], [%1], 16;" :: "r"(dst), "l"(src));
}
#define CP_COMMIT() asm volatile("cp.async.commit_group;" ::: "memory")
#define CP_WAIT(n)  asm volatile("cp.async.wait_group %0;" :: "n"(n) : "memory")

__device__ __forceinline__ uint32_t paddr(uint32_t row, uint32_t cb) {
    uint32_t pr = row >> 1;
    return pr * 128 + ((((row & 1) << 6) + cb) ^ ((pr & 7) << 4));
}

__device__ __forceinline__ void decode_mask(const unsigned char* q, const unsigned char* v,
                                            int i, bool& qv, bool& vv) {
    unsigned char b1 = q[1], b3 = q[3];
    int type = (b1 == 1) ? 0 : (b1 == 0x3F) ? 3 : (b3 == 0x3F) ? 2 : 1;
    switch (type) {
        case 0: qv = q[i] != 0;                            vv = v[i] != 0; break;
        case 1: qv = ((const int*)q)[i] != 0;              vv = ((const int*)v)[i] != 0; break;
        case 2: qv = ((const float*)q)[i] != 0.f;          vv = ((const float*)v)[i] != 0.f; break;
        default: qv = ((const unsigned short*)q)[i] != 0;  vv = ((const unsigned short*)v)[i] != 0; break;
    }
}

// ---------------- mask decode ----------------
__global__ void maskconv_kernel(const unsigned char* __restrict__ q,
                                const unsigned char* __restrict__ v,
                                float* __restrict__ pq, float* __restrict__ pv) {
    int i = blockIdx.x * blockDim.x + threadIdx.x;
    if (i >= B_ * T_) return;
    bool qv, vv;
    decode_mask(q, v, i, qv, vv);
    pq[i] = qv ? 0.f : 1.f;
    pv[i] = vv ? 0.f : 1.f;
}

// ---------------- per-batch valid lengths ----------------
__global__ void lens_kernel(const unsigned char* __restrict__ q,
                            const unsigned char* __restrict__ v,
                            int* __restrict__ len1, int* __restrict__ len2,
                            int* __restrict__ jmin, int* __restrict__ imax) {
    __shared__ int s1, s2;
    int b = blockIdx.x, t = threadIdx.x;
    if (t == 0) { s1 = 0; s2 = 0; }
    __syncthreads();
    bool qv, vv;
    decode_mask(q, v, b * T_ + t, qv, vv);
    unsigned m1 = __ballot_sync(0xffffffffu, qv);
    unsigned m2 = __ballot_sync(0xffffffffu, vv);
    if ((t & 31) == 0) { atomicAdd(&s1, __popc(m1)); atomicAdd(&s2, __popc(m2)); }
    __syncthreads();
    if (t == 0) {
        len1[b] = s1; len2[b] = s2;
        jmin[b] = s1 < s2 ? s1 : s2;
        imax[b] = s1 > s2 ? s1 : s2;
    }
}

// ---------------- U/V de-interleave + fp16 convert ----------------
__global__ void convUV_kernel(const float* __restrict__ U, const float* __restrict__ V,
                              __half* __restrict__ Uo, __half* __restrict__ Vo) {
    int idx = blockIdx.x * blockDim.x + threadIdx.x;
    if (idx >= KF_ * T_ * O_) return;
    int k = idx >> 17;
    int m = idx & (T_ * O_ - 1);
    Uo[idx] = __float2half(U[m * KF_ + k]);
    Vo[idx] = __float2half(V[m * KF_ + k]);
}

// ---------------- R/Q GEMM: 64x128 tile, double-buffered (cp.async B + reg-staged A) ----------------
__global__ __launch_bounds__(128) void gemm_rq_kernel(
    const float* __restrict__ A, const float* __restrict__ Bm,
    float* __restrict__ C, __half* __restrict__ Ct,
    const float* __restrict__ bias,
    const float* __restrict__ pad, const int* __restrict__ lenp) {
    int b = blockIdx.z;
    int n0 = blockIdx.x * 128;
    int m0 = blockIdx.y * 64;
    int tid = threadIdx.x;
    if (n0 >= lenp[b]) {
        float4 z = make_float4(0.f, 0.f, 0.f, 0.f);
        #pragma unroll
        for (int e = 0; e < 16; e++) {
            int idx = tid + e * 128;
            int m = idx >> 5, nq = idx & 31;
            *reinterpret_cast<float4*>(&C[((long)b * O_ + m0 + m) * T_ + n0 + nq * 4]) = z;
        }
        uint4 zh = make_uint4(0, 0, 0, 0);
        #pragma unroll
        for (int e = 0; e < 8; e++) {
            int idx = tid + e * 128;
            int n = idx >> 3, mq = idx & 7;
            *reinterpret_cast<uint4*>(&Ct[((long)b * T_ + n0 + n) * O_ + m0 + mq * 8]) = zh;
        }
        return;
    }
    const float* Bb = Bm + (long)b * (D_ * T_);
    __shared__ float As[2][16][68];
    __shared__ float Bs[2][16][132];
    uint32_t bs_base = smem_to_u32(&Bs[0][0][0]);
    int tx = tid & 15, ty = tid >> 4;

    // per-thread A-load coords (2 float4 per stage)
    int am[2], ak[2];
    #pragma unroll
    for (int e = 0; e < 2; e++) {
        int idx = tid + e * 128;
        am[e] = idx >> 2;            // 0..63
        ak[e] = (idx & 3) * 4;       // 0,4,8,12
    }

    auto load_b = [&](int k0, int st) {
        #pragma unroll
        for (int e = 0; e < 4; e++) {
            int idx = tid + e * 128;
            int r = idx >> 5, cq = idx & 31;
            cpasync16(bs_base + (uint32_t)((st * 16 * 132 + r * 132 + cq * 4) * 4),
                      &Bb[(long)(k0 + r) * T_ + n0 + cq * 4]);
        }
    };

    // preload stage 0
    float4 areg[2];
    #pragma unroll
    for (int e = 0; e < 2; e++)
        areg[e] = *reinterpret_cast<const float4*>(&A[(m0 + am[e]) * D_ + ak[e]]);
    #pragma unroll
    for (int e = 0; e < 2; e++) {
        As[0][ak[e] + 0][am[e]] = areg[e].x;
        As[0][ak[e] + 1][am[e]] = areg[e].y;
        As[0][ak[e] + 2][am[e]] = areg[e].z;
        As[0][ak[e] + 3][am[e]] = areg[e].w;
    }
    load_b(0, 0);
    CP_COMMIT();

    float acc[8][8] = {};
    for (int it = 0; it < 16; it++) {
        int st = it & 1;
        if (it + 1 < 16) {
            load_b((it + 1) * 16, st ^ 1);
            CP_COMMIT();
            #pragma unroll
            for (int e = 0; e < 2; e++)
                areg[e] = *reinterpret_cast<const float4*>(
                    &A[(m0 + am[e]) * D_ + (it + 1) * 16 + ak[e]]);
            CP_WAIT(1);
        } else {
            CP_WAIT(0);
        }
        __syncthreads();
        #pragma unroll
        for (int kk = 0; kk < 16; kk++) {
            float4 a0 = *reinterpret_cast<const float4*>(&As[st][kk][ty * 8]);
            float4 a1 = *reinterpret_cast<const float4*>(&As[st][kk][ty * 8 + 4]);
            float4 b0 = *reinterpret_cast<const float4*>(&Bs[st][kk][tx * 8]);
            float4 b1 = *reinterpret_cast<const float4*>(&Bs[st][kk][tx * 8 + 4]);
            float av[8] = {a0.x, a0.y, a0.z, a0.w, a1.x, a1.y, a1.z, a1.w};
            float bv[8] = {b0.x, b0.y, b0.z, b0.w, b1.x, b1.y, b1.z, b1.w};
            #pragma unroll
            for (int i = 0; i < 8; i++)
                #pragma unroll
                for (int j = 0; j < 8; j++)
                    acc[i][j] += av[i] * bv[j];
        }
        if (it + 1 < 16) {
            #pragma unroll
            for (int e = 0; e < 2; e++) {
                As[st ^ 1][ak[e] + 0][am[e]] = areg[e].x;
                As[st ^ 1][ak[e] + 1][am[e]] = areg[e].y;
                As[st ^ 1][ak[e] + 2][am[e]] = areg[e].z;
                As[st ^ 1][ak[e] + 3][am[e]] = areg[e].w;
            }
        }
    }

    #pragma unroll
    for (int i = 0; i < 8; i++) {
        int m = m0 + ty * 8 + i;
        float bi = bias[m];
        #pragma unroll
        for (int j = 0; j < 8; j++) {
            int n = n0 + tx * 8 + j;
            acc[i][j] = fmaxf(acc[i][j] - NEGC * pad[b * T_ + n] + bi, 0.f);
        }
        float* dst = &C[((long)b * O_ + m) * T_ + n0 + tx * 8];
        *reinterpret_cast<float4*>(dst) = make_float4(acc[i][0], acc[i][1], acc[i][2], acc[i][3]);
        *reinterpret_cast<float4*>(dst + 4) = make_float4(acc[i][4], acc[i][5], acc[i][6], acc[i][7]);
    }
    #pragma unroll
    for (int j = 0; j < 8; j++) {
        int n = n0 + tx * 8 + j;
        __half h[8];
        #pragma unroll
        for (int i = 0; i < 8; i++) h[i] = __float2half(acc[i][j]);
        *reinterpret_cast<uint4*>(&Ct[((long)b * T_ + n) * O_ + m0 + ty * 8]) =
            *reinterpret_cast<const uint4*>(h);
    }
}

// ---------------- generic 64x64 tile GEMM (W2 only) ----------------
__global__ void gemm64_kernel(const float* __restrict__ A, const float* __restrict__ Bm,
                              float* __restrict__ C, int K, int N, int Mtot,
                              long strideB) {
    int b  = blockIdx.z;
    int n0 = blockIdx.x * 64;
    int m0 = blockIdx.y * 64;
    const float* Bb = Bm + (long)b * strideB;
    __shared__ float As[16][68];
    __shared__ float Bs[16][68];
    int tid = threadIdx.x;
    int tx = tid & 15, ty = tid >> 4;
    float acc[4][4] = {};
    for (int k0 = 0; k0 < K; k0 += 16) {
        #pragma unroll
        for (int p = 0; p < 4; p++) {
            int r = (tid >> 4) + p * 16;
            int c = tid & 15;
            As[c][r] = A[(m0 + r) * K + k0 + c];
        }
        #pragma unroll
        for (int p = 0; p < 4; p++) {
            int r = (tid >> 6) + p * 4;
            int c = tid & 63;
            Bs[r][c] = Bb[(long)(k0 + r) * N + n0 + c];
        }
        __syncthreads();
        #pragma unroll
        for (int kk = 0; kk < 16; kk++) {
            float4 a4 = *reinterpret_cast<const float4*>(&As[kk][ty * 4]);
            float a[4] = {a4.x, a4.y, a4.z, a4.w};
            float4 bb = *reinterpret_cast<const float4*>(&Bs[kk][tx * 4]);
            float bv[4] = {bb.x, bb.y, bb.z, bb.w};
            #pragma unroll
            for (int i = 0; i < 4; i++)
                #pragma unroll
                for (int j = 0; j < 4; j++)
                    acc[i][j] += a[i] * bv[j];
        }
        __syncthreads();
    }
    #pragma unroll
    for (int i = 0; i < 4; i++) {
        int m = m0 + ty * 4 + i;
        #pragma unroll
        for (int j = 0; j < 4; j++) {
            int n = n0 + tx * 4 + j;
            C[(long)b * Mtot * N + (long)m * N + n] = acc[i][j];
        }
    }
}

// ======================= fp16 HMMA F kernel =======================
#define FS_B 32768
#define FS_TOTAL 98304

__global__ __launch_bounds__(256, 2) void f_mma_kernel(
    const __half* __restrict__ Uk, const __half* __restrict__ Vk,
    const __half* __restrict__ Rt, const __half* __restrict__ Qt,
    float* __restrict__ F, const int* __restrict__ jmin, const int* __restrict__ imax) {
    extern __shared__ char sm[];
    uint32_t sb = smem_to_u32(sm);
    int tid = threadIdx.x, lane = tid & 31, w = tid >> 5;
    int wi = w >> 1, wj = w & 1;
    int b = blockIdx.z, i0 = blockIdx.y * 128, j0 = blockIdx.x * 64;
    int l16 = lane & 15, lh = lane >> 4;

    if (i0 >= imax[b]) return;

    if (j0 >= jmin[b]) {
        int row = tid >> 1, half = tid & 1;
        float4 z = make_float4(0.f, 0.f, 0.f, 0.f);
        float* dst = F + ((long)b * T_ + i0 + row) * T_ + j0 + half * 32;
        #pragma unroll
        for (int e = 0; e < 8; e++) reinterpret_cast<float4*>(dst)[e] = z;
        return;
    }

    const __half* apt[2] = {Uk, Vk};
    const __half* bpt[2] = {Rt, Qt};

    #pragma unroll
    for (int arr = 0; arr < 2; arr++) {
        const __half* src = bpt[arr] + ((long)b * T_ + j0) * O_;
        #pragma unroll
        for (int e = 0; e < 8; e++) {
            int idx = tid + e * 256;
            int ch = idx >> 8;
            int row = (idx & 255) >> 2;
            int cb = (idx & 3) * 16;
            const void* g = src + (long)row * O_ + ch * 32 + cb / 2;
            cpasync16(sb + FS_B + arr * 32768 + ch * 4096 + paddr(row, cb), g);
        }
    }
    CP_COMMIT();

    auto load_a = [&](int cu, int st) {
        int k = cu >> 3, ch = cu & 7;
        #pragma unroll
        for (int arr = 0; arr < 2; arr++) {
            const __half* src = apt[arr] + ((long)k * T_ + i0) * O_ + ch * 32;
            #pragma unroll
            for (int e = 0; e < 2; e++) {
                int idx = tid + e * 256;
                int row = idx >> 2;
                int cb = (idx & 3) * 16;
                const void* g = src + (long)row * O_ + cb / 2;
                cpasync16(sb + st * 16384 + arr * 8192 + paddr(row, cb), g);
            }
        }
    };

    load_a(0, 0);
    CP_COMMIT();

    float f[32], d1[32], d2[32];
    #pragma unroll
    for (int i = 0; i < 32; i++) { f[i] = 0.f; d1[i] = 0.f; d2[i] = 0.f; }

    for (int cu = 0; cu < 64; cu++) {
        int st = cu & 1, ch = cu & 7;
        if (cu + 1 < 64) {
            load_a(cu + 1, (cu + 1) & 1);
            CP_COMMIT();
            CP_WAIT(1);
        } else {
            CP_WAIT(0);
        }
        __syncthreads();

        uint32_t abase = sb + st * 16384;
        #pragma unroll
        for (int os = 0; os < 2; os++) {
            uint32_t colb = (uint32_t)(os * 32 + lh * 16);
            uint32_t arow = (uint32_t)(wi * 32 + l16);
            uint32_t brow = (uint32_t)(wj * 32 + l16);
            {
                uint32_t a0[4], a1[4], b0r[4], b1r[4];
                ldsm4(a0, abase + 0 * 8192 + paddr(arow, colb));
                ldsm4(a1, abase + 0 * 8192 + paddr(arow + 16, colb));
                uint32_t bb0 = sb + FS_B + 0 * 32768 + ch * 4096;
                ldsm4(b0r, bb0 + paddr(brow, colb));
                ldsm4(b1r, bb0 + paddr(brow + 16, colb));
                #pragma unroll
                for (int mt = 0; mt < 2; mt++) {
                    const uint32_t* a = mt ? a1 : a0;
                    #pragma unroll
                    for (int nt = 0; nt < 4; nt++) {
                        const uint32_t* bb = (nt >> 1) ? b1r : b0r;
                        int s = nt & 1;
                        mma16816h(d1 + (mt * 4 + nt) * 4, a, bb[s], bb[s + 2]);
                    }
                }
            }
            {
                uint32_t a0[4], a1[4], b0r[4], b1r[4];
                ldsm4(a0, abase + 1 * 8192 + paddr(arow, colb));
                ldsm4(a1, abase + 1 * 8192 + paddr(arow + 16, colb));
                uint32_t bb1 = sb + FS_B + 1 * 32768 + ch * 4096;
                ldsm4(b0r, bb1 + paddr(brow, colb));
                ldsm4(b1r, bb1 + paddr(brow + 16, colb));
                #pragma unroll
                for (int mt = 0; mt < 2; mt++) {
                    const uint32_t* a = mt ? a1 : a0;
                    #pragma unroll
                    for (int nt = 0; nt < 4; nt++) {
                        const uint32_t* bb = (nt >> 1) ? b1r : b0r;
                        int s = nt & 1;
                        mma16816h(d2 + (mt * 4 + nt) * 4, a, bb[s], bb[s + 2]);
                    }
                }
            }
        }
        if (ch == 7) {
            #pragma unroll
            for (int i = 0; i < 32; i++) {
                f[i] += d1[i] * d2[i];
                d1[i] = 0.f; d2[i] = 0.f;
            }
        }
        __syncthreads();
    }

    int r4 = lane >> 2, c2 = (lane & 3) * 2;
    #pragma unroll
    for (int mt = 0; mt < 2; mt++) {
        #pragma unroll
        for (int nt = 0; nt < 4; nt++) {
            float* d = f + (mt * 4 + nt) * 4;
            long row = i0 + wi * 32 + mt * 16 + r4;
            long col = j0 + wj * 32 + nt * 8 + c2;
            float* dst = F + ((long)b * T_ + row) * T_ + col;
            dst[0] = d[0]; dst[1] = d[1];
            dst[8 * T_] = d[2]; dst[8 * T_ + 1] = d[3];
        }
    }
}

// ---------------- fused M + d kernel ----------------
__global__ void md_kernel(const float* __restrict__ Bias, const float* __restrict__ Mul,
                          const float* __restrict__ F, const float* __restrict__ w,
                          const float* __restrict__ pad, float* __restrict__ d,
                          const int* __restrict__ lencol, const int* __restrict__ lenmul) {
    int b  = blockIdx.y;
    int c0 = blockIdx.x * 64;
    int tid = threadIdx.x;
    if (c0 >= lencol[b]) {
        if (tid < 64) d[b * T_ + c0 + tid] = -NEGC;
        return;
    }
    int ibound = (lenmul[b] + 15) & ~15;
    __shared__ float Ms[16][68];
    __shared__ float Fs[16][68];
    __shared__ float red[16][64];
    int tx = tid & 15, ty = tid >> 4;
    float acc[4][4] = {};
    const float* Mb = Mul + (long)b * G_ * T_;
    const float* Fb = F   + (long)b * T_ * T_;
    for (int i0 = 0; i0 < ibound; i0 += 16) {
        #pragma unroll
        for (int p = 0; p < 4; p++) {
            int r = (tid >> 4) + p * 16;
            int c = tid & 15;
            Ms[c][r] = Mb[r * T_ + i0 + c];
        }
        #pragma unroll
        for (int p = 0; p < 4; p++) {
            int r = (tid >> 6) + p * 4;
            int c = tid & 63;
            Fs[r][c] = Fb[(long)(i0 + r) * T_ + c0 + c];
        }
        __syncthreads();
        #pragma unroll
        for (int ii = 0; ii < 16; ii++) {
            float4 m4 = *reinterpret_cast<const float4*>(&Ms[ii][ty * 4]);
            float m[4] = {m4.x, m4.y, m4.z, m4.w};
            float4 f4 = *reinterpret_cast<const float4*>(&Fs[ii][tx * 4]);
            float ff[4] = {f4.x, f4.y, f4.z, f4.w};
            #pragma unroll
            for (int i = 0; i < 4; i++)
                #pragma unroll
                for (int j = 0; j < 4; j++)
                    acc[i][j] += m[i] * ff[j];
        }
        __syncthreads();
    }
    float part[4] = {0.f, 0.f, 0.f, 0.f};
    #pragma unroll
    for (int gq = 0; gq < 4; gq++) {
        int g = ty * 4 + gq;
        float wg = w[g];
        #pragma unroll
        for (int c = 0; c < 4; c++) {
            float vv = acc[gq][c] + Bias[(long)b * G_ * T_ + g * T_ + c0 + tx * 4 + c];
            part[c] += wg * fmaxf(vv, 0.f);
        }
    }
    #pragma unroll
    for (int c = 0; c < 4; c++) red[ty][tx * 4 + c] = part[c];
    __syncthreads();
    #pragma unroll
    for (int s = 8; s > 0; s >>= 1) {
        if (ty < s) {
            #pragma unroll
            for (int c = 0; c < 4; c++) red[ty][tx * 4 + c] += red[ty + s][tx * 4 + c];
        }
        __syncthreads();
    }
    if (ty == 0) {
        #pragma unroll
        for (int c = 0; c < 4; c++) {
            int col = c0 + tx * 4 + c;
            d[b * T_ + col] = red[0][tx * 4 + c] - NEGC * pad[b * T_ + col];
        }
    }
}

// ---------------- softmax ----------------
__global__ void softmax_kernel(const float* __restrict__ d1, const float* __restrict__ d2,
                               float* __restrict__ g1, float* __restrict__ g2) {
    int b = blockIdx.x;
    const float* d = blockIdx.y ? d2 : d1;
    float* g = blockIdx.y ? g2 : g1;
    int t = threadIdx.x;
    float v = d[b * T_ + t];
    __shared__ float red[16];
    float m = v;
    #pragma unroll
    for (int o = 16; o; o >>= 1) m = fmaxf(m, __shfl_xor_sync(0xffffffffu, m, o));
    if ((t & 31) == 0) red[t >> 5] = m;
    __syncthreads();
    if (t < 32) {
        float x = (t < 16) ? red[t] : -3.4e38f;
        #pragma unroll
        for (int o = 8; o; o >>= 1) x = fmaxf(x, __shfl_xor_sync(0xffffffffu, x, o));
        if (t == 0) red[0] = x;
    }
    __syncthreads();
    float mx = red[0];
    __syncthreads();
    float e = expf(v - mx);
    float s = e;
    #pragma unroll
    for (int o = 16; o; o >>= 1) s += __shfl_xor_sync(0xffffffffu, s, o);
    if ((t & 31) == 0) red[t >> 5] = s;
    __syncthreads();
    if (t < 32) {
        float x = (t < 16) ? red[t] : 0.f;
        #pragma unroll
        for (int o = 8; o; o >>= 1) x += __shfl_xor_sync(0xffffffffu, x, o);
        if (t == 0) red[0] = x;
    }
    __syncthreads();
    g[b * T_ + t] = e / red[0];
}

// ---------------- final reduction ----------------
__global__ void final_kernel(const float* __restrict__ R, const float* __restrict__ Q,
                             const float* __restrict__ gv, const float* __restrict__ gq,
                             float* __restrict__ out) {
    int b = blockIdx.x;
    __shared__ float sgv[T_], sgq[T_];
    int tid = threadIdx.x;
    sgv[tid] = gv[b * T_ + tid];
    sgq[tid] = gq[b * T_ + tid];
    __syncthreads();
    int o = tid & 255;
    int h = tid >> 8;
    const float* Rb = R + (long)b * O_ * T_;
    const float* Qb = Q + (long)b * O_ * T_;
    float tr = 0.f, lg = 0.f;
    #pragma unroll 4
    for (int t = h * 256; t < h * 256 + 256; t++) {
        tr += sgv[t] * Rb[t * O_ + o];
        lg += sgq[t] * Qb[t * O_ + o];
    }
    __shared__ float str[2][256], slg[2][256];
    str[h][o] = tr;
    slg[h][o] = lg;
    __syncthreads();
    if (h == 0) out[b * O_ + o] = (str[0][o] + str[1][o]) * (slg[0][o] + slg[1][o]);
}

// ---------------- launcher ----------------
extern "C" void kernel_launch(void* const* d_in, const int* in_sizes, int n_in,
                              void* d_out, int out_size) {
    const float* x0  = (const float*)d_in[0];
    const float* x1  = (const float*)d_in[1];
    const unsigned char* qm = (const unsigned char*)d_in[2];
    const unsigned char* vm = (const unsigned char*)d_in[3];
    const float* W_R = (const float*)d_in[4];
    const float* W_Q = (const float*)d_in[5];
    const float* br  = (const float*)d_in[6];
    const float* bq  = (const float*)d_in[7];
    const float* U   = (const float*)d_in[8];
    const float* V   = (const float*)d_in[9];
    const float* W2R = (const float*)d_in[10];
    const float* W2Q = (const float*)d_in[11];
    const float* wmv = (const float*)d_in[12];
    const float* wmq = (const float*)d_in[13];
    float* out = (float*)d_out;

    float *pR, *pQ, *pF, *pWR, *pWQ, *pd1, *pd2, *pg1, *pg2, *ppq, *ppv;
    int *pl1, *pl2, *pjm, *pim;
    __half *pUk, *pVk, *pRt, *pQt;
    cudaGetSymbolAddress((void**)&pR,  g_R);
    cudaGetSymbolAddress((void**)&pQ,  g_Q);
    cudaGetSymbolAddress((void**)&pF,  g_F);
    cudaGetSymbolAddress((void**)&pWR, g_WR);
    cudaGetSymbolAddress((void**)&pWQ, g_WQ);
    cudaGetSymbolAddress((void**)&pd1, g_d1);
    cudaGetSymbolAddress((void**)&pd2, g_d2);
    cudaGetSymbolAddress((void**)&pg1, g_g1);
    cudaGetSymbolAddress((void**)&pg2, g_g2);
    cudaGetSymbolAddress((void**)&ppq, g_pq);
    cudaGetSymbolAddress((void**)&ppv, g_pv);
    cudaGetSymbolAddress((void**)&pl1, g_len1);
    cudaGetSymbolAddress((void**)&pl2, g_len2);
    cudaGetSymbolAddress((void**)&pjm, g_jmin);
    cudaGetSymbolAddress((void**)&pim, g_imax);
    cudaGetSymbolAddress((void**)&pUk, g_Uk);
    cudaGetSymbolAddress((void**)&pVk, g_Vk);
    cudaGetSymbolAddress((void**)&pRt, g_Rt);
    cudaGetSymbolAddress((void**)&pQt, g_Qt);

    static bool attr_done = false;
    if (!attr_done) {
        cudaFuncSetAttribute(f_mma_kernel, cudaFuncAttributeMaxDynamicSharedMemorySize, FS_TOTAL);
        attr_done = true;
    }

    maskconv_kernel<<<(B_ * T_ + 255) / 256, 256>>>(qm, vm, ppq, ppv);
    lens_kernel<<<B_, T_>>>(qm, vm, pl1, pl2, pjm, pim);
    convUV_kernel<<<(KF_ * T_ * O_ + 255) / 256, 256>>>(U, V, pUk, pVk);

    gemm_rq_kernel<<<dim3(T_ / 128, O_ / 64, B_), 128>>>(W_R, x0, pR, pRt, br, ppq, pl1);
    gemm_rq_kernel<<<dim3(T_ / 128, O_ / 64, B_), 128>>>(W_Q, x1, pQ, pQt, bq, ppv, pl2);

    f_mma_kernel<<<dim3(T_ / 64, T_ / 128, B_), 256, FS_TOTAL>>>(
        pUk, pVk, pRt, pQt, pF, pjm, pim);

    gemm64_kernel<<<dim3(T_ / 64, 1, B_), 256>>>(
        W2R, pR, pWR, O_, T_, G_, (long)O_ * T_);
    gemm64_kernel<<<dim3(T_ / 64, 1, B_), 256>>>(
        W2Q, pQ, pWQ, O_, T_, G_, (long)O_ * T_);

    md_kernel<<<dim3(T_ / 64, B_), 256>>>(pWR, pWQ, pF, wmv, ppq, pd1, pl1, pl2);
    md_kernel<<<dim3(T_ / 64, B_), 256>>>(pWQ, pWR, pF, wmq, ppv, pd2, pl2, pl1);

    softmax_kernel<<<dim3(B_, 2), T_>>>(pd1, pd2, pg1, pg2);

    final_kernel<<<B_, T_>>>(pR, pQ, pg1, pg2, out);
}

// round 12
// speedup vs baseline: 1.9810x; 1.1226x over previous
#include <cuda_runtime.h>
#include <cuda_fp16.h>
#include <cstdint>

#define NEGC 1e9f

#define B_  32
#define T_  512
#define D_  256
#define O_  256
#define KF_ 8
#define G_  64

// ---------------- scratch ----------------
__device__ float g_R [B_ * O_ * T_];
__device__ float g_Q [B_ * O_ * T_];
__device__ float g_F [B_ * T_ * T_];
__device__ float g_WR[B_ * G_ * T_];
__device__ float g_WQ[B_ * G_ * T_];
__device__ float g_d1[B_ * T_];
__device__ float g_d2[B_ * T_];
__device__ float g_g1[B_ * T_];
__device__ float g_g2[B_ * T_];
__device__ float g_pq[B_ * T_];
__device__ float g_pv[B_ * T_];
__device__ int   g_len1[B_];
__device__ int   g_len2[B_];
__device__ int   g_jmin[B_];
__device__ int   g_imax[B_];

__device__ __half g_Uk[KF_ * T_ * O_];
__device__ __half g_Vk[KF_ * T_ * O_];
__device__ __half g_Rt[B_ * T_ * O_];
__device__ __half g_Qt[B_ * T_ * O_];
// fp16 GEMM operands for R/Q
__device__ __half g_WRh[O_ * D_];
__device__ __half g_WQh[O_ * D_];
__device__ __half g_x0t[B_ * T_ * D_];   // x0 transposed [b][t][k]
__device__ __half g_x1t[B_ * T_ * D_];

// =================== helpers ===================
__device__ __forceinline__ uint32_t smem_to_u32(const void* p) {
    uint32_t a;
    asm("{ .reg .u64 t; cvta.to.shared.u64 t, %1; cvt.u32.u64 %0, t; }" : "=r"(a) : "l"(p));
    return a;
}
__device__ __forceinline__ void ldsm4(uint32_t* r, uint32_t addr) {
    asm volatile("ldmatrix.sync.aligned.m8n8.x4.shared.b16 {%0,%1,%2,%3}, [%4];"
        : "=r"(r[0]), "=r"(r[1]), "=r"(r[2]), "=r"(r[3]) : "r"(addr));
}
__device__ __forceinline__ void mma16816h(float* d, const uint32_t* a,
                                          uint32_t b0, uint32_t b1) {
    asm volatile("mma.sync.aligned.m16n8k16.row.col.f32.f16.f16.f32 "
        "{%0,%1,%2,%3}, {%4,%5,%6,%7}, {%8,%9}, {%0,%1,%2,%3};"
        : "+f"(d[0]), "+f"(d[1]), "+f"(d[2]), "+f"(d[3])
        : "r"(a[0]), "r"(a[1]), "r"(a[2]), "r"(a[3]), "r"(b0), "r"(b1));
}
__device__ __forceinline__ void cpasync16(uint32_t dst, const void* src) {
    asm volatile("cp.async.cg.shared.global [%0], [%1], 16;" :: "r"(dst), "l"(src));
}
#define CP_COMMIT() asm volatile("cp.async.commit_group;" ::: "memory")
#define CP_WAIT(n)  asm volatile("cp.async.wait_group %0;" :: "n"(n) : "memory")

__device__ __forceinline__ uint32_t paddr(uint32_t row, uint32_t cb) {
    uint32_t pr = row >> 1;
    return pr * 128 + ((((row & 1) << 6) + cb) ^ ((pr & 7) << 4));
}

__device__ __forceinline__ void decode_mask(const unsigned char* q, const unsigned char* v,
                                            int i, bool& qv, bool& vv) {
    unsigned char b1 = q[1], b3 = q[3];
    int type = (b1 == 1) ? 0 : (b1 == 0x3F) ? 3 : (b3 == 0x3F) ? 2 : 1;
    switch (type) {
        case 0: qv = q[i] != 0;                            vv = v[i] != 0; break;
        case 1: qv = ((const int*)q)[i] != 0;              vv = ((const int*)v)[i] != 0; break;
        case 2: qv = ((const float*)q)[i] != 0.f;          vv = ((const float*)v)[i] != 0.f; break;
        default: qv = ((const unsigned short*)q)[i] != 0;  vv = ((const unsigned short*)v)[i] != 0; break;
    }
}

// ---------------- mask decode ----------------
__global__ void maskconv_kernel(const unsigned char* __restrict__ q,
                                const unsigned char* __restrict__ v,
                                float* __restrict__ pq, float* __restrict__ pv) {
    int i = blockIdx.x * blockDim.x + threadIdx.x;
    if (i >= B_ * T_) return;
    bool qv, vv;
    decode_mask(q, v, i, qv, vv);
    pq[i] = qv ? 0.f : 1.f;
    pv[i] = vv ? 0.f : 1.f;
}

// ---------------- per-batch valid lengths ----------------
__global__ void lens_kernel(const unsigned char* __restrict__ q,
                            const unsigned char* __restrict__ v,
                            int* __restrict__ len1, int* __restrict__ len2,
                            int* __restrict__ jmin, int* __restrict__ imax) {
    __shared__ int s1, s2;
    int b = blockIdx.x, t = threadIdx.x;
    if (t == 0) { s1 = 0; s2 = 0; }
    __syncthreads();
    bool qv, vv;
    decode_mask(q, v, b * T_ + t, qv, vv);
    unsigned m1 = __ballot_sync(0xffffffffu, qv);
    unsigned m2 = __ballot_sync(0xffffffffu, vv);
    if ((t & 31) == 0) { atomicAdd(&s1, __popc(m1)); atomicAdd(&s2, __popc(m2)); }
    __syncthreads();
    if (t == 0) {
        len1[b] = s1; len2[b] = s2;
        jmin[b] = s1 < s2 ? s1 : s2;
        imax[b] = s1 > s2 ? s1 : s2;
    }
}

// ---------------- U/V de-interleave + fp16 ----------------
__global__ void convUV_kernel(const float* __restrict__ U, const float* __restrict__ V,
                              __half* __restrict__ Uo, __half* __restrict__ Vo) {
    int idx = blockIdx.x * blockDim.x + threadIdx.x;
    if (idx >= KF_ * T_ * O_) return;
    int k = idx >> 17;
    int m = idx & (T_ * O_ - 1);
    Uo[idx] = __float2half(U[m * KF_ + k]);
    Vo[idx] = __float2half(V[m * KF_ + k]);
}

// ---------------- W -> fp16 ----------------
__global__ void convW_kernel(const float* __restrict__ WR, const float* __restrict__ WQ,
                             __half* __restrict__ WRh, __half* __restrict__ WQh) {
    int i = blockIdx.x * blockDim.x + threadIdx.x;
    if (i >= O_ * D_) return;
    WRh[i] = __float2half(WR[i]);
    WQh[i] = __float2half(WQ[i]);
}

// ---------------- x transpose -> fp16: xt[b][t][k] = x[b].flat[k*T + t] ----------------
__global__ void convX_kernel(const float* __restrict__ x0, const float* __restrict__ x1,
                             __half* __restrict__ x0t, __half* __restrict__ x1t) {
    __shared__ float tile[32][33];
    int zz = blockIdx.z;
    int b = zz & 31;
    bool is1 = (zz >> 5) != 0;
    const float* src = (is1 ? x1 : x0) + (long)b * D_ * T_;
    __half* dst = (is1 ? x1t : x0t) + (long)b * T_ * D_;
    int t0 = blockIdx.x * 32, k0 = blockIdx.y * 32;
    int tx = threadIdx.x, ty = threadIdx.y;
    #pragma unroll
    for (int r = 0; r < 4; r++)
        tile[ty + r * 8][tx] = src[(long)(k0 + ty + r * 8) * T_ + t0 + tx];
    __syncthreads();
    #pragma unroll
    for (int r = 0; r < 4; r++)
        dst[(long)(t0 + ty + r * 8) * D_ + k0 + tx] = __float2half(tile[tx][ty + r * 8]);
}

// ---------------- fp16 HMMA R/Q GEMM: m64 x n128, W persistent, xT streamed ----------------
// SMEM: A(W) [64m][256k] paddr-chunked (8 x 4KB = 32KB) at 0;
//       B(xT) 2 stages x [128n][32k] (8KB) at 32768. Cs epilogue overlays at 0.
__global__ __launch_bounds__(256) void gemm_rq_h_kernel(
    const __half* __restrict__ Wh, const __half* __restrict__ Xt,
    float* __restrict__ C, __half* __restrict__ Ct,
    const float* __restrict__ bias,
    const float* __restrict__ pad, const int* __restrict__ lenp) {
    __shared__ char gsm[49152];
    uint32_t sb = smem_to_u32(gsm);
    int b = blockIdx.z;
    int n0 = blockIdx.x * 128;
    int m0 = blockIdx.y * 64;
    int tid = threadIdx.x, lane = tid & 31, w = tid >> 5;
    int wi = w >> 2, wj = w & 3;
    int l16 = lane & 15, lh = lane >> 4;

    if (n0 >= lenp[b]) {
        float4 z = make_float4(0.f, 0.f, 0.f, 0.f);
        #pragma unroll
        for (int e = 0; e < 8; e++) {
            int idx = tid + e * 256;               // 0..2047 float4
            int m = idx >> 5, nq = idx & 31;
            *reinterpret_cast<float4*>(&C[((long)b * O_ + m0 + m) * T_ + n0 + nq * 4]) = z;
        }
        uint4 zh = make_uint4(0, 0, 0, 0);
        #pragma unroll
        for (int e = 0; e < 2; e++) {
            int idx = tid + e * 256;               // 0..511 uint4 (8 halfs)
            int n = idx >> 2, mq = idx & 3;
            *reinterpret_cast<uint4*>(&Ct[((long)b * T_ + n0 + n) * O_ + m0 + mq * 16]) = zh;
        }
        return;
    }

    const __half* Wb = Wh + (long)m0 * D_;
    const __half* Xb = Xt + ((long)b * T_ + n0) * D_;

    // preload all A (W) chunks: 8 chunks x 4KB; 8 transfers per thread
    #pragma unroll
    for (int e = 0; e < 8; e++) {
        int idx = tid + e * 256;                   // 0..2047 transfers of 16B
        int ch = idx >> 8;                         // 0..7
        int row = (idx & 255) >> 2;                // 0..63 (m)
        int cb = (idx & 3) * 16;
        cpasync16(sb + ch * 4096 + paddr(row, cb),
                  Wb + (long)row * D_ + ch * 32 + cb / 2);
    }
    CP_COMMIT();

    auto load_b = [&](int ch, int st) {
        #pragma unroll
        for (int e = 0; e < 2; e++) {
            int idx = tid + e * 256;               // 0..511 transfers
            int row = idx >> 2;                    // 0..127 (n)
            int cb = (idx & 3) * 16;
            cpasync16(sb + 32768 + st * 8192 + paddr(row, cb),
                      Xb + (long)row * D_ + ch * 32 + cb / 2);
        }
    };
    load_b(0, 0);
    CP_COMMIT();

    float acc[32];
    #pragma unroll
    for (int i = 0; i < 32; i++) acc[i] = 0.f;

    for (int ch = 0; ch < 8; ch++) {
        int st = ch & 1;
        if (ch + 1 < 8) {
            load_b(ch + 1, st ^ 1);
            CP_COMMIT();
            CP_WAIT(1);
        } else {
            CP_WAIT(0);
        }
        __syncthreads();
        uint32_t abase = sb + ch * 4096;
        uint32_t bbase = sb + 32768 + st * 8192;
        #pragma unroll
        for (int os = 0; os < 2; os++) {
            uint32_t colb = (uint32_t)(os * 32 + lh * 16);
            uint32_t arow = (uint32_t)(wi * 32 + l16);
            uint32_t brow = (uint32_t)(wj * 32 + l16);
            uint32_t a0[4], a1[4], b0r[4], b1r[4];
            ldsm4(a0, abase + paddr(arow, colb));
            ldsm4(a1, abase + paddr(arow + 16, colb));
            ldsm4(b0r, bbase + paddr(brow, colb));
            ldsm4(b1r, bbase + paddr(brow + 16, colb));
            #pragma unroll
            for (int mt = 0; mt < 2; mt++) {
                const uint32_t* a = mt ? a1 : a0;
                #pragma unroll
                for (int nt = 0; nt < 4; nt++) {
                    const uint32_t* bb = (nt >> 1) ? b1r : b0r;
                    int s = nt & 1;
                    mma16816h(acc + (mt * 4 + nt) * 4, a, bb[s], bb[s + 2]);
                }
            }
        }
        __syncthreads();
    }

    // epilogue: mask + bias + relu in fp32; write C; stage fp16 for transposed Ct
    __half* Cs = reinterpret_cast<__half*>(gsm);   // [64 m][136 stride]
    int r4 = lane >> 2, c2 = (lane & 3) * 2;
    #pragma unroll
    for (int mt = 0; mt < 2; mt++) {
        #pragma unroll
        for (int nt = 0; nt < 4; nt++) {
            float* d = acc + (mt * 4 + nt) * 4;
            #pragma unroll
            for (int half_ = 0; half_ < 2; half_++) {
                int row = wi * 32 + mt * 16 + r4 + half_ * 8;
                int col = wj * 32 + nt * 8 + c2;
                int m = m0 + row, n = n0 + col;
                float bi = bias[m];
                float v0 = fmaxf(d[half_ * 2 + 0] - NEGC * pad[b * T_ + n] + bi, 0.f);
                float v1 = fmaxf(d[half_ * 2 + 1] - NEGC * pad[b * T_ + n + 1] + bi, 0.f);
                float* dst = &C[((long)b * O_ + m) * T_ + n];
                dst[0] = v0; dst[1] = v1;
                Cs[row * 136 + col] = __float2half(v0);
                Cs[row * 136 + col + 1] = __float2half(v1);
            }
        }
    }
    __syncthreads();
    // transposed fp16 write: Ct[b][t=n][o=m]
    {
        int n = tid >> 1;
        int mh = (tid & 1) * 32;
        __half hbuf[32];
        #pragma unroll
        for (int mm = 0; mm < 32; mm++) hbuf[mm] = Cs[(mh + mm) * 136 + n];
        uint4* dst = reinterpret_cast<uint4*>(&Ct[((long)b * T_ + n0 + n) * O_ + m0 + mh]);
        const uint4* srcv = reinterpret_cast<const uint4*>(hbuf);
        dst[0] = srcv[0]; dst[1] = srcv[1]; dst[2] = srcv[2]; dst[3] = srcv[3];
    }
}

// ---------------- generic 64x64 tile GEMM (W2 only) ----------------
__global__ void gemm64_kernel(const float* __restrict__ A, const float* __restrict__ Bm,
                              float* __restrict__ C, int K, int N, int Mtot,
                              long strideB) {
    int b  = blockIdx.z;
    int n0 = blockIdx.x * 64;
    int m0 = blockIdx.y * 64;
    const float* Bb = Bm + (long)b * strideB;
    __shared__ float As[16][68];
    __shared__ float Bs[16][68];
    int tid = threadIdx.x;
    int tx = tid & 15, ty = tid >> 4;
    float acc[4][4] = {};
    for (int k0 = 0; k0 < K; k0 += 16) {
        #pragma unroll
        for (int p = 0; p < 4; p++) {
            int r = (tid >> 4) + p * 16;
            int c = tid & 15;
            As[c][r] = A[(m0 + r) * K + k0 + c];
        }
        #pragma unroll
        for (int p = 0; p < 4; p++) {
            int r = (tid >> 6) + p * 4;
            int c = tid & 63;
            Bs[r][c] = Bb[(long)(k0 + r) * N + n0 + c];
        }
        __syncthreads();
        #pragma unroll
        for (int kk = 0; kk < 16; kk++) {
            float4 a4 = *reinterpret_cast<const float4*>(&As[kk][ty * 4]);
            float a[4] = {a4.x, a4.y, a4.z, a4.w};
            float4 bb = *reinterpret_cast<const float4*>(&Bs[kk][tx * 4]);
            float bv[4] = {bb.x, bb.y, bb.z, bb.w};
            #pragma unroll
            for (int i = 0; i < 4; i++)
                #pragma unroll
                for (int j = 0; j < 4; j++)
                    acc[i][j] += a[i] * bv[j];
        }
        __syncthreads();
    }
    #pragma unroll
    for (int i = 0; i < 4; i++) {
        int m = m0 + ty * 4 + i;
        #pragma unroll
        for (int j = 0; j < 4; j++) {
            int n = n0 + tx * 4 + j;
            C[(long)b * Mtot * N + (long)m * N + n] = acc[i][j];
        }
    }
}

// ======================= fp16 HMMA F kernel =======================
#define FS_B 32768
#define FS_TOTAL 98304

__global__ __launch_bounds__(256, 2) void f_mma_kernel(
    const __half* __restrict__ Uk, const __half* __restrict__ Vk,
    const __half* __restrict__ Rt, const __half* __restrict__ Qt,
    float* __restrict__ F, const int* __restrict__ jmin, const int* __restrict__ imax) {
    extern __shared__ char sm[];
    uint32_t sb = smem_to_u32(sm);
    int tid = threadIdx.x, lane = tid & 31, w = tid >> 5;
    int wi = w >> 1, wj = w & 1;
    int b = blockIdx.z, i0 = blockIdx.y * 128, j0 = blockIdx.x * 64;
    int l16 = lane & 15, lh = lane >> 4;

    if (i0 >= imax[b]) return;

    if (j0 >= jmin[b]) {
        int row = tid >> 1, half = tid & 1;
        float4 z = make_float4(0.f, 0.f, 0.f, 0.f);
        float* dst = F + ((long)b * T_ + i0 + row) * T_ + j0 + half * 32;
        #pragma unroll
        for (int e = 0; e < 8; e++) reinterpret_cast<float4*>(dst)[e] = z;
        return;
    }

    const __half* apt[2] = {Uk, Vk};
    const __half* bpt[2] = {Rt, Qt};

    #pragma unroll
    for (int arr = 0; arr < 2; arr++) {
        const __half* src = bpt[arr] + ((long)b * T_ + j0) * O_;
        #pragma unroll
        for (int e = 0; e < 8; e++) {
            int idx = tid + e * 256;
            int ch = idx >> 8;
            int row = (idx & 255) >> 2;
            int cb = (idx & 3) * 16;
            const void* g = src + (long)row * O_ + ch * 32 + cb / 2;
            cpasync16(sb + FS_B + arr * 32768 + ch * 4096 + paddr(row, cb), g);
        }
    }
    CP_COMMIT();

    auto load_a = [&](int cu, int st) {
        int k = cu >> 3, ch = cu & 7;
        #pragma unroll
        for (int arr = 0; arr < 2; arr++) {
            const __half* src = apt[arr] + ((long)k * T_ + i0) * O_ + ch * 32;
            #pragma unroll
            for (int e = 0; e < 2; e++) {
                int idx = tid + e * 256;
                int row = idx >> 2;
                int cb = (idx & 3) * 16;
                const void* g = src + (long)row * O_ + cb / 2;
                cpasync16(sb + st * 16384 + arr * 8192 + paddr(row, cb), g);
            }
        }
    };

    load_a(0, 0);
    CP_COMMIT();

    float f[32], d1[32], d2[32];
    #pragma unroll
    for (int i = 0; i < 32; i++) { f[i] = 0.f; d1[i] = 0.f; d2[i] = 0.f; }

    for (int cu = 0; cu < 64; cu++) {
        int st = cu & 1, ch = cu & 7;
        if (cu + 1 < 64) {
            load_a(cu + 1, (cu + 1) & 1);
            CP_COMMIT();
            CP_WAIT(1);
        } else {
            CP_WAIT(0);
        }
        __syncthreads();

        uint32_t abase = sb + st * 16384;
        #pragma unroll
        for (int os = 0; os < 2; os++) {
            uint32_t colb = (uint32_t)(os * 32 + lh * 16);
            uint32_t arow = (uint32_t)(wi * 32 + l16);
            uint32_t brow = (uint32_t)(wj * 32 + l16);
            {
                uint32_t a0[4], a1[4], b0r[4], b1r[4];
                ldsm4(a0, abase + 0 * 8192 + paddr(arow, colb));
                ldsm4(a1, abase + 0 * 8192 + paddr(arow + 16, colb));
                uint32_t bb0 = sb + FS_B + 0 * 32768 + ch * 4096;
                ldsm4(b0r, bb0 + paddr(brow, colb));
                ldsm4(b1r, bb0 + paddr(brow + 16, colb));
                #pragma unroll
                for (int mt = 0; mt < 2; mt++) {
                    const uint32_t* a = mt ? a1 : a0;
                    #pragma unroll
                    for (int nt = 0; nt < 4; nt++) {
                        const uint32_t* bb = (nt >> 1) ? b1r : b0r;
                        int s = nt & 1;
                        mma16816h(d1 + (mt * 4 + nt) * 4, a, bb[s], bb[s + 2]);
                    }
                }
            }
            {
                uint32_t a0[4], a1[4], b0r[4], b1r[4];
                ldsm4(a0, abase + 1 * 8192 + paddr(arow, colb));
                ldsm4(a1, abase + 1 * 8192 + paddr(arow + 16, colb));
                uint32_t bb1 = sb + FS_B + 1 * 32768 + ch * 4096;
                ldsm4(b0r, bb1 + paddr(brow, colb));
                ldsm4(b1r, bb1 + paddr(brow + 16, colb));
                #pragma unroll
                for (int mt = 0; mt < 2; mt++) {
                    const uint32_t* a = mt ? a1 : a0;
                    #pragma unroll
                    for (int nt = 0; nt < 4; nt++) {
                        const uint32_t* bb = (nt >> 1) ? b1r : b0r;
                        int s = nt & 1;
                        mma16816h(d2 + (mt * 4 + nt) * 4, a, bb[s], bb[s + 2]);
                    }
                }
            }
        }
        if (ch == 7) {
            #pragma unroll
            for (int i = 0; i < 32; i++) {
                f[i] += d1[i] * d2[i];
                d1[i] = 0.f; d2[i] = 0.f;
            }
        }
        __syncthreads();
    }

    int r4 = lane >> 2, c2 = (lane & 3) * 2;
    #pragma unroll
    for (int mt = 0; mt < 2; mt++) {
        #pragma unroll
        for (int nt = 0; nt < 4; nt++) {
            float* d = f + (mt * 4 + nt) * 4;
            long row = i0 + wi * 32 + mt * 16 + r4;
            long col = j0 + wj * 32 + nt * 8 + c2;
            float* dst = F + ((long)b * T_ + row) * T_ + col;
            dst[0] = d[0]; dst[1] = d[1];
            dst[8 * T_] = d[2]; dst[8 * T_ + 1] = d[3];
        }
    }
}

// ---------------- fused M + d kernel ----------------
__global__ void md_kernel(const float* __restrict__ Bias, const float* __restrict__ Mul,
                          const float* __restrict__ F, const float* __restrict__ w,
                          const float* __restrict__ pad, float* __restrict__ d,
                          const int* __restrict__ lencol, const int* __restrict__ lenmul) {
    int b  = blockIdx.y;
    int c0 = blockIdx.x * 64;
    int tid = threadIdx.x;
    if (c0 >= lencol[b]) {
        if (tid < 64) d[b * T_ + c0 + tid] = -NEGC;
        return;
    }
    int ibound = (lenmul[b] + 15) & ~15;
    __shared__ float Ms[16][68];
    __shared__ float Fs[16][68];
    __shared__ float red[16][64];
    int tx = tid & 15, ty = tid >> 4;
    float acc[4][4] = {};
    const float* Mb = Mul + (long)b * G_ * T_;
    const float* Fb = F   + (long)b * T_ * T_;
    for (int i0 = 0; i0 < ibound; i0 += 16) {
        #pragma unroll
        for (int p = 0; p < 4; p++) {
            int r = (tid >> 4) + p * 16;
            int c = tid & 15;
            Ms[c][r] = Mb[r * T_ + i0 + c];
        }
        #pragma unroll
        for (int p = 0; p < 4; p++) {
            int r = (tid >> 6) + p * 4;
            int c = tid & 63;
            Fs[r][c] = Fb[(long)(i0 + r) * T_ + c0 + c];
        }
        __syncthreads();
        #pragma unroll
        for (int ii = 0; ii < 16; ii++) {
            float4 m4 = *reinterpret_cast<const float4*>(&Ms[ii][ty * 4]);
            float m[4] = {m4.x, m4.y, m4.z, m4.w};
            float4 f4 = *reinterpret_cast<const float4*>(&Fs[ii][tx * 4]);
            float ff[4] = {f4.x, f4.y, f4.z, f4.w};
            #pragma unroll
            for (int i = 0; i < 4; i++)
                #pragma unroll
                for (int j = 0; j < 4; j++)
                    acc[i][j] += m[i] * ff[j];
        }
        __syncthreads();
    }
    float part[4] = {0.f, 0.f, 0.f, 0.f};
    #pragma unroll
    for (int gq = 0; gq < 4; gq++) {
        int g = ty * 4 + gq;
        float wg = w[g];
        #pragma unroll
        for (int c = 0; c < 4; c++) {
            float vv = acc[gq][c] + Bias[(long)b * G_ * T_ + g * T_ + c0 + tx * 4 + c];
            part[c] += wg * fmaxf(vv, 0.f);
        }
    }
    #pragma unroll
    for (int c = 0; c < 4; c++) red[ty][tx * 4 + c] = part[c];
    __syncthreads();
    #pragma unroll
    for (int s = 8; s > 0; s >>= 1) {
        if (ty < s) {
            #pragma unroll
            for (int c = 0; c < 4; c++) red[ty][tx * 4 + c] += red[ty + s][tx * 4 + c];
        }
        __syncthreads();
    }
    if (ty == 0) {
        #pragma unroll
        for (int c = 0; c < 4; c++) {
            int col = c0 + tx * 4 + c;
            d[b * T_ + col] = red[0][tx * 4 + c] - NEGC * pad[b * T_ + col];
        }
    }
}

// ---------------- softmax ----------------
__global__ void softmax_kernel(const float* __restrict__ d1, const float* __restrict__ d2,
                               float* __restrict__ g1, float* __restrict__ g2) {
    int b = blockIdx.x;
    const float* d = blockIdx.y ? d2 : d1;
    float* g = blockIdx.y ? g2 : g1;
    int t = threadIdx.x;
    float v = d[b * T_ + t];
    __shared__ float red[16];
    float m = v;
    #pragma unroll
    for (int o = 16; o; o >>= 1) m = fmaxf(m, __shfl_xor_sync(0xffffffffu, m, o));
    if ((t & 31) == 0) red[t >> 5] = m;
    __syncthreads();
    if (t < 32) {
        float x = (t < 16) ? red[t] : -3.4e38f;
        #pragma unroll
        for (int o = 8; o; o >>= 1) x = fmaxf(x, __shfl_xor_sync(0xffffffffu, x, o));
        if (t == 0) red[0] = x;
    }
    __syncthreads();
    float mx = red[0];
    __syncthreads();
    float e = expf(v - mx);
    float s = e;
    #pragma unroll
    for (int o = 16; o; o >>= 1) s += __shfl_xor_sync(0xffffffffu, s, o);
    if ((t & 31) == 0) red[t >> 5] = s;
    __syncthreads();
    if (t < 32) {
        float x = (t < 16) ? red[t] : 0.f;
        #pragma unroll
        for (int o = 8; o; o >>= 1) x += __shfl_xor_sync(0xffffffffu, x, o);
        if (t == 0) red[0] = x;
    }
    __syncthreads();
    g[b * T_ + t] = e / red[0];
}

// ---------------- final reduction ----------------
__global__ void final_kernel(const float* __restrict__ R, const float* __restrict__ Q,
                             const float* __restrict__ gv, const float* __restrict__ gq,
                             float* __restrict__ out) {
    int b = blockIdx.x;
    __shared__ float sgv[T_], sgq[T_];
    int tid = threadIdx.x;
    sgv[tid] = gv[b * T_ + tid];
    sgq[tid] = gq[b * T_ + tid];
    __syncthreads();
    int o = tid & 255;
    int h = tid >> 8;
    const float* Rb = R + (long)b * O_ * T_;
    const float* Qb = Q + (long)b * O_ * T_;
    float tr = 0.f, lg = 0.f;
    #pragma unroll 4
    for (int t = h * 256; t < h * 256 + 256; t++) {
        tr += sgv[t] * Rb[t * O_ + o];
        lg += sgq[t] * Qb[t * O_ + o];
    }
    __shared__ float str[2][256], slg[2][256];
    str[h][o] = tr;
    slg[h][o] = lg;
    __syncthreads();
    if (h == 0) out[b * O_ + o] = (str[0][o] + str[1][o]) * (slg[0][o] + slg[1][o]);
}

// ---------------- launcher ----------------
extern "C" void kernel_launch(void* const* d_in, const int* in_sizes, int n_in,
                              void* d_out, int out_size) {
    const float* x0  = (const float*)d_in[0];
    const float* x1  = (const float*)d_in[1];
    const unsigned char* qm = (const unsigned char*)d_in[2];
    const unsigned char* vm = (const unsigned char*)d_in[3];
    const float* W_R = (const float*)d_in[4];
    const float* W_Q = (const float*)d_in[5];
    const float* br  = (const float*)d_in[6];
    const float* bq  = (const float*)d_in[7];
    const float* U   = (const float*)d_in[8];
    const float* V   = (const float*)d_in[9];
    const float* W2R = (const float*)d_in[10];
    const float* W2Q = (const float*)d_in[11];
    const float* wmv = (const float*)d_in[12];
    const float* wmq = (const float*)d_in[13];
    float* out = (float*)d_out;

    float *pR, *pQ, *pF, *pWR, *pWQ, *pd1, *pd2, *pg1, *pg2, *ppq, *ppv;
    int *pl1, *pl2, *pjm, *pim;
    __half *pUk, *pVk, *pRt, *pQt, *pWRh, *pWQh, *px0t, *px1t;
    cudaGetSymbolAddress((void**)&pR,  g_R);
    cudaGetSymbolAddress((void**)&pQ,  g_Q);
    cudaGetSymbolAddress((void**)&pF,  g_F);
    cudaGetSymbolAddress((void**)&pWR, g_WR);
    cudaGetSymbolAddress((void**)&pWQ, g_WQ);
    cudaGetSymbolAddress((void**)&pd1, g_d1);
    cudaGetSymbolAddress((void**)&pd2, g_d2);
    cudaGetSymbolAddress((void**)&pg1, g_g1);
    cudaGetSymbolAddress((void**)&pg2, g_g2);
    cudaGetSymbolAddress((void**)&ppq, g_pq);
    cudaGetSymbolAddress((void**)&ppv, g_pv);
    cudaGetSymbolAddress((void**)&pl1, g_len1);
    cudaGetSymbolAddress((void**)&pl2, g_len2);
    cudaGetSymbolAddress((void**)&pjm, g_jmin);
    cudaGetSymbolAddress((void**)&pim, g_imax);
    cudaGetSymbolAddress((void**)&pUk, g_Uk);
    cudaGetSymbolAddress((void**)&pVk, g_Vk);
    cudaGetSymbolAddress((void**)&pRt, g_Rt);
    cudaGetSymbolAddress((void**)&pQt, g_Qt);
    cudaGetSymbolAddress((void**)&pWRh, g_WRh);
    cudaGetSymbolAddress((void**)&pWQh, g_WQh);
    cudaGetSymbolAddress((void**)&px0t, g_x0t);
    cudaGetSymbolAddress((void**)&px1t, g_x1t);

    static bool attr_done = false;
    if (!attr_done) {
        cudaFuncSetAttribute(f_mma_kernel, cudaFuncAttributeMaxDynamicSharedMemorySize, FS_TOTAL);
        attr_done = true;
    }

    maskconv_kernel<<<(B_ * T_ + 255) / 256, 256>>>(qm, vm, ppq, ppv);
    lens_kernel<<<B_, T_>>>(qm, vm, pl1, pl2, pjm, pim);
    convUV_kernel<<<(KF_ * T_ * O_ + 255) / 256, 256>>>(U, V, pUk, pVk);
    convW_kernel<<<(O_ * D_ + 255) / 256, 256>>>(W_R, W_Q, pWRh, pWQh);
    convX_kernel<<<dim3(T_ / 32, D_ / 32, 2 * B_), dim3(32, 8)>>>(x0, x1, px0t, px1t);

    gemm_rq_h_kernel<<<dim3(T_ / 128, O_ / 64, B_), 256>>>(
        pWRh, px0t, pR, pRt, br, ppq, pl1);
    gemm_rq_h_kernel<<<dim3(T_ / 128, O_ / 64, B_), 256>>>(
        pWQh, px1t, pQ, pQt, bq, ppv, pl2);

    f_mma_kernel<<<dim3(T_ / 64, T_ / 128, B_), 256, FS_TOTAL>>>(
        pUk, pVk, pRt, pQt, pF, pjm, pim);

    gemm64_kernel<<<dim3(T_ / 64, 1, B_), 256>>>(
        W2R, pR, pWR, O_, T_, G_, (long)O_ * T_);
    gemm64_kernel<<<dim3(T_ / 64, 1, B_), 256>>>(
        W2Q, pQ, pWQ, O_, T_, G_, (long)O_ * T_);

    md_kernel<<<dim3(T_ / 64, B_), 256>>>(pWR, pWQ, pF, wmv, ppq, pd1, pl1, pl2);
    md_kernel<<<dim3(T_ / 64, B_), 256>>>(pWQ, pWR, pF, wmq, ppv, pd2, pl2, pl1);

    softmax_kernel<<<dim3(B_, 2), T_>>>(pd1, pd2, pg1, pg2);

    final_kernel<<<B_, T_>>>(pR, pQ, pg1, pg2, out);
}

// round 13
// speedup vs baseline: 2.5636x; 1.2941x over previous
#include <cuda_runtime.h>
#include <cuda_fp16.h>
#include <cstdint>

#define NEGC 1e9f

#define B_  32
#define T_  512
#define D_  256
#define O_  256
#define KF_ 8
#define G_  64

// ---------------- scratch ----------------
__device__ float g_R [B_ * O_ * T_];
__device__ float g_Q [B_ * O_ * T_];
__device__ float g_d1[B_ * T_];
__device__ float g_d2[B_ * T_];
__device__ float g_g1[B_ * T_];
__device__ float g_g2[B_ * T_];
__device__ float g_pq[B_ * T_];
__device__ float g_pv[B_ * T_];
__device__ int   g_len1[B_];
__device__ int   g_len2[B_];
__device__ int   g_jmin[B_];
__device__ int   g_imax[B_];

__device__ __half g_Uk[KF_ * T_ * O_];
__device__ __half g_Vk[KF_ * T_ * O_];
__device__ __half g_Rt[B_ * T_ * O_];
__device__ __half g_Qt[B_ * T_ * O_];
__device__ __half g_WRh[O_ * D_];
__device__ __half g_WQh[O_ * D_];
__device__ __half g_W2Rh[G_ * O_];
__device__ __half g_W2Qh[G_ * O_];
__device__ __half g_x0t[B_ * T_ * D_];
__device__ __half g_x1t[B_ * T_ * D_];
__device__ __half g_Ft [B_ * T_ * T_];   // F transposed: Ft[b][j][i] = F[b][i][j], fp16
__device__ __half g_WRb[B_ * G_ * T_];   // WR fp16 [b][g][t]
__device__ __half g_WQb[B_ * G_ * T_];

// =================== helpers ===================
__device__ __forceinline__ uint32_t smem_to_u32(const void* p) {
    uint32_t a;
    asm("{ .reg .u64 t; cvta.to.shared.u64 t, %1; cvt.u32.u64 %0, t; }" : "=r"(a) : "l"(p));
    return a;
}
__device__ __forceinline__ void ldsm4(uint32_t* r, uint32_t addr) {
    asm volatile("ldmatrix.sync.aligned.m8n8.x4.shared.b16 {%0,%1,%2,%3}, [%4];"
        : "=r"(r[0]), "=r"(r[1]), "=r"(r[2]), "=r"(r[3]) : "r"(addr));
}
__device__ __forceinline__ void mma16816h(float* d, const uint32_t* a,
                                          uint32_t b0, uint32_t b1) {
    asm volatile("mma.sync.aligned.m16n8k16.row.col.f32.f16.f16.f32 "
        "{%0,%1,%2,%3}, {%4,%5,%6,%7}, {%8,%9}, {%0,%1,%2,%3};"
        : "+f"(d[0]), "+f"(d[1]), "+f"(d[2]), "+f"(d[3])
        : "r"(a[0]), "r"(a[1]), "r"(a[2]), "r"(a[3]), "r"(b0), "r"(b1));
}
__device__ __forceinline__ void cpasync16(uint32_t dst, const void* src) {
    asm volatile("cp.async.cg.shared.global [%0], [%1], 16;" :: "r"(dst), "l"(src));
}
#define CP_COMMIT() asm volatile("cp.async.commit_group;" ::: "memory")
#define CP_WAIT(n)  asm volatile("cp.async.wait_group %0;" :: "n"(n) : "memory")

__device__ __forceinline__ uint32_t paddr(uint32_t row, uint32_t cb) {
    uint32_t pr = row >> 1;
    return pr * 128 + ((((row & 1) << 6) + cb) ^ ((pr & 7) << 4));
}

__device__ __forceinline__ void decode_mask(const unsigned char* q, const unsigned char* v,
                                            int i, bool& qv, bool& vv) {
    unsigned char b1 = q[1], b3 = q[3];
    int type = (b1 == 1) ? 0 : (b1 == 0x3F) ? 3 : (b3 == 0x3F) ? 2 : 1;
    switch (type) {
        case 0: qv = q[i] != 0;                            vv = v[i] != 0; break;
        case 1: qv = ((const int*)q)[i] != 0;              vv = ((const int*)v)[i] != 0; break;
        case 2: qv = ((const float*)q)[i] != 0.f;          vv = ((const float*)v)[i] != 0.f; break;
        default: qv = ((const unsigned short*)q)[i] != 0;  vv = ((const unsigned short*)v)[i] != 0; break;
    }
}

// ---------------- mask decode ----------------
__global__ void maskconv_kernel(const unsigned char* __restrict__ q,
                                const unsigned char* __restrict__ v,
                                float* __restrict__ pq, float* __restrict__ pv) {
    int i = blockIdx.x * blockDim.x + threadIdx.x;
    if (i >= B_ * T_) return;
    bool qv, vv;
    decode_mask(q, v, i, qv, vv);
    pq[i] = qv ? 0.f : 1.f;
    pv[i] = vv ? 0.f : 1.f;
}

// ---------------- per-batch valid lengths ----------------
__global__ void lens_kernel(const unsigned char* __restrict__ q,
                            const unsigned char* __restrict__ v,
                            int* __restrict__ len1, int* __restrict__ len2,
                            int* __restrict__ jmin, int* __restrict__ imax) {
    __shared__ int s1, s2;
    int b = blockIdx.x, t = threadIdx.x;
    if (t == 0) { s1 = 0; s2 = 0; }
    __syncthreads();
    bool qv, vv;
    decode_mask(q, v, b * T_ + t, qv, vv);
    unsigned m1 = __ballot_sync(0xffffffffu, qv);
    unsigned m2 = __ballot_sync(0xffffffffu, vv);
    if ((t & 31) == 0) { atomicAdd(&s1, __popc(m1)); atomicAdd(&s2, __popc(m2)); }
    __syncthreads();
    if (t == 0) {
        len1[b] = s1; len2[b] = s2;
        jmin[b] = s1 < s2 ? s1 : s2;
        imax[b] = s1 > s2 ? s1 : s2;
    }
}

// ---------------- U/V de-interleave + fp16 ----------------
__global__ void convUV_kernel(const float* __restrict__ U, const float* __restrict__ V,
                              __half* __restrict__ Uo, __half* __restrict__ Vo) {
    int idx = blockIdx.x * blockDim.x + threadIdx.x;
    if (idx >= KF_ * T_ * O_) return;
    int k = idx >> 17;
    int m = idx & (T_ * O_ - 1);
    Uo[idx] = __float2half(U[m * KF_ + k]);
    Vo[idx] = __float2half(V[m * KF_ + k]);
}

// ---------------- W / W2 -> fp16 ----------------
__global__ void convW_kernel(const float* __restrict__ WR, const float* __restrict__ WQ,
                             const float* __restrict__ W2R, const float* __restrict__ W2Q,
                             __half* __restrict__ WRh, __half* __restrict__ WQh,
                             __half* __restrict__ W2Rh, __half* __restrict__ W2Qh) {
    int i = blockIdx.x * blockDim.x + threadIdx.x;
    if (i < O_ * D_) {
        WRh[i] = __float2half(WR[i]);
        WQh[i] = __float2half(WQ[i]);
    }
    if (i < G_ * O_) {
        W2Rh[i] = __float2half(W2R[i]);
        W2Qh[i] = __float2half(W2Q[i]);
    }
}

// ---------------- x transpose -> fp16 ----------------
__global__ void convX_kernel(const float* __restrict__ x0, const float* __restrict__ x1,
                             __half* __restrict__ x0t, __half* __restrict__ x1t) {
    __shared__ float tile[32][33];
    int zz = blockIdx.z;
    int b = zz & 31;
    bool is1 = (zz >> 5) != 0;
    const float* src = (is1 ? x1 : x0) + (long)b * D_ * T_;
    __half* dst = (is1 ? x1t : x0t) + (long)b * T_ * D_;
    int t0 = blockIdx.x * 32, k0 = blockIdx.y * 32;
    int tx = threadIdx.x, ty = threadIdx.y;
    #pragma unroll
    for (int r = 0; r < 4; r++)
        tile[ty + r * 8][tx] = src[(long)(k0 + ty + r * 8) * T_ + t0 + tx];
    __syncthreads();
    #pragma unroll
    for (int r = 0; r < 4; r++)
        dst[(long)(t0 + ty + r * 8) * D_ + k0 + tx] = __float2half(tile[tx][ty + r * 8]);
}

// ---------------- fp16 HMMA R/Q GEMM ----------------
__global__ __launch_bounds__(256) void gemm_rq_h_kernel(
    const __half* __restrict__ Wh, const __half* __restrict__ Xt,
    float* __restrict__ C, __half* __restrict__ Ct,
    const float* __restrict__ bias,
    const float* __restrict__ pad, const int* __restrict__ lenp) {
    __shared__ char gsm[49152];
    uint32_t sb = smem_to_u32(gsm);
    int b = blockIdx.z;
    int n0 = blockIdx.x * 128;
    int m0 = blockIdx.y * 64;
    int tid = threadIdx.x, lane = tid & 31, w = tid >> 5;
    int wi = w >> 2, wj = w & 3;
    int l16 = lane & 15, lh = lane >> 4;

    if (n0 >= lenp[b]) {
        float4 z = make_float4(0.f, 0.f, 0.f, 0.f);
        #pragma unroll
        for (int e = 0; e < 8; e++) {
            int idx = tid + e * 256;
            int m = idx >> 5, nq = idx & 31;
            *reinterpret_cast<float4*>(&C[((long)b * O_ + m0 + m) * T_ + n0 + nq * 4]) = z;
        }
        uint4 zh = make_uint4(0, 0, 0, 0);
        #pragma unroll
        for (int e = 0; e < 2; e++) {
            int idx = tid + e * 256;
            int n = idx >> 2, mq = idx & 3;
            *reinterpret_cast<uint4*>(&Ct[((long)b * T_ + n0 + n) * O_ + m0 + mq * 16]) = zh;
        }
        return;
    }

    const __half* Wb = Wh + (long)m0 * D_;
    const __half* Xb = Xt + ((long)b * T_ + n0) * D_;

    #pragma unroll
    for (int e = 0; e < 8; e++) {
        int idx = tid + e * 256;
        int ch = idx >> 8;
        int row = (idx & 255) >> 2;
        int cb = (idx & 3) * 16;
        cpasync16(sb + ch * 4096 + paddr(row, cb),
                  Wb + (long)row * D_ + ch * 32 + cb / 2);
    }
    CP_COMMIT();

    auto load_b = [&](int ch, int st) {
        #pragma unroll
        for (int e = 0; e < 2; e++) {
            int idx = tid + e * 256;
            int row = idx >> 2;
            int cb = (idx & 3) * 16;
            cpasync16(sb + 32768 + st * 8192 + paddr(row, cb),
                      Xb + (long)row * D_ + ch * 32 + cb / 2);
        }
    };
    load_b(0, 0);
    CP_COMMIT();

    float acc[32];
    #pragma unroll
    for (int i = 0; i < 32; i++) acc[i] = 0.f;

    for (int ch = 0; ch < 8; ch++) {
        int st = ch & 1;
        if (ch + 1 < 8) {
            load_b(ch + 1, st ^ 1);
            CP_COMMIT();
            CP_WAIT(1);
        } else {
            CP_WAIT(0);
        }
        __syncthreads();
        uint32_t abase = sb + ch * 4096;
        uint32_t bbase = sb + 32768 + st * 8192;
        #pragma unroll
        for (int os = 0; os < 2; os++) {
            uint32_t colb = (uint32_t)(os * 32 + lh * 16);
            uint32_t arow = (uint32_t)(wi * 32 + l16);
            uint32_t brow = (uint32_t)(wj * 32 + l16);
            uint32_t a0[4], a1[4], b0r[4], b1r[4];
            ldsm4(a0, abase + paddr(arow, colb));
            ldsm4(a1, abase + paddr(arow + 16, colb));
            ldsm4(b0r, bbase + paddr(brow, colb));
            ldsm4(b1r, bbase + paddr(brow + 16, colb));
            #pragma unroll
            for (int mt = 0; mt < 2; mt++) {
                const uint32_t* a = mt ? a1 : a0;
                #pragma unroll
                for (int nt = 0; nt < 4; nt++) {
                    const uint32_t* bb = (nt >> 1) ? b1r : b0r;
                    int s = nt & 1;
                    mma16816h(acc + (mt * 4 + nt) * 4, a, bb[s], bb[s + 2]);
                }
            }
        }
        __syncthreads();
    }

    __half* Cs = reinterpret_cast<__half*>(gsm);
    int r4 = lane >> 2, c2 = (lane & 3) * 2;
    #pragma unroll
    for (int mt = 0; mt < 2; mt++) {
        #pragma unroll
        for (int nt = 0; nt < 4; nt++) {
            float* d = acc + (mt * 4 + nt) * 4;
            #pragma unroll
            for (int half_ = 0; half_ < 2; half_++) {
                int row = wi * 32 + mt * 16 + r4 + half_ * 8;
                int col = wj * 32 + nt * 8 + c2;
                int m = m0 + row, n = n0 + col;
                float bi = bias[m];
                float v0 = fmaxf(d[half_ * 2 + 0] - NEGC * pad[b * T_ + n] + bi, 0.f);
                float v1 = fmaxf(d[half_ * 2 + 1] - NEGC * pad[b * T_ + n + 1] + bi, 0.f);
                float* dst = &C[((long)b * O_ + m) * T_ + n];
                dst[0] = v0; dst[1] = v1;
                Cs[row * 136 + col] = __float2half(v0);
                Cs[row * 136 + col + 1] = __float2half(v1);
            }
        }
    }
    __syncthreads();
    {
        int n = tid >> 1;
        int mh = (tid & 1) * 32;
        __half hbuf[32];
        #pragma unroll
        for (int mm = 0; mm < 32; mm++) hbuf[mm] = Cs[(mh + mm) * 136 + n];
        uint4* dst = reinterpret_cast<uint4*>(&Ct[((long)b * T_ + n0 + n) * O_ + m0 + mh]);
        const uint4* srcv = reinterpret_cast<const uint4*>(hbuf);
        dst[0] = srcv[0]; dst[1] = srcv[1]; dst[2] = srcv[2]; dst[3] = srcv[3];
    }
}

// ---------------- fp16 HMMA W2 GEMM: Out[b][g][t] = sum_o W2[g,o]*Xt[b][t][o] ----------------
__global__ __launch_bounds__(256) void wgemm_h_kernel(
    const __half* __restrict__ W2h, const __half* __restrict__ Xt,
    __half* __restrict__ Out) {
    __shared__ char gsm[49152];
    uint32_t sb = smem_to_u32(gsm);
    int b = blockIdx.y;
    int n0 = blockIdx.x * 128;
    int tid = threadIdx.x, lane = tid & 31, w = tid >> 5;
    int wi = w >> 2, wj = w & 3;
    int l16 = lane & 15, lh = lane >> 4;
    const __half* Xb = Xt + ((long)b * T_ + n0) * O_;

    #pragma unroll
    for (int e = 0; e < 8; e++) {
        int idx = tid + e * 256;
        int ch = idx >> 8;
        int row = (idx & 255) >> 2;
        int cb = (idx & 3) * 16;
        cpasync16(sb + ch * 4096 + paddr(row, cb),
                  W2h + (long)row * O_ + ch * 32 + cb / 2);
    }
    CP_COMMIT();

    auto load_b = [&](int ch, int st) {
        #pragma unroll
        for (int e = 0; e < 2; e++) {
            int idx = tid + e * 256;
            int row = idx >> 2;
            int cb = (idx & 3) * 16;
            cpasync16(sb + 32768 + st * 8192 + paddr(row, cb),
                      Xb + (long)row * O_ + ch * 32 + cb / 2);
        }
    };
    load_b(0, 0);
    CP_COMMIT();

    float acc[32];
    #pragma unroll
    for (int i = 0; i < 32; i++) acc[i] = 0.f;

    for (int ch = 0; ch < 8; ch++) {
        int st = ch & 1;
        if (ch + 1 < 8) {
            load_b(ch + 1, st ^ 1);
            CP_COMMIT();
            CP_WAIT(1);
        } else {
            CP_WAIT(0);
        }
        __syncthreads();
        uint32_t abase = sb + ch * 4096;
        uint32_t bbase = sb + 32768 + st * 8192;
        #pragma unroll
        for (int os = 0; os < 2; os++) {
            uint32_t colb = (uint32_t)(os * 32 + lh * 16);
            uint32_t arow = (uint32_t)(wi * 32 + l16);
            uint32_t brow = (uint32_t)(wj * 32 + l16);
            uint32_t a0[4], a1[4], b0r[4], b1r[4];
            ldsm4(a0, abase + paddr(arow, colb));
            ldsm4(a1, abase + paddr(arow + 16, colb));
            ldsm4(b0r, bbase + paddr(brow, colb));
            ldsm4(b1r, bbase + paddr(brow + 16, colb));
            #pragma unroll
            for (int mt = 0; mt < 2; mt++) {
                const uint32_t* a = mt ? a1 : a0;
                #pragma unroll
                for (int nt = 0; nt < 4; nt++) {
                    const uint32_t* bb = (nt >> 1) ? b1r : b0r;
                    int s = nt & 1;
                    mma16816h(acc + (mt * 4 + nt) * 4, a, bb[s], bb[s + 2]);
                }
            }
        }
        __syncthreads();
    }

    int r4 = lane >> 2, c2 = (lane & 3) * 2;
    #pragma unroll
    for (int mt = 0; mt < 2; mt++) {
        #pragma unroll
        for (int nt = 0; nt < 4; nt++) {
            float* d = acc + (mt * 4 + nt) * 4;
            #pragma unroll
            for (int half_ = 0; half_ < 2; half_++) {
                int g = wi * 32 + mt * 16 + r4 + half_ * 8;
                int t = n0 + wj * 32 + nt * 8 + c2;
                __half2 v = __floats2half2_rn(d[half_ * 2], d[half_ * 2 + 1]);
                *reinterpret_cast<__half2*>(&Out[((long)b * G_ + g) * T_ + t]) = v;
            }
        }
    }
}

// ======================= fp16 HMMA F kernel -> Ft (transposed fp16) =======================
#define FS_B 32768
#define FS_TOTAL 98304

__global__ __launch_bounds__(256, 2) void f_mma_kernel(
    const __half* __restrict__ Uk, const __half* __restrict__ Vk,
    const __half* __restrict__ Rt, const __half* __restrict__ Qt,
    __half* __restrict__ Ft, const int* __restrict__ jmin, const int* __restrict__ imax) {
    extern __shared__ char sm[];
    uint32_t sb = smem_to_u32(sm);
    int tid = threadIdx.x, lane = tid & 31, w = tid >> 5;
    int wi = w >> 1, wj = w & 1;
    int b = blockIdx.z, i0 = blockIdx.y * 128, j0 = blockIdx.x * 64;
    int l16 = lane & 15, lh = lane >> 4;

    if (i0 >= imax[b]) return;

    if (j0 >= jmin[b]) {
        int j = tid >> 2, iq = (tid & 3) * 32;
        uint4 z4 = make_uint4(0, 0, 0, 0);
        uint4* dst = reinterpret_cast<uint4*>(&Ft[((long)b * T_ + j0 + j) * T_ + i0 + iq]);
        dst[0] = z4; dst[1] = z4; dst[2] = z4; dst[3] = z4;
        return;
    }

    const __half* apt[2] = {Uk, Vk};
    const __half* bpt[2] = {Rt, Qt};

    #pragma unroll
    for (int arr = 0; arr < 2; arr++) {
        const __half* src = bpt[arr] + ((long)b * T_ + j0) * O_;
        #pragma unroll
        for (int e = 0; e < 8; e++) {
            int idx = tid + e * 256;
            int ch = idx >> 8;
            int row = (idx & 255) >> 2;
            int cb = (idx & 3) * 16;
            const void* g = src + (long)row * O_ + ch * 32 + cb / 2;
            cpasync16(sb + FS_B + arr * 32768 + ch * 4096 + paddr(row, cb), g);
        }
    }
    CP_COMMIT();

    auto load_a = [&](int cu, int st) {
        int k = cu >> 3, ch = cu & 7;
        #pragma unroll
        for (int arr = 0; arr < 2; arr++) {
            const __half* src = apt[arr] + ((long)k * T_ + i0) * O_ + ch * 32;
            #pragma unroll
            for (int e = 0; e < 2; e++) {
                int idx = tid + e * 256;
                int row = idx >> 2;
                int cb = (idx & 3) * 16;
                const void* g = src + (long)row * O_ + cb / 2;
                cpasync16(sb + st * 16384 + arr * 8192 + paddr(row, cb), g);
            }
        }
    };

    load_a(0, 0);
    CP_COMMIT();

    float f[32], d1[32], d2[32];
    #pragma unroll
    for (int i = 0; i < 32; i++) { f[i] = 0.f; d1[i] = 0.f; d2[i] = 0.f; }

    for (int cu = 0; cu < 64; cu++) {
        int st = cu & 1, ch = cu & 7;
        if (cu + 1 < 64) {
            load_a(cu + 1, (cu + 1) & 1);
            CP_COMMIT();
            CP_WAIT(1);
        } else {
            CP_WAIT(0);
        }
        __syncthreads();

        uint32_t abase = sb + st * 16384;
        #pragma unroll
        for (int os = 0; os < 2; os++) {
            uint32_t colb = (uint32_t)(os * 32 + lh * 16);
            uint32_t arow = (uint32_t)(wi * 32 + l16);
            uint32_t brow = (uint32_t)(wj * 32 + l16);
            {
                uint32_t a0[4], a1[4], b0r[4], b1r[4];
                ldsm4(a0, abase + 0 * 8192 + paddr(arow, colb));
                ldsm4(a1, abase + 0 * 8192 + paddr(arow + 16, colb));
                uint32_t bb0 = sb + FS_B + 0 * 32768 + ch * 4096;
                ldsm4(b0r, bb0 + paddr(brow, colb));
                ldsm4(b1r, bb0 + paddr(brow + 16, colb));
                #pragma unroll
                for (int mt = 0; mt < 2; mt++) {
                    const uint32_t* a = mt ? a1 : a0;
                    #pragma unroll
                    for (int nt = 0; nt < 4; nt++) {
                        const uint32_t* bb = (nt >> 1) ? b1r : b0r;
                        int s = nt & 1;
                        mma16816h(d1 + (mt * 4 + nt) * 4, a, bb[s], bb[s + 2]);
                    }
                }
            }
            {
                uint32_t a0[4], a1[4], b0r[4], b1r[4];
                ldsm4(a0, abase + 1 * 8192 + paddr(arow, colb));
                ldsm4(a1, abase + 1 * 8192 + paddr(arow + 16, colb));
                uint32_t bb1 = sb + FS_B + 1 * 32768 + ch * 4096;
                ldsm4(b0r, bb1 + paddr(brow, colb));
                ldsm4(b1r, bb1 + paddr(brow + 16, colb));
                #pragma unroll
                for (int mt = 0; mt < 2; mt++) {
                    const uint32_t* a = mt ? a1 : a0;
                    #pragma unroll
                    for (int nt = 0; nt < 4; nt++) {
                        const uint32_t* bb = (nt >> 1) ? b1r : b0r;
                        int s = nt & 1;
                        mma16816h(d2 + (mt * 4 + nt) * 4, a, bb[s], bb[s + 2]);
                    }
                }
            }
        }
        if (ch == 7) {
            #pragma unroll
            for (int i = 0; i < 32; i++) {
                f[i] += d1[i] * d2[i];
                d1[i] = 0.f; d2[i] = 0.f;
            }
        }
        __syncthreads();
    }

    // stage fp16 tile [128 i][72 j] into reused A-ring SMEM, then coalesced transposed write
    __half* Fs16 = reinterpret_cast<__half*>(sm);
    int r4 = lane >> 2, c2 = (lane & 3) * 2;
    #pragma unroll
    for (int mt = 0; mt < 2; mt++) {
        #pragma unroll
        for (int nt = 0; nt < 4; nt++) {
            float* d = f + (mt * 4 + nt) * 4;
            #pragma unroll
            for (int hh = 0; hh < 2; hh++) {
                int i_l = wi * 32 + mt * 16 + r4 + hh * 8;
                int j_l = wj * 32 + nt * 8 + c2;
                *reinterpret_cast<__half2*>(&Fs16[i_l * 72 + j_l]) =
                    __floats2half2_rn(d[hh * 2], d[hh * 2 + 1]);
            }
        }
    }
    __syncthreads();
    {
        int j = tid >> 2, iq = (tid & 3) * 32;
        __half hbuf[32];
        #pragma unroll
        for (int ii = 0; ii < 32; ii++) hbuf[ii] = Fs16[(iq + ii) * 72 + j];
        uint4* dst = reinterpret_cast<uint4*>(&Ft[((long)b * T_ + j0 + j) * T_ + i0 + iq]);
        const uint4* s4 = reinterpret_cast<const uint4*>(hbuf);
        dst[0] = s4[0]; dst[1] = s4[1]; dst[2] = s4[2]; dst[3] = s4[3];
    }
}

// ---------------- fp16 HMMA fused M + d kernel ----------------
// d[b,col] = sum_g w[g]*relu(Bias[g,c0+col] + sum_i Mul[g,i]*Ft[c0+col][i]) - NEG*pad
__global__ __launch_bounds__(128) void md_h_kernel(
    const __half* __restrict__ Bias, const __half* __restrict__ Mul,
    const __half* __restrict__ Ft, const float* __restrict__ wv,
    const float* __restrict__ pad, float* __restrict__ d,
    const int* __restrict__ lencol, const int* __restrict__ lenmul) {
    __shared__ char msm[16384];
    __shared__ float red[64][65];
    __shared__ float p2[2][64];
    uint32_t sb = smem_to_u32(msm);
    int b = blockIdx.y, c0 = blockIdx.x * 64;
    int tid = threadIdx.x, lane = tid & 31, w_ = tid >> 5;
    int wg = w_ >> 1, wc = w_ & 1;
    int l16 = lane & 15, lh = lane >> 4;

    if (c0 >= lencol[b]) {
        if (tid < 64) d[b * T_ + c0 + tid] = -NEGC;
        return;
    }
    int nch = ((lenmul[b] + 31) & ~31) >> 5;
    const __half* Mb = Mul + (long)b * G_ * T_;
    const __half* Fb = Ft + ((long)b * T_ + c0) * T_;

    auto load_ch = [&](int ch, int st) {
        #pragma unroll
        for (int e = 0; e < 2; e++) {
            int idx = tid + e * 128;
            int row = idx >> 2, cb = (idx & 3) * 16;
            cpasync16(sb + st * 8192 + paddr(row, cb), Mb + (long)row * T_ + ch * 32 + cb / 2);
        }
        #pragma unroll
        for (int e = 0; e < 2; e++) {
            int idx = tid + e * 128;
            int row = idx >> 2, cb = (idx & 3) * 16;
            cpasync16(sb + st * 8192 + 4096 + paddr(row, cb), Fb + (long)row * T_ + ch * 32 + cb / 2);
        }
    };
    load_ch(0, 0);
    CP_COMMIT();

    float acc[32];
    #pragma unroll
    for (int i = 0; i < 32; i++) acc[i] = 0.f;

    for (int ch = 0; ch < nch; ch++) {
        int st = ch & 1;
        if (ch + 1 < nch) {
            load_ch(ch + 1, st ^ 1);
            CP_COMMIT();
            CP_WAIT(1);
        } else {
            CP_WAIT(0);
        }
        __syncthreads();
        uint32_t ab = sb + st * 8192, bb_ = ab + 4096;
        #pragma unroll
        for (int os = 0; os < 2; os++) {
            uint32_t colb = (uint32_t)(os * 32 + lh * 16);
            uint32_t arow = (uint32_t)(wg * 32 + l16);
            uint32_t brow = (uint32_t)(wc * 32 + l16);
            uint32_t a0[4], a1[4], b0r[4], b1r[4];
            ldsm4(a0, ab + paddr(arow, colb));
            ldsm4(a1, ab + paddr(arow + 16, colb));
            ldsm4(b0r, bb_ + paddr(brow, colb));
            ldsm4(b1r, bb_ + paddr(brow + 16, colb));
            #pragma unroll
            for (int mt = 0; mt < 2; mt++) {
                const uint32_t* a = mt ? a1 : a0;
                #pragma unroll
                for (int nt = 0; nt < 4; nt++) {
                    const uint32_t* bb = (nt >> 1) ? b1r : b0r;
                    int s = nt & 1;
                    mma16816h(acc + (mt * 4 + nt) * 4, a, bb[s], bb[s + 2]);
                }
            }
        }
        __syncthreads();
    }

    int r4 = lane >> 2, c2 = (lane & 3) * 2;
    #pragma unroll
    for (int mt = 0; mt < 2; mt++) {
        #pragma unroll
        for (int nt = 0; nt < 4; nt++) {
            float* dd = acc + (mt * 4 + nt) * 4;
            #pragma unroll
            for (int hh = 0; hh < 2; hh++) {
                int g = wg * 32 + mt * 16 + r4 + hh * 8;
                int col = wc * 32 + nt * 8 + c2;
                float wgt = wv[g];
                float bi0 = __half2float(Bias[(long)b * G_ * T_ + g * T_ + c0 + col]);
                float bi1 = __half2float(Bias[(long)b * G_ * T_ + g * T_ + c0 + col + 1]);
                red[g][col]     = wgt * fmaxf(dd[hh * 2 + 0] + bi0, 0.f);
                red[g][col + 1] = wgt * fmaxf(dd[hh * 2 + 1] + bi1, 0.f);
            }
        }
    }
    __syncthreads();
    {
        int col = tid & 63, h = tid >> 6;
        float s = 0.f;
        #pragma unroll
        for (int g = 0; g < 32; g++) s += red[h * 32 + g][col];
        p2[h][col] = s;
    }
    __syncthreads();
    if (tid < 64)
        d[b * T_ + c0 + tid] = p2[0][tid] + p2[1][tid] - NEGC * pad[b * T_ + c0 + tid];
}

// ---------------- softmax ----------------
__global__ void softmax_kernel(const float* __restrict__ d1, const float* __restrict__ d2,
                               float* __restrict__ g1, float* __restrict__ g2) {
    int b = blockIdx.x;
    const float* d = blockIdx.y ? d2 : d1;
    float* g = blockIdx.y ? g2 : g1;
    int t = threadIdx.x;
    float v = d[b * T_ + t];
    __shared__ float red[16];
    float m = v;
    #pragma unroll
    for (int o = 16; o; o >>= 1) m = fmaxf(m, __shfl_xor_sync(0xffffffffu, m, o));
    if ((t & 31) == 0) red[t >> 5] = m;
    __syncthreads();
    if (t < 32) {
        float x = (t < 16) ? red[t] : -3.4e38f;
        #pragma unroll
        for (int o = 8; o; o >>= 1) x = fmaxf(x, __shfl_xor_sync(0xffffffffu, x, o));
        if (t == 0) red[0] = x;
    }
    __syncthreads();
    float mx = red[0];
    __syncthreads();
    float e = expf(v - mx);
    float s = e;
    #pragma unroll
    for (int o = 16; o; o >>= 1) s += __shfl_xor_sync(0xffffffffu, s, o);
    if ((t & 31) == 0) red[t >> 5] = s;
    __syncthreads();
    if (t < 32) {
        float x = (t < 16) ? red[t] : 0.f;
        #pragma unroll
        for (int o = 8; o; o >>= 1) x += __shfl_xor_sync(0xffffffffu, x, o);
        if (t == 0) red[0] = x;
    }
    __syncthreads();
    g[b * T_ + t] = e / red[0];
}

// ---------------- final reduction ----------------
__global__ void final_kernel(const float* __restrict__ R, const float* __restrict__ Q,
                             const float* __restrict__ gv, const float* __restrict__ gq,
                             float* __restrict__ out) {
    int b = blockIdx.x;
    __shared__ float sgv[T_], sgq[T_];
    int tid = threadIdx.x;
    sgv[tid] = gv[b * T_ + tid];
    sgq[tid] = gq[b * T_ + tid];
    __syncthreads();
    int o = tid & 255;
    int h = tid >> 8;
    const float* Rb = R + (long)b * O_ * T_;
    const float* Qb = Q + (long)b * O_ * T_;
    float tr = 0.f, lg = 0.f;
    #pragma unroll 4
    for (int t = h * 256; t < h * 256 + 256; t++) {
        tr += sgv[t] * Rb[t * O_ + o];
        lg += sgq[t] * Qb[t * O_ + o];
    }
    __shared__ float str[2][256], slg[2][256];
    str[h][o] = tr;
    slg[h][o] = lg;
    __syncthreads();
    if (h == 0) out[b * O_ + o] = (str[0][o] + str[1][o]) * (slg[0][o] + slg[1][o]);
}

// ---------------- launcher ----------------
extern "C" void kernel_launch(void* const* d_in, const int* in_sizes, int n_in,
                              void* d_out, int out_size) {
    const float* x0  = (const float*)d_in[0];
    const float* x1  = (const float*)d_in[1];
    const unsigned char* qm = (const unsigned char*)d_in[2];
    const unsigned char* vm = (const unsigned char*)d_in[3];
    const float* W_R = (const float*)d_in[4];
    const float* W_Q = (const float*)d_in[5];
    const float* br  = (const float*)d_in[6];
    const float* bq  = (const float*)d_in[7];
    const float* U   = (const float*)d_in[8];
    const float* V   = (const float*)d_in[9];
    const float* W2R = (const float*)d_in[10];
    const float* W2Q = (const float*)d_in[11];
    const float* wmv = (const float*)d_in[12];
    const float* wmq = (const float*)d_in[13];
    float* out = (float*)d_out;

    float *pR, *pQ, *pd1, *pd2, *pg1, *pg2, *ppq, *ppv;
    int *pl1, *pl2, *pjm, *pim;
    __half *pUk, *pVk, *pRt, *pQt, *pWRh, *pWQh, *pW2Rh, *pW2Qh, *px0t, *px1t, *pFt, *pWRb, *pWQb;
    cudaGetSymbolAddress((void**)&pR,  g_R);
    cudaGetSymbolAddress((void**)&pQ,  g_Q);
    cudaGetSymbolAddress((void**)&pd1, g_d1);
    cudaGetSymbolAddress((void**)&pd2, g_d2);
    cudaGetSymbolAddress((void**)&pg1, g_g1);
    cudaGetSymbolAddress((void**)&pg2, g_g2);
    cudaGetSymbolAddress((void**)&ppq, g_pq);
    cudaGetSymbolAddress((void**)&ppv, g_pv);
    cudaGetSymbolAddress((void**)&pl1, g_len1);
    cudaGetSymbolAddress((void**)&pl2, g_len2);
    cudaGetSymbolAddress((void**)&pjm, g_jmin);
    cudaGetSymbolAddress((void**)&pim, g_imax);
    cudaGetSymbolAddress((void**)&pUk, g_Uk);
    cudaGetSymbolAddress((void**)&pVk, g_Vk);
    cudaGetSymbolAddress((void**)&pRt, g_Rt);
    cudaGetSymbolAddress((void**)&pQt, g_Qt);
    cudaGetSymbolAddress((void**)&pWRh, g_WRh);
    cudaGetSymbolAddress((void**)&pWQh, g_WQh);
    cudaGetSymbolAddress((void**)&pW2Rh, g_W2Rh);
    cudaGetSymbolAddress((void**)&pW2Qh, g_W2Qh);
    cudaGetSymbolAddress((void**)&px0t, g_x0t);
    cudaGetSymbolAddress((void**)&px1t, g_x1t);
    cudaGetSymbolAddress((void**)&pFt, g_Ft);
    cudaGetSymbolAddress((void**)&pWRb, g_WRb);
    cudaGetSymbolAddress((void**)&pWQb, g_WQb);

    static bool attr_done = false;
    if (!attr_done) {
        cudaFuncSetAttribute(f_mma_kernel, cudaFuncAttributeMaxDynamicSharedMemorySize, FS_TOTAL);
        attr_done = true;
    }

    maskconv_kernel<<<(B_ * T_ + 255) / 256, 256>>>(qm, vm, ppq, ppv);
    lens_kernel<<<B_, T_>>>(qm, vm, pl1, pl2, pjm, pim);
    convUV_kernel<<<(KF_ * T_ * O_ + 255) / 256, 256>>>(U, V, pUk, pVk);
    convW_kernel<<<(O_ * D_ + 255) / 256, 256>>>(W_R, W_Q, W2R, W2Q, pWRh, pWQh, pW2Rh, pW2Qh);
    convX_kernel<<<dim3(T_ / 32, D_ / 32, 2 * B_), dim3(32, 8)>>>(x0, x1, px0t, px1t);

    gemm_rq_h_kernel<<<dim3(T_ / 128, O_ / 64, B_), 256>>>(
        pWRh, px0t, pR, pRt, br, ppq, pl1);
    gemm_rq_h_kernel<<<dim3(T_ / 128, O_ / 64, B_), 256>>>(
        pWQh, px1t, pQ, pQt, bq, ppv, pl2);

    f_mma_kernel<<<dim3(T_ / 64, T_ / 128, B_), 256, FS_TOTAL>>>(
        pUk, pVk, pRt, pQt, pFt, pjm, pim);

    wgemm_h_kernel<<<dim3(T_ / 128, B_), 256>>>(pW2Rh, pRt, pWRb);
    wgemm_h_kernel<<<dim3(T_ / 128, B_), 256>>>(pW2Qh, pQt, pWQb);

    md_h_kernel<<<dim3(T_ / 64, B_), 128>>>(pWRb, pWQb, pFt, wmv, ppq, pd1, pl1, pl2);
    md_h_kernel<<<dim3(T_ / 64, B_), 128>>>(pWQb, pWRb, pFt, wmq, ppv, pd2, pl2, pl1);

    softmax_kernel<<<dim3(B_, 2), T_>>>(pd1, pd2, pg1, pg2);

    final_kernel<<<B_, T_>>>(pR, pQ, pg1, pg2, out);
}